// round 9
// baseline (speedup 1.0000x reference)
#include <cuda_runtime.h>
#include <math.h>

// ---------------------------------------------------------------------------
// QANet forward on sm_103a.
// R9: GEMMs moved to tensor cores (mma.sync m16n8k8 tf32, TF32x3 for fp32-grade
//     accuracy). LN/conv/residual/stats fusion retained. Rest as R4.
// ---------------------------------------------------------------------------
#define kB 64
#define kD 128
#define kN 400
#define kM 50
#define kH 8
#define kKD 16
#define kNC 4
#define kKW 7
#define kPAD 3

typedef unsigned long long u64;
typedef unsigned int u32;

__device__ __forceinline__ u64 pk2(float lo, float hi) {
    u64 r; asm("mov.b64 %0,{%1,%2};" : "=l"(r) : "f"(lo), "f"(hi)); return r;
}
__device__ __forceinline__ void upk2(u64 v, float& lo, float& hi) {
    asm("mov.b64 {%0,%1},%2;" : "=f"(lo), "=f"(hi) : "l"(v));
}
__device__ __forceinline__ u64 fma2(u64 a, u64 b, u64 c) {
    u64 d; asm("fma.rn.f32x2 %0,%1,%2,%3;" : "=l"(d) : "l"(a), "l"(b), "l"(c)); return d;
}
__device__ __forceinline__ u64 mul2(u64 a, u64 b) {
    u64 d; asm("mul.rn.f32x2 %0,%1,%2;" : "=l"(d) : "l"(a), "l"(b)); return d;
}
__device__ __forceinline__ void tf32pair(float x, u32& hi, u32& lo) {
    asm("cvt.rna.tf32.f32 %0, %1;" : "=r"(hi) : "f"(x));
    float r = x - __uint_as_float(hi);
    asm("cvt.rna.tf32.f32 %0, %1;" : "=r"(lo) : "f"(r));
}
__device__ __forceinline__ void mma8(float& c0, float& c1, float& c2, float& c3,
                                     u32 a0, u32 a1, u32 a2, u32 a3,
                                     u32 b0, u32 b1) {
    asm("mma.sync.aligned.m16n8k8.row.col.f32.tf32.tf32.f32 "
        "{%0,%1,%2,%3},{%4,%5,%6,%7},{%8,%9},{%0,%1,%2,%3};"
        : "+f"(c0), "+f"(c1), "+f"(c2), "+f"(c3)
        : "r"(a0), "r"(a1), "r"(a2), "r"(a3), "r"(b0), "r"(b1));
}

// ------------------------- device scratch (static) -------------------------
__device__ float g_C[kB * kD * kN];
__device__ float g_Q[kB * kD * kM];
__device__ float g_dw[kB * kD * kN];
__device__ float g_Q2[kB * kD * kM];
__device__ float g_qkv[kB * 3 * kD * kN];
__device__ float g_ao[kB * kD * kN];
__device__ float g_Wqkv[3 * kD * kD];   // [e][d]
__device__ float g_bqkv[3 * kD];
__device__ float g_pe[kD * kN];
__device__ float g_mu[kB * kN];
__device__ float g_ri[kB * kN];
__device__ float g_S[kB * kM * kN];
__device__ float g_Sr[kB * kM * kN];
__device__ float g_Sc[kB * kM * kN];
__device__ float g_U[kB * kM * kD];
__device__ float g_Ct[kB * kN * kD];
__device__ float g_Qt[kB * kM * kD];
__device__ float g_Qw[kB * kM * kD];
__device__ float g_cc[kB * kN];
__device__ float g_qq[kB * kM];

// ------------------------------ PE table ----------------------------------
__global__ void k_pe() {
    int idx = blockIdx.x * blockDim.x + threadIdx.x;
    if (idx >= kD * kN) return;
    int d = idx / kN;
    int l = idx % kN;
    int d0 = d & ~1;
    double f = pow(10000.0, -(double)d0 / (double)kD);
    double a = (double)l * f;
    g_pe[idx] = (d & 1) ? (float)cos(a) : (float)sin(a);
}

// ----------------- add PE + compute LN stats in one pass -------------------
__global__ void __launch_bounds__(128) k_add_pe_stats(const float* __restrict__ x,
                                                      float* __restrict__ y,
                                                      float* __restrict__ omu,
                                                      float* __restrict__ ori, int L) {
    int tid = threadIdx.x;
    int lsub = tid & 31;
    int grp = tid >> 5;
    int pos = blockIdx.x * 32 + lsub;
    int P = kB * L;
    bool ok = pos < P;
    int b = ok ? pos / L : 0;
    int l = ok ? pos % L : 0;

    float s = 0.f, sq = 0.f;
    if (ok) {
        const float* xp = x + ((size_t)b * kD + grp * 32) * L + l;
        float* yp = y + ((size_t)b * kD + grp * 32) * L + l;
#pragma unroll
        for (int k = 0; k < 32; k++) {
            int d = grp * 32 + k;
            float v = xp[(size_t)k * L] + g_pe[d * kN + l];
            yp[(size_t)k * L] = v;
            s += v;
            sq += v * v;
        }
    }
    __shared__ float ss[4][32], sb[4][32];
    ss[grp][lsub] = s;
    sb[grp][lsub] = sq;
    __syncthreads();
    if (grp == 0 && ok) {
        float ts = ss[0][lsub] + ss[1][lsub] + ss[2][lsub] + ss[3][lsub];
        float tq = sb[0][lsub] + sb[1][lsub] + sb[2][lsub] + sb[3][lsub];
        float mu = ts * (1.f / 128.f);
        float var = (tq - 128.f * mu * mu) * (1.f / 127.f);
        var = fmaxf(var, 0.f);
        omu[pos] = mu;
        ori[pos] = 1.f / (sqrtf(var) + 1e-6f);
    }
}

// ---------------- fused LN + depthwise conv + pointwise GEMM (tf32) ---------
// 256 threads = 8 warps. Block tile 128e x 64l; warp tile 32e x 32l.
__global__ void __launch_bounds__(256) k_cgemm(const float* __restrict__ X,
                                               const float* __restrict__ Wpw,  // [e][d]
                                               const float* __restrict__ pwb,
                                               const float* __restrict__ cw,
                                               const float* __restrict__ cb,
                                               const float* __restrict__ gamma,
                                               const float* __restrict__ beta,
                                               const float* __restrict__ mu,
                                               const float* __restrict__ ri,
                                               float* __restrict__ out,
                                               float* __restrict__ omu,
                                               float* __restrict__ ori, int L) {
    __shared__ float Xl[32][72];
    __shared__ u32 Whi[32][136], Wlo[32][136];
    __shared__ u32 Xhi[32][72], Xlo[32][72];
    __shared__ float mus[72], ris[72];
    __shared__ float gs[128], bs2[128];
    __shared__ float cws[128][8];
    __shared__ float sumA[64], sqA[64];

    int tid = threadIdx.x;
    int lane = tid & 31;
    int warp = tid >> 5;
    int grp = lane >> 2;     // 0..7
    int tig = lane & 3;      // 0..3
    int wm = warp >> 1;      // 0..3 -> e_base
    int wn = warp & 1;       // 0..1 -> l_base
    int e_base = wm * 32;
    int l_base = wn * 32;
    int l0 = blockIdx.x * 64;
    int b = blockIdx.z;

    if (tid < 70) {
        int gl = l0 + tid - 3;
        bool in = (gl >= 0 && gl < L);
        mus[tid] = in ? mu[(size_t)b * L + gl] : 0.f;
        ris[tid] = in ? ri[(size_t)b * L + gl] : 0.f;
    }
    if (tid < 128) {
        gs[tid] = gamma[tid];
        bs2[tid] = beta[tid];
#pragma unroll
        for (int k = 0; k < 7; k++) cws[tid][k] = cw[tid * 7 + k];
        cws[tid][7] = cb[tid];
    }
    if (tid < 64) { sumA[tid] = 0.f; sqA[tid] = 0.f; }
    __syncthreads();

    float c[8][4];
#pragma unroll
    for (int i = 0; i < 8; i++)
#pragma unroll
        for (int j = 0; j < 4; j++) c[i][j] = 0.f;

    for (int ks = 0; ks < 4; ks++) {
        int d0 = ks * 32;
        // LN'd halo tile 32x70
#pragma unroll
        for (int r = 0; r < 9; r++) {
            int idx = tid + r * 256;
            if (idx < 2240) {
                int dd = idx / 70;
                int ll = idx - dd * 70;
                int gl = l0 + ll - 3;
                float v = 0.f;
                if (gl >= 0 && gl < L) {
                    float xv = X[((size_t)b * 128 + d0 + dd) * L + gl];
                    v = gs[d0 + dd] * (xv - mus[ll]) * ris[ll] + bs2[d0 + dd];
                }
                Xl[dd][ll] = v;
            }
        }
        // W tile: Whi/Wlo[dd][e]
#pragma unroll
        for (int r = 0; r < 16; r++) {
            int idx = tid + r * 256;
            int e = idx >> 5;
            int dd = idx & 31;
            float w = Wpw[(size_t)e * 128 + d0 + dd];
            u32 hi, lo;
            tf32pair(w, hi, lo);
            Whi[dd][e] = hi;
            Wlo[dd][e] = lo;
        }
        __syncthreads();
        // conv -> Xhi/Xlo
#pragma unroll
        for (int r = 0; r < 8; r++) {
            int idx = tid + r * 256;
            int dd = idx >> 6;
            int ll = idx & 63;
            int d = d0 + dd;
            float a = cws[d][7];
#pragma unroll
            for (int kk = 0; kk < 7; kk++) a += cws[d][kk] * Xl[dd][ll + kk];
            u32 hi, lo;
            tf32pair(a, hi, lo);
            Xhi[dd][ll] = hi;
            Xlo[dd][ll] = lo;
        }
        __syncthreads();
        // mma over 4 sub-steps of K=8
#pragma unroll
        for (int kk = 0; kk < 4; kk++) {
            int k8 = kk * 8;
            u32 ahi[2][4], alo[2][4];
#pragma unroll
            for (int mt = 0; mt < 2; mt++) {
                int e = e_base + mt * 16 + grp;
                ahi[mt][0] = Whi[k8 + tig][e];
                ahi[mt][1] = Whi[k8 + tig][e + 8];
                ahi[mt][2] = Whi[k8 + tig + 4][e];
                ahi[mt][3] = Whi[k8 + tig + 4][e + 8];
                alo[mt][0] = Wlo[k8 + tig][e];
                alo[mt][1] = Wlo[k8 + tig][e + 8];
                alo[mt][2] = Wlo[k8 + tig + 4][e];
                alo[mt][3] = Wlo[k8 + tig + 4][e + 8];
            }
            u32 bhi[4][2], blo[4][2];
#pragma unroll
            for (int nt = 0; nt < 4; nt++) {
                int l = l_base + nt * 8 + grp;
                bhi[nt][0] = Xhi[k8 + tig][l];
                bhi[nt][1] = Xhi[k8 + tig + 4][l];
                blo[nt][0] = Xlo[k8 + tig][l];
                blo[nt][1] = Xlo[k8 + tig + 4][l];
            }
#pragma unroll
            for (int mt = 0; mt < 2; mt++)
#pragma unroll
                for (int nt = 0; nt < 4; nt++) {
                    float* cc2 = c[mt * 4 + nt];
                    mma8(cc2[0], cc2[1], cc2[2], cc2[3],
                         ahi[mt][0], ahi[mt][1], ahi[mt][2], ahi[mt][3],
                         bhi[nt][0], bhi[nt][1]);
                    mma8(cc2[0], cc2[1], cc2[2], cc2[3],
                         ahi[mt][0], ahi[mt][1], ahi[mt][2], ahi[mt][3],
                         blo[nt][0], blo[nt][1]);
                    mma8(cc2[0], cc2[1], cc2[2], cc2[3],
                         alo[mt][0], alo[mt][1], alo[mt][2], alo[mt][3],
                         bhi[nt][0], bhi[nt][1]);
                }
        }
        __syncthreads();
    }

    // epilogue: bias + relu + residual + stats (atomic) + store
#pragma unroll
    for (int mt = 0; mt < 2; mt++) {
#pragma unroll
        for (int nt = 0; nt < 4; nt++) {
            float* cc2 = c[mt * 4 + nt];
            int e0 = e_base + mt * 16 + grp;
            int ll = l_base + nt * 8 + tig * 2;
#pragma unroll
            for (int rr = 0; rr < 2; rr++) {
                int e = e0 + rr * 8;
                float bv = pwb[e];
#pragma unroll
                for (int qq2 = 0; qq2 < 2; qq2++) {
                    int lg = l0 + ll + qq2;
                    if (lg < L) {
                        float v = fmaxf(cc2[rr * 2 + qq2] + bv, 0.f);
                        size_t oi = ((size_t)b * 128 + e) * L + lg;
                        v += X[oi];
                        out[oi] = v;
                        atomicAdd(&sumA[ll + qq2], v);
                        atomicAdd(&sqA[ll + qq2], v * v);
                    }
                }
            }
        }
    }
    __syncthreads();
    if (tid < 64) {
        int lg = l0 + tid;
        if (lg < L) {
            float s = sumA[tid], ss2 = sqA[tid];
            float muv = s * (1.f / 128.f);
            float var = (ss2 - 128.f * muv * muv) * (1.f / 127.f);
            var = fmaxf(var, 0.f);
            omu[(size_t)b * L + lg] = muv;
            ori[(size_t)b * L + lg] = 1.f / (sqrtf(var) + 1e-6f);
        }
    }
}

// ------------------------------- GEMM (tf32) --------------------------------
template <bool TR, bool RELU, bool RES, bool LNX, bool STATS>
__global__ void __launch_bounds__(256) k_gemm(const float* __restrict__ X,
                                              const float* __restrict__ W,
                                              const float* __restrict__ bias,
                                              const float* res, float* out,
                                              int L, int Etot,
                                              const float* __restrict__ mu,
                                              const float* __restrict__ ri,
                                              const float* __restrict__ gamma,
                                              const float* __restrict__ beta,
                                              float* omu, float* ori) {
    __shared__ u32 Whi[32][136], Wlo[32][136];
    __shared__ u32 Xhi[32][72], Xlo[32][72];
    __shared__ float mus[64], ris[64];
    __shared__ float gs[128], bs2[128];
    __shared__ float sumA[64], sqA[64];

    int tid = threadIdx.x;
    int lane = tid & 31;
    int warp = tid >> 5;
    int grp = lane >> 2;
    int tig = lane & 3;
    int wm = warp >> 1;
    int wn = warp & 1;
    int e_base = wm * 32;
    int l_base = wn * 32;
    int l0 = blockIdx.x * 64;
    int et = blockIdx.y * 128;
    int b = blockIdx.z;

    if (LNX) {
        if (tid < 64) {
            int p = l0 + tid;
            mus[tid] = (p < L) ? mu[(size_t)b * L + p] : 0.f;
            ris[tid] = (p < L) ? ri[(size_t)b * L + p] : 0.f;
        }
        if (tid < 128) {
            gs[tid] = gamma[tid];
            bs2[tid] = beta[tid];
        }
    }
    if (STATS && tid < 64) { sumA[tid] = 0.f; sqA[tid] = 0.f; }
    __syncthreads();

    float c[8][4];
#pragma unroll
    for (int i = 0; i < 8; i++)
#pragma unroll
        for (int j = 0; j < 4; j++) c[i][j] = 0.f;

    for (int ks = 0; ks < 4; ks++) {
        int d0 = ks * 32;
        // X tile
#pragma unroll
        for (int r = 0; r < 8; r++) {
            int idx = tid + r * 256;
            int dd = idx >> 6;
            int ll = idx & 63;
            int lg = l0 + ll;
            float v = 0.f;
            if (lg < L) {
                v = X[((size_t)b * 128 + d0 + dd) * L + lg];
                if (LNX) v = gs[d0 + dd] * (v - mus[ll]) * ris[ll] + bs2[d0 + dd];
            }
            u32 hi, lo;
            tf32pair(v, hi, lo);
            Xhi[dd][ll] = hi;
            Xlo[dd][ll] = lo;
        }
        // W tile
#pragma unroll
        for (int r = 0; r < 16; r++) {
            int idx = tid + r * 256;
            float w;
            int dd, e;
            if (TR) {
                dd = idx >> 7;
                e = idx & 127;
                w = W[(size_t)(d0 + dd) * Etot + et + e];
            } else {
                e = idx >> 5;
                dd = idx & 31;
                w = W[(size_t)(et + e) * 128 + d0 + dd];
            }
            u32 hi, lo;
            tf32pair(w, hi, lo);
            Whi[dd][e] = hi;
            Wlo[dd][e] = lo;
        }
        __syncthreads();
#pragma unroll
        for (int kk = 0; kk < 4; kk++) {
            int k8 = kk * 8;
            u32 ahi[2][4], alo[2][4];
#pragma unroll
            for (int mt = 0; mt < 2; mt++) {
                int e = e_base + mt * 16 + grp;
                ahi[mt][0] = Whi[k8 + tig][e];
                ahi[mt][1] = Whi[k8 + tig][e + 8];
                ahi[mt][2] = Whi[k8 + tig + 4][e];
                ahi[mt][3] = Whi[k8 + tig + 4][e + 8];
                alo[mt][0] = Wlo[k8 + tig][e];
                alo[mt][1] = Wlo[k8 + tig][e + 8];
                alo[mt][2] = Wlo[k8 + tig + 4][e];
                alo[mt][3] = Wlo[k8 + tig + 4][e + 8];
            }
            u32 bhi[4][2], blo[4][2];
#pragma unroll
            for (int nt = 0; nt < 4; nt++) {
                int l = l_base + nt * 8 + grp;
                bhi[nt][0] = Xhi[k8 + tig][l];
                bhi[nt][1] = Xhi[k8 + tig + 4][l];
                blo[nt][0] = Xlo[k8 + tig][l];
                blo[nt][1] = Xlo[k8 + tig + 4][l];
            }
#pragma unroll
            for (int mt = 0; mt < 2; mt++)
#pragma unroll
                for (int nt = 0; nt < 4; nt++) {
                    float* cc2 = c[mt * 4 + nt];
                    mma8(cc2[0], cc2[1], cc2[2], cc2[3],
                         ahi[mt][0], ahi[mt][1], ahi[mt][2], ahi[mt][3],
                         bhi[nt][0], bhi[nt][1]);
                    mma8(cc2[0], cc2[1], cc2[2], cc2[3],
                         ahi[mt][0], ahi[mt][1], ahi[mt][2], ahi[mt][3],
                         blo[nt][0], blo[nt][1]);
                    mma8(cc2[0], cc2[1], cc2[2], cc2[3],
                         alo[mt][0], alo[mt][1], alo[mt][2], alo[mt][3],
                         bhi[nt][0], bhi[nt][1]);
                }
        }
        __syncthreads();
    }

#pragma unroll
    for (int mt = 0; mt < 2; mt++) {
#pragma unroll
        for (int nt = 0; nt < 4; nt++) {
            float* cc2 = c[mt * 4 + nt];
            int e0 = e_base + mt * 16 + grp;
            int ll = l_base + nt * 8 + tig * 2;
#pragma unroll
            for (int rr = 0; rr < 2; rr++) {
                int e = et + e0 + rr * 8;
                float bv = bias[e];
#pragma unroll
                for (int qq2 = 0; qq2 < 2; qq2++) {
                    int lg = l0 + ll + qq2;
                    if (lg < L) {
                        float v = cc2[rr * 2 + qq2] + bv;
                        if (RELU) v = fmaxf(v, 0.f);
                        size_t oi = ((size_t)b * Etot + e) * L + lg;
                        if (RES) v += res[oi];
                        out[oi] = v;
                        if (STATS) {
                            atomicAdd(&sumA[ll + qq2], v);
                            atomicAdd(&sqA[ll + qq2], v * v);
                        }
                    }
                }
            }
        }
    }
    if (STATS) {
        __syncthreads();
        if (tid < 64) {
            int lg = l0 + tid;
            if (lg < L) {
                float s = sumA[tid], ss2 = sqA[tid];
                float muv = s * (1.f / 128.f);
                float var = (ss2 - 128.f * muv * muv) * (1.f / 127.f);
                var = fmaxf(var, 0.f);
                omu[(size_t)b * L + lg] = muv;
                ori[(size_t)b * L + lg] = 1.f / (sqrtf(var) + 1e-6f);
            }
        }
    }
}

// ----------------------------- QKV packing ---------------------------------
__global__ void k_pack_qkv(const float* __restrict__ Wq, const float* __restrict__ Wk,
                           const float* __restrict__ Wv, const float* __restrict__ bq,
                           const float* __restrict__ bk, const float* __restrict__ bv) {
    int idx = blockIdx.x * blockDim.x + threadIdx.x;
    if (idx < 3 * 128 * 128) {
        int e = idx >> 7;
        int d = idx & 127;
        int qv = e >> 7;
        int hk = e & 127;
        int h = hk >> 4;
        int kk = hk & 15;
        const float* src = (qv == 0) ? Wq : (qv == 1 ? Wk : Wv);
        g_Wqkv[idx] = src[((size_t)h * 128 + d) * 16 + kk];
    }
    if (idx < 384) {
        int qv = idx >> 7;
        int hk = idx & 127;
        const float* srcb = (qv == 0) ? bq : (qv == 1 ? bk : bv);
        g_bqkv[idx] = srcb[hk];
    }
}

// ----------------------------- attention core ------------------------------
__global__ void __launch_bounds__(256) k_attn(const float* __restrict__ qkv,
                                              const float* __restrict__ mask,
                                              float* __restrict__ o, int L) {
    const int KT = 64;
    __shared__ u64 ks[KT][9], vs[KT][9];
    __shared__ float ms[KT];
    int tid = threadIdx.x;
    int bh = blockIdx.y;
    int b = bh >> 3;
    int h = bh & 7;
    int i = blockIdx.x * 256 + tid;
    bool act = i < L;

    u64 q2[8];
    if (act) {
        const float* qp = qkv + ((size_t)b * 384 + h * 16) * L + i;
#pragma unroll
        for (int c = 0; c < 8; c++)
            q2[c] = pk2(qp[(size_t)(2 * c) * L] * 0.25f, qp[(size_t)(2 * c + 1) * L] * 0.25f);
    }
    float m = -INFINITY, lsum = 0.f;
    u64 acc[8] = {0, 0, 0, 0, 0, 0, 0, 0};

    for (int j0 = 0; j0 < L; j0 += KT) {
        int cnt = min(KT, L - j0);
        for (int idx = tid; idx < 8 * KT; idx += 256) {
            int c = idx >> 6;
            int t = idx & 63;
            if (t < cnt) {
                const float* kp = qkv + ((size_t)b * 384 + 128 + h * 16 + 2 * c) * L + j0 + t;
                ks[t][c] = pk2(kp[0], kp[(size_t)L]);
                const float* vp = kp + (size_t)128 * L;
                vs[t][c] = pk2(vp[0], vp[(size_t)L]);
            } else {
                ks[t][c] = 0;
                vs[t][c] = 0;
            }
        }
        if (tid < KT) ms[tid] = (tid < cnt) ? mask[(size_t)b * L + j0 + tid] : 0.f;
        __syncthreads();
        if (act) {
            for (int g = 0; g < cnt; g += 8) {
                float sreg[8];
#pragma unroll
                for (int t2 = 0; t2 < 8; t2++) {
                    int t = g + t2;
                    u64 s2 = 0;
#pragma unroll
                    for (int c = 0; c < 8; c++) s2 = fma2(q2[c], ks[t][c], s2);
                    float slo, shi;
                    upk2(s2, slo, shi);
                    sreg[t2] = slo + shi - 1e30f * (1.f - ms[t]);
                }
                float gm = sreg[0];
#pragma unroll
                for (int t2 = 1; t2 < 8; t2++) gm = fmaxf(gm, sreg[t2]);
                float nm = fmaxf(m, gm);
                float sc = __expf(m - nm);
                lsum *= sc;
                u64 scp = pk2(sc, sc);
#pragma unroll
                for (int c = 0; c < 8; c++) acc[c] = mul2(scp, acc[c]);
#pragma unroll
                for (int t2 = 0; t2 < 8; t2++) {
                    int t = g + t2;
                    float p = __expf(sreg[t2] - nm);
                    lsum += p;
                    u64 pp = pk2(p, p);
#pragma unroll
                    for (int c = 0; c < 8; c++) acc[c] = fma2(pp, vs[t][c], acc[c]);
                }
                m = nm;
            }
        }
        __syncthreads();
    }
    if (act) {
        float r = 1.f / lsum;
        float* op = o + ((size_t)b * 128 + h * 16) * L + i;
#pragma unroll
        for (int c = 0; c < 8; c++) {
            float lo, hi;
            upk2(acc[c], lo, hi);
            op[(size_t)(2 * c) * L] = lo * r;
            op[(size_t)(2 * c + 1) * L] = hi * r;
        }
    }
}

// ------------------------------ transposes ---------------------------------
__global__ void k_trC(const float* __restrict__ X, float* __restrict__ Y, int L) {
    __shared__ float t[32][33];
    int b = blockIdx.z, d0 = blockIdx.y * 32, l0 = blockIdx.x * 32;
    int tx = threadIdx.x, ty = threadIdx.y;
#pragma unroll
    for (int k = 0; k < 4; k++) {
        int l = l0 + tx;
        t[ty + 8 * k][tx] = (l < L) ? X[((size_t)b * 128 + d0 + ty + 8 * k) * L + l] : 0.f;
    }
    __syncthreads();
#pragma unroll
    for (int k = 0; k < 4; k++) {
        int l = l0 + ty + 8 * k;
        if (l < L) Y[((size_t)b * L + l) * 128 + d0 + tx] = t[tx][ty + 8 * k];
    }
}

__global__ void k_trQ(const float* __restrict__ X, float* __restrict__ Yt,
                      float* __restrict__ Yw, const float* __restrict__ wm) {
    __shared__ float t[32][33];
    int b = blockIdx.z, d0 = blockIdx.y * 32, l0 = blockIdx.x * 32;
    int tx = threadIdx.x, ty = threadIdx.y;
#pragma unroll
    for (int k = 0; k < 4; k++) {
        int l = l0 + tx;
        t[ty + 8 * k][tx] = (l < kM) ? X[((size_t)b * 128 + d0 + ty + 8 * k) * kM + l] : 0.f;
    }
    __syncthreads();
    float w = wm[d0 + tx];
#pragma unroll
    for (int k = 0; k < 4; k++) {
        int l = l0 + ty + 8 * k;
        if (l < kM) {
            float v = t[tx][ty + 8 * k];
            size_t oi = ((size_t)b * kM + l) * 128 + d0 + tx;
            Yt[oi] = v;
            Yw[oi] = v * w;
        }
    }
}

// ------------------------------ CQ attention -------------------------------
__global__ void k_dot(const float* __restrict__ X, const float* __restrict__ w,
                      float* __restrict__ out, int L) {
    int idx = blockIdx.x * blockDim.x + threadIdx.x;
    if (idx >= kB * L) return;
    int b = idx / L;
    int pos = idx % L;
    const float* xp = X + (size_t)b * kD * L + pos;
    float a = 0.f;
#pragma unroll 8
    for (int d = 0; d < kD; d++) a += w[d] * xp[(size_t)d * L];
    out[idx] = a;
}

__global__ void __launch_bounds__(256) k_sgemm(const float* __restrict__ X,
                                               const float* __restrict__ Qw,
                                               const float* __restrict__ cc,
                                               const float* __restrict__ qq,
                                               const float* __restrict__ b0,
                                               float* __restrict__ S) {
    __shared__ float Xs[32][33];
    __shared__ float Ws[32][68];
    int tid = threadIdx.x;
    int l = tid & 31;
    int eg = tid >> 5;
    int l0 = blockIdx.x * 32;
    int b = blockIdx.y;
    u64 acc[4] = {0, 0, 0, 0};

    for (int d0 = 0; d0 < 128; d0 += 32) {
#pragma unroll
        for (int r = 0; r < 4; r++) {
            int idx = tid + r * 256;
            int dd = idx >> 5, ll = idx & 31;
            int lg = l0 + ll;
            Xs[dd][ll] = (lg < kN) ? X[((size_t)b * 128 + d0 + dd) * kN + lg] : 0.f;
        }
#pragma unroll
        for (int r = 0; r < 8; r++) {
            int idx = tid + r * 256;
            int dd = idx >> 6;
            int e = idx & 63;
            Ws[dd][e] = (e < kM) ? Qw[((size_t)b * kM + e) * 128 + d0 + dd] : 0.f;
        }
        __syncthreads();
#pragma unroll
        for (int dd = 0; dd < 32; dd++) {
            float xv = Xs[dd][l];
            u64 xx = pk2(xv, xv);
            const ulonglong2* wr = (const ulonglong2*)&Ws[dd][eg * 8];
            ulonglong2 w0 = wr[0], w1 = wr[1];
            acc[0] = fma2(xx, w0.x, acc[0]);
            acc[1] = fma2(xx, w0.y, acc[1]);
            acc[2] = fma2(xx, w1.x, acc[2]);
            acc[3] = fma2(xx, w1.y, acc[3]);
        }
        __syncthreads();
    }
    int lg = l0 + l;
    if (lg < kN) {
        float base = cc[b * kN + lg] + b0[0];
#pragma unroll
        for (int j = 0; j < 4; j++) {
            float v0, v1;
            upk2(acc[j], v0, v1);
            int e0 = eg * 8 + 2 * j;
            if (e0 < kM) S[((size_t)b * kM + e0) * kN + lg] = v0 + base + qq[b * kM + e0];
            if (e0 + 1 < kM) S[((size_t)b * kM + e0 + 1) * kN + lg] = v1 + base + qq[b * kM + e0 + 1];
        }
    }
}

__global__ void k_smrow(const float* __restrict__ qmask) {
    int idx = blockIdx.x * blockDim.x + threadIdx.x;
    if (idx >= kB * kN) return;
    int b = idx / kN;
    int n = idx % kN;
    float v[kM];
    float mx = -INFINITY;
#pragma unroll
    for (int m = 0; m < kM; m++) {
        v[m] = g_S[((size_t)b * kM + m) * kN + n] - 1e30f * (1.f - qmask[b * kM + m]);
        mx = fmaxf(mx, v[m]);
    }
    float s = 0.f;
#pragma unroll
    for (int m = 0; m < kM; m++) {
        v[m] = __expf(v[m] - mx);
        s += v[m];
    }
    float r = 1.f / s;
#pragma unroll
    for (int m = 0; m < kM; m++) g_Sr[((size_t)b * kM + m) * kN + n] = v[m] * r;
}

__global__ void k_smcol(const float* __restrict__ cmask) {
    int w = (blockIdx.x * blockDim.x + threadIdx.x) >> 5;
    int lane = threadIdx.x & 31;
    if (w >= kB * kM) return;
    int b = w / kM;
    const float* row = g_S + (size_t)w * kN;
    const float* mrow = cmask + (size_t)b * kN;
    float v[13];
#pragma unroll
    for (int k = 0; k < 13; k++) {
        int n = lane + k * 32;
        v[k] = (n < kN) ? row[n] - 1e30f * (1.f - mrow[n]) : -INFINITY;
    }
    float mx = v[0];
#pragma unroll
    for (int k = 1; k < 13; k++) mx = fmaxf(mx, v[k]);
#pragma unroll
    for (int o = 16; o; o >>= 1) mx = fmaxf(mx, __shfl_xor_sync(0xffffffff, mx, o));
    float s = 0.f;
    float e[13];
#pragma unroll
    for (int k = 0; k < 13; k++) {
        int n = lane + k * 32;
        e[k] = (n < kN) ? __expf(v[k] - mx) : 0.f;
        s += e[k];
    }
#pragma unroll
    for (int o = 16; o; o >>= 1) s += __shfl_xor_sync(0xffffffff, s, o);
    float r = 1.f / s;
    float* orow = g_Sc + (size_t)w * kN;
#pragma unroll
    for (int k = 0; k < 13; k++) {
        int n = lane + k * 32;
        if (n < kN) orow[n] = e[k] * r;
    }
}

__global__ void __launch_bounds__(512) k_U(const float* __restrict__ Ct) {
    int b = blockIdx.x;
    int tid = threadIdx.x;
    int d = tid & 127;
    int mq = tid >> 7;
    __shared__ float cts[16][128];
    __shared__ float scs[16][56];
    u64 acc[7] = {0, 0, 0, 0, 0, 0, 0};

    for (int n0 = 0; n0 < kN; n0 += 16) {
#pragma unroll
        for (int r = 0; r < 4; r++) {
            int idx = tid + r * 512;
            int n = idx >> 7, dd = idx & 127;
            cts[n][dd] = Ct[((size_t)b * kN + n0 + n) * 128 + dd];
        }
        for (int idx = tid; idx < 16 * 56; idx += 512) {
            int n = idx & 15;
            int m = idx >> 4;
            scs[n][m] = (m < kM) ? g_Sc[((size_t)b * kM + m) * kN + n0 + n] : 0.f;
        }
        __syncthreads();
#pragma unroll
        for (int n = 0; n < 16; n++) {
            float ct = cts[n][d];
            u64 c2 = pk2(ct, ct);
            const u64* sp = (const u64*)&scs[n][mq * 14];
#pragma unroll
            for (int j = 0; j < 7; j++) acc[j] = fma2(c2, sp[j], acc[j]);
        }
        __syncthreads();
    }
#pragma unroll
    for (int j = 0; j < 7; j++) {
        float v0, v1;
        upk2(acc[j], v0, v1);
        int m = mq * 14 + 2 * j;
        if (m < kM) g_U[((size_t)b * kM + m) * 128 + d] = v0;
        if (m + 1 < kM) g_U[((size_t)b * kM + m + 1) * 128 + d] = v1;
    }
}

__global__ void __launch_bounds__(256) k_out(const float* __restrict__ Ct,
                                             float* __restrict__ out) {
    int b = blockIdx.x / 25;
    int n0 = (blockIdx.x % 25) * 16;
    int tid = threadIdx.x;
    int d = tid & 127;
    int nq = tid >> 7;
    __shared__ float srs[kM][16];
    for (int idx = tid; idx < kM * 16; idx += 256) {
        int m = idx >> 4, nj = idx & 15;
        srs[m][nj] = g_Sr[((size_t)b * kM + m) * kN + n0 + nj];
    }
    __syncthreads();
    u64 a2[4] = {0, 0, 0, 0};
    u64 b2[4] = {0, 0, 0, 0};
    for (int m = 0; m < kM; m++) {
        float qv = g_Qt[((size_t)b * kM + m) * 128 + d];
        float uv = g_U[((size_t)b * kM + m) * 128 + d];
        u64 q2 = pk2(qv, qv), u2 = pk2(uv, uv);
        const u64* sp = (const u64*)&srs[m][nq * 8];
#pragma unroll
        for (int j = 0; j < 4; j++) {
            a2[j] = fma2(sp[j], q2, a2[j]);
            b2[j] = fma2(sp[j], u2, b2[j]);
        }
    }
#pragma unroll
    for (int j = 0; j < 4; j++) {
        float a0, a1, bt0, bt1;
        upk2(a2[j], a0, a1);
        upk2(b2[j], bt0, bt1);
#pragma unroll
        for (int t = 0; t < 2; t++) {
            int n = n0 + nq * 8 + 2 * j + t;
            float a = (t == 0) ? a0 : a1;
            float bt = (t == 0) ? bt0 : bt1;
            float c = Ct[((size_t)b * kN + n) * 128 + d];
            size_t base = ((size_t)b * kN + n) * 512;
            out[base + d] = c;
            out[base + 128 + d] = a;
            out[base + 256 + d] = c * a;
            out[base + 384 + d] = c * bt;
        }
    }
}

// ------------------------------- host side ---------------------------------
static inline int ceil_div(int a, int b) { return (a + b - 1) / b; }

extern "C" void kernel_launch(void* const* d_in, const int* in_sizes, int n_in,
                              void* d_out, int out_size) {
    (void)in_sizes; (void)n_in; (void)out_size;
    const float* ctx   = (const float*)d_in[0];
    const float* qst   = (const float*)d_in[1];
    const float* cmask = (const float*)d_in[2];
    const float* qmask = (const float*)d_in[3];
    const float* ln_g  = (const float*)d_in[4];
    const float* ln_b  = (const float*)d_in[5];
    const float* dww   = (const float*)d_in[6];
    const float* dwb   = (const float*)d_in[7];
    const float* pww   = (const float*)d_in[8];
    const float* pwb   = (const float*)d_in[9];
    const float* Wq    = (const float*)d_in[10];
    const float* bq    = (const float*)d_in[11];
    const float* Wk    = (const float*)d_in[12];
    const float* bk    = (const float*)d_in[13];
    const float* Wv    = (const float*)d_in[14];
    const float* bv    = (const float*)d_in[15];
    const float* Wo    = (const float*)d_in[16];
    const float* bo    = (const float*)d_in[17];
    const float* Wfc   = (const float*)d_in[18];
    const float* bfc   = (const float*)d_in[19];
    const float* cq_wc = (const float*)d_in[20];
    const float* cq_wq = (const float*)d_in[21];
    const float* cq_wm = (const float*)d_in[22];
    const float* cq_b  = (const float*)d_in[23];

    float *pC, *pQ, *pdw, *pQ2, *pqkv, *pao, *pcc, *pqq, *pCt, *pQt, *pQw, *pmu, *pri;
    cudaGetSymbolAddress((void**)&pC, g_C);
    cudaGetSymbolAddress((void**)&pQ, g_Q);
    cudaGetSymbolAddress((void**)&pdw, g_dw);
    cudaGetSymbolAddress((void**)&pQ2, g_Q2);
    cudaGetSymbolAddress((void**)&pqkv, g_qkv);
    cudaGetSymbolAddress((void**)&pao, g_ao);
    cudaGetSymbolAddress((void**)&pcc, g_cc);
    cudaGetSymbolAddress((void**)&pqq, g_qq);
    cudaGetSymbolAddress((void**)&pCt, g_Ct);
    cudaGetSymbolAddress((void**)&pQt, g_Qt);
    cudaGetSymbolAddress((void**)&pQw, g_Qw);
    cudaGetSymbolAddress((void**)&pmu, g_mu);
    cudaGetSymbolAddress((void**)&pri, g_ri);
    float* pWqkv; cudaGetSymbolAddress((void**)&pWqkv, g_Wqkv);
    float* pbqkv; cudaGetSymbolAddress((void**)&pbqkv, g_bqkv);
    float* pS;    cudaGetSymbolAddress((void**)&pS, g_S);

    k_pe<<<ceil_div(kD * kN, 256), 256>>>();
    k_pack_qkv<<<ceil_div(3 * 128 * 128, 256), 256>>>(Wq, Wk, Wv, bq, bk, bv);

    auto run_block = [&](const float* emb, float* act, float* alt, const float* msk, int L) {
        int lt = ceil_div(L, 64);
        k_add_pe_stats<<<ceil_div(kB * L, 32), 128>>>(emb, act, pmu, pri, L);
        float* bufs[2] = {act, alt};
        for (int i = 0; i < kNC; i++) {
            float* src = bufs[i & 1];
            float* dst = bufs[(i + 1) & 1];
            k_cgemm<<<dim3(lt, 1, kB), 256>>>(
                src, pww + (size_t)i * kD * kD, pwb + (size_t)i * kD,
                dww + (size_t)i * kD * kKW, dwb + (size_t)i * kD,
                ln_g, ln_b, pmu, pri, dst, pmu, pri, L);
        }
        k_gemm<false, false, false, true, false><<<dim3(lt, 3, kB), 256>>>(
            act, pWqkv, pbqkv, nullptr, pqkv, L, 384, pmu, pri, ln_g, ln_b, nullptr, nullptr);
        k_attn<<<dim3(ceil_div(L, 256), kB * kH), 256>>>(pqkv, msk, pao, L);
        k_gemm<true, false, true, false, true><<<dim3(lt, 1, kB), 256>>>(
            pao, Wo, bo, act, act, L, kD, nullptr, nullptr, nullptr, nullptr, pmu, pri);
        k_gemm<false, false, true, true, false><<<dim3(lt, 1, kB), 256>>>(
            act, Wfc, bfc, act, act, L, kD, pmu, pri, ln_g, ln_b, nullptr, nullptr);
    };

    run_block(ctx, pC, pdw, cmask, kN);
    run_block(qst, pQ, pQ2, qmask, kM);

    // --------- context-query attention ---------
    k_dot<<<ceil_div(kB * kN, 256), 256>>>(pC, cq_wc, pcc, kN);
    k_dot<<<ceil_div(kB * kM, 256), 256>>>(pQ, cq_wq, pqq, kM);
    k_trC<<<dim3(13, 4, kB), dim3(32, 8)>>>(pC, pCt, kN);
    k_trQ<<<dim3(2, 4, kB), dim3(32, 8)>>>(pQ, pQt, pQw, cq_wm);
    k_sgemm<<<dim3(13, kB), 256>>>(pC, pQw, pcc, pqq, cq_b, pS);
    k_smrow<<<ceil_div(kB * kN, 256), 256>>>(qmask);
    k_smcol<<<ceil_div(kB * kM * 32, 256), 256>>>(cmask);
    k_U<<<kB, 512>>>(pCt);
    k_out<<<kB * 25, 256>>>(pCt, (float*)d_out);
}

// round 10
// speedup vs baseline: 1.6791x; 1.6791x over previous
#include <cuda_runtime.h>
#include <math.h>

// ---------------------------------------------------------------------------
// QANet forward, fp32 on sm_103a.
// R10: R4 structure; GEMM inner loops use scalar FFMA (rt=2) with warp-uniform
//      W broadcasts instead of packed f32x2 (suspected rt=4 quarter-rate).
// ---------------------------------------------------------------------------
#define kB 64
#define kD 128
#define kN 400
#define kM 50
#define kH 8
#define kKD 16
#define kNC 4
#define kKW 7
#define kPAD 3

typedef unsigned long long u64;

__device__ __forceinline__ u64 pk2(float lo, float hi) {
    u64 r; asm("mov.b64 %0,{%1,%2};" : "=l"(r) : "f"(lo), "f"(hi)); return r;
}
__device__ __forceinline__ void upk2(u64 v, float& lo, float& hi) {
    asm("mov.b64 {%0,%1},%2;" : "=f"(lo), "=f"(hi) : "l"(v));
}
__device__ __forceinline__ u64 fma2(u64 a, u64 b, u64 c) {
    u64 d; asm("fma.rn.f32x2 %0,%1,%2,%3;" : "=l"(d) : "l"(a), "l"(b), "l"(c)); return d;
}
__device__ __forceinline__ u64 mul2(u64 a, u64 b) {
    u64 d; asm("mul.rn.f32x2 %0,%1,%2;" : "=l"(d) : "l"(a), "l"(b)); return d;
}

// ------------------------- device scratch (static) -------------------------
__device__ float g_C[kB * kD * kN];
__device__ float g_Q[kB * kD * kM];
__device__ float g_dw[kB * kD * kN];
__device__ float g_Q2[kB * kD * kM];
__device__ float g_qkv[kB * 3 * kD * kN];
__device__ float g_ao[kB * kD * kN];
__device__ float g_Wqkv[3 * kD * kD];   // [e][d]
__device__ float g_bqkv[3 * kD];
__device__ float g_pe[kD * kN];
__device__ float g_mu[kB * kN];
__device__ float g_ri[kB * kN];
__device__ float g_S[kB * kM * kN];
__device__ float g_Sr[kB * kM * kN];
__device__ float g_Sc[kB * kM * kN];
__device__ float g_U[kB * kM * kD];
__device__ float g_Ct[kB * kN * kD];
__device__ float g_Qt[kB * kM * kD];
__device__ float g_Qw[kB * kM * kD];
__device__ float g_cc[kB * kN];
__device__ float g_qq[kB * kM];

// ------------------------------ PE table ----------------------------------
__global__ void k_pe() {
    int idx = blockIdx.x * blockDim.x + threadIdx.x;
    if (idx >= kD * kN) return;
    int d = idx / kN;
    int l = idx % kN;
    int d0 = d & ~1;
    double f = pow(10000.0, -(double)d0 / (double)kD);
    double a = (double)l * f;
    g_pe[idx] = (d & 1) ? (float)cos(a) : (float)sin(a);
}

// ----------------- add PE + compute LN stats in one pass -------------------
__global__ void __launch_bounds__(128) k_add_pe_stats(const float* __restrict__ x,
                                                      float* __restrict__ y,
                                                      float* __restrict__ omu,
                                                      float* __restrict__ ori, int L) {
    int tid = threadIdx.x;
    int lsub = tid & 31;
    int grp = tid >> 5;
    int pos = blockIdx.x * 32 + lsub;
    int P = kB * L;
    bool ok = pos < P;
    int b = ok ? pos / L : 0;
    int l = ok ? pos % L : 0;

    float s = 0.f, sq = 0.f;
    if (ok) {
        const float* xp = x + ((size_t)b * kD + grp * 32) * L + l;
        float* yp = y + ((size_t)b * kD + grp * 32) * L + l;
#pragma unroll
        for (int k = 0; k < 32; k++) {
            int d = grp * 32 + k;
            float v = xp[(size_t)k * L] + g_pe[d * kN + l];
            yp[(size_t)k * L] = v;
            s += v;
            sq += v * v;
        }
    }
    __shared__ float ss[4][32], sb[4][32];
    ss[grp][lsub] = s;
    sb[grp][lsub] = sq;
    __syncthreads();
    if (grp == 0 && ok) {
        float ts = ss[0][lsub] + ss[1][lsub] + ss[2][lsub] + ss[3][lsub];
        float tq = sb[0][lsub] + sb[1][lsub] + sb[2][lsub] + sb[3][lsub];
        float mu = ts * (1.f / 128.f);
        float var = (tq - 128.f * mu * mu) * (1.f / 127.f);
        var = fmaxf(var, 0.f);
        omu[pos] = mu;
        ori[pos] = 1.f / (sqrtf(var) + 1e-6f);
    }
}

// ---------------- fused LN + depthwise conv + pointwise GEMM ----------------
// 256 threads = 8 warps. Block tile 128e x 64l.
// eq = tid>>5 (warp -> 16 e's, W reads warp-uniform broadcast);
// lq = tid&31 (lane -> 2 l's). Scalar FFMA inner loop.
__global__ void __launch_bounds__(256) k_cgemm(const float* __restrict__ X,
                                               const float* __restrict__ Wpw,  // [e][d]
                                               const float* __restrict__ pwb,
                                               const float* __restrict__ cw,
                                               const float* __restrict__ cb,
                                               const float* __restrict__ gamma,
                                               const float* __restrict__ beta,
                                               const float* __restrict__ mu,
                                               const float* __restrict__ ri,
                                               float* __restrict__ out,
                                               float* __restrict__ omu,
                                               float* __restrict__ ori, int L) {
    __shared__ __align__(16) float Xl[32][72];
    __shared__ __align__(16) float Xs[32][68];
    __shared__ __align__(16) float Ws[32][132];
    __shared__ float mus[72], ris[72];
    __shared__ float gs[128], bs2[128];
    __shared__ float cws[128][8];

    int tid = threadIdx.x;
    int eq = tid >> 5;
    int lq = tid & 31;
    int l0 = blockIdx.x * 64;
    int b = blockIdx.z;

    if (tid < 70) {
        int gl = l0 + tid - 3;
        bool in = (gl >= 0 && gl < L);
        mus[tid] = in ? mu[(size_t)b * L + gl] : 0.f;
        ris[tid] = in ? ri[(size_t)b * L + gl] : 0.f;
    }
    if (tid < 128) {
        gs[tid] = gamma[tid];
        bs2[tid] = beta[tid];
#pragma unroll
        for (int k = 0; k < 7; k++) cws[tid][k] = cw[tid * 7 + k];
        cws[tid][7] = cb[tid];
    }
    __syncthreads();

    float acc[32];
#pragma unroll
    for (int j = 0; j < 32; j++) acc[j] = 0.f;

    for (int k = 0; k < 4; k++) {
        int d0 = k * 32;
        // LN'd halo tile (32 x 70)
#pragma unroll
        for (int r = 0; r < 9; r++) {
            int idx = tid + r * 256;
            if (idx < 2240) {
                int dd = idx / 70;
                int ll = idx - dd * 70;
                int gl = l0 + ll - 3;
                float v = 0.f;
                if (gl >= 0 && gl < L) {
                    float xv = X[((size_t)b * 128 + d0 + dd) * L + gl];
                    v = gs[d0 + dd] * (xv - mus[ll]) * ris[ll] + bs2[d0 + dd];
                }
                Xl[dd][ll] = v;
            }
        }
        // pw weights: Ws[dd][e]
#pragma unroll
        for (int r = 0; r < 16; r++) {
            int idx = tid + r * 256;
            int e = idx >> 5;
            int dd = idx & 31;
            Ws[dd][e] = Wpw[(size_t)e * 128 + d0 + dd];
        }
        __syncthreads();
        // depthwise conv -> Xs
#pragma unroll
        for (int r = 0; r < 8; r++) {
            int idx = tid + r * 256;
            int dd = idx >> 6;
            int ll = idx & 63;
            int d = d0 + dd;
            float a = cws[d][7];
#pragma unroll
            for (int kk = 0; kk < 7; kk++) a += cws[d][kk] * Xl[dd][ll + kk];
            Xs[dd][ll] = a;
        }
        __syncthreads();
        // scalar FFMA main loop: 16e x 2l per thread
#pragma unroll
        for (int dd = 0; dd < 32; dd++) {
            float2 xv = *(const float2*)&Xs[dd][lq * 2];
            const float4* wp = (const float4*)&Ws[dd][eq * 16];
            float4 w0 = wp[0], w1 = wp[1], w2 = wp[2], w3 = wp[3];
            acc[0]  += w0.x * xv.x;  acc[1]  += w0.x * xv.y;
            acc[2]  += w0.y * xv.x;  acc[3]  += w0.y * xv.y;
            acc[4]  += w0.z * xv.x;  acc[5]  += w0.z * xv.y;
            acc[6]  += w0.w * xv.x;  acc[7]  += w0.w * xv.y;
            acc[8]  += w1.x * xv.x;  acc[9]  += w1.x * xv.y;
            acc[10] += w1.y * xv.x;  acc[11] += w1.y * xv.y;
            acc[12] += w1.z * xv.x;  acc[13] += w1.z * xv.y;
            acc[14] += w1.w * xv.x;  acc[15] += w1.w * xv.y;
            acc[16] += w2.x * xv.x;  acc[17] += w2.x * xv.y;
            acc[18] += w2.y * xv.x;  acc[19] += w2.y * xv.y;
            acc[20] += w2.z * xv.x;  acc[21] += w2.z * xv.y;
            acc[22] += w2.w * xv.x;  acc[23] += w2.w * xv.y;
            acc[24] += w3.x * xv.x;  acc[25] += w3.x * xv.y;
            acc[26] += w3.y * xv.x;  acc[27] += w3.y * xv.y;
            acc[28] += w3.z * xv.x;  acc[29] += w3.z * xv.y;
            acc[30] += w3.w * xv.x;  acc[31] += w3.w * xv.y;
        }
        __syncthreads();
    }

    float sum_l[2] = {0.f, 0.f};
    float sq_l[2] = {0.f, 0.f};
#pragma unroll
    for (int p = 0; p < 16; p++) {
        int e0 = eq * 16 + p;
        float bv = pwb[e0];
#pragma unroll
        for (int q = 0; q < 2; q++) {
            float v = fmaxf(acc[p * 2 + q] + bv, 0.f);
            int lg = l0 + lq * 2 + q;
            if (lg < L) {
                size_t oi = ((size_t)b * 128 + e0) * L + lg;
                v += X[oi];
                out[oi] = v;
            }
            sum_l[q] += v;
            sq_l[q] += v * v;
        }
    }
    // stats reduction overlay on Ws (dead): red1 [8][64] at 0, red2 at 512
    float* red = &Ws[0][0];
    red[eq * 64 + lq * 2 + 0] = sum_l[0];
    red[eq * 64 + lq * 2 + 1] = sum_l[1];
    red[512 + eq * 64 + lq * 2 + 0] = sq_l[0];
    red[512 + eq * 64 + lq * 2 + 1] = sq_l[1];
    __syncthreads();
    if (tid < 64) {
        int lg = l0 + tid;
        if (lg < L) {
            float s = 0.f, ss = 0.f;
#pragma unroll
            for (int g = 0; g < 8; g++) {
                s += red[g * 64 + tid];
                ss += red[512 + g * 64 + tid];
            }
            float muv = s * (1.f / 128.f);
            float var = (ss - 128.f * muv * muv) * (1.f / 127.f);
            var = fmaxf(var, 0.f);
            omu[(size_t)b * L + lg] = muv;
            ori[(size_t)b * L + lg] = 1.f / (sqrtf(var) + 1e-6f);
        }
    }
}

// ------------------------------- GEMM --------------------------------------
// Same tiling; scalar FFMA; W broadcast. TR=false: W [e][128]; TR=true: [d][Etot].
template <bool TR, bool RELU, bool RES, bool LNX, bool STATS>
__global__ void __launch_bounds__(256) k_gemm(const float* __restrict__ X,
                                              const float* __restrict__ W,
                                              const float* __restrict__ bias,
                                              const float* res, float* out,
                                              int L, int Etot,
                                              const float* __restrict__ mu,
                                              const float* __restrict__ ri,
                                              const float* __restrict__ gamma,
                                              const float* __restrict__ beta,
                                              float* omu, float* ori) {
    __shared__ __align__(16) float Xs[32][68];
    __shared__ __align__(16) float Ws[32][132];
    __shared__ float mus[64], ris[64];
    __shared__ float gs[128], bs2[128];

    int tid = threadIdx.x;
    int eq = tid >> 5;
    int lq = tid & 31;
    int l0 = blockIdx.x * 64;
    int et = blockIdx.y * 128;
    int b = blockIdx.z;

    if (LNX) {
        if (tid < 64) {
            int p = l0 + tid;
            mus[tid] = (p < L) ? mu[(size_t)b * L + p] : 0.f;
            ris[tid] = (p < L) ? ri[(size_t)b * L + p] : 0.f;
        }
        if (tid < 128) {
            gs[tid] = gamma[tid];
            bs2[tid] = beta[tid];
        }
        __syncthreads();
    }

    float acc[32];
#pragma unroll
    for (int j = 0; j < 32; j++) acc[j] = 0.f;

    for (int k = 0; k < 4; k++) {
        int d0 = k * 32;
#pragma unroll
        for (int r = 0; r < 8; r++) {
            int idx = tid + r * 256;
            int dd = idx >> 6;
            int ll = idx & 63;
            int lg = l0 + ll;
            float v = 0.f;
            if (lg < L) {
                v = X[((size_t)b * 128 + d0 + dd) * L + lg];
                if (LNX) v = gs[d0 + dd] * (v - mus[ll]) * ris[ll] + bs2[d0 + dd];
            }
            Xs[dd][ll] = v;
        }
#pragma unroll
        for (int r = 0; r < 16; r++) {
            int idx = tid + r * 256;
            if (TR) {
                int dd = idx >> 7;
                int e = idx & 127;
                Ws[dd][e] = W[(size_t)(d0 + dd) * Etot + et + e];
            } else {
                int e = idx >> 5;
                int dd = idx & 31;
                Ws[dd][e] = W[(size_t)(et + e) * 128 + d0 + dd];
            }
        }
        __syncthreads();
#pragma unroll
        for (int dd = 0; dd < 32; dd++) {
            float2 xv = *(const float2*)&Xs[dd][lq * 2];
            const float4* wp = (const float4*)&Ws[dd][eq * 16];
            float4 w0 = wp[0], w1 = wp[1], w2 = wp[2], w3 = wp[3];
            acc[0]  += w0.x * xv.x;  acc[1]  += w0.x * xv.y;
            acc[2]  += w0.y * xv.x;  acc[3]  += w0.y * xv.y;
            acc[4]  += w0.z * xv.x;  acc[5]  += w0.z * xv.y;
            acc[6]  += w0.w * xv.x;  acc[7]  += w0.w * xv.y;
            acc[8]  += w1.x * xv.x;  acc[9]  += w1.x * xv.y;
            acc[10] += w1.y * xv.x;  acc[11] += w1.y * xv.y;
            acc[12] += w1.z * xv.x;  acc[13] += w1.z * xv.y;
            acc[14] += w1.w * xv.x;  acc[15] += w1.w * xv.y;
            acc[16] += w2.x * xv.x;  acc[17] += w2.x * xv.y;
            acc[18] += w2.y * xv.x;  acc[19] += w2.y * xv.y;
            acc[20] += w2.z * xv.x;  acc[21] += w2.z * xv.y;
            acc[22] += w2.w * xv.x;  acc[23] += w2.w * xv.y;
            acc[24] += w3.x * xv.x;  acc[25] += w3.x * xv.y;
            acc[26] += w3.y * xv.x;  acc[27] += w3.y * xv.y;
            acc[28] += w3.z * xv.x;  acc[29] += w3.z * xv.y;
            acc[30] += w3.w * xv.x;  acc[31] += w3.w * xv.y;
        }
        __syncthreads();
    }

    float sum_l[2] = {0.f, 0.f};
    float sq_l[2] = {0.f, 0.f};
#pragma unroll
    for (int p = 0; p < 16; p++) {
        int e0 = et + eq * 16 + p;
        float bv = bias[e0];
#pragma unroll
        for (int q = 0; q < 2; q++) {
            float v = acc[p * 2 + q] + bv;
            if (RELU) v = fmaxf(v, 0.f);
            int lg = l0 + lq * 2 + q;
            if (lg < L) {
                size_t oi = ((size_t)b * Etot + e0) * L + lg;
                if (RES) v += res[oi];
                out[oi] = v;
            }
            if (STATS) {
                sum_l[q] += v;
                sq_l[q] += v * v;
            }
        }
    }
    if (STATS) {
        float* red = &Ws[0][0];
        red[eq * 64 + lq * 2 + 0] = sum_l[0];
        red[eq * 64 + lq * 2 + 1] = sum_l[1];
        red[512 + eq * 64 + lq * 2 + 0] = sq_l[0];
        red[512 + eq * 64 + lq * 2 + 1] = sq_l[1];
        __syncthreads();
        if (tid < 64) {
            int lg = l0 + tid;
            if (lg < L) {
                float s = 0.f, ss = 0.f;
#pragma unroll
                for (int g = 0; g < 8; g++) {
                    s += red[g * 64 + tid];
                    ss += red[512 + g * 64 + tid];
                }
                float muv = s * (1.f / 128.f);
                float var = (ss - 128.f * muv * muv) * (1.f / 127.f);
                var = fmaxf(var, 0.f);
                omu[(size_t)b * L + lg] = muv;
                ori[(size_t)b * L + lg] = 1.f / (sqrtf(var) + 1e-6f);
            }
        }
    }
}

// ----------------------------- QKV packing ---------------------------------
__global__ void k_pack_qkv(const float* __restrict__ Wq, const float* __restrict__ Wk,
                           const float* __restrict__ Wv, const float* __restrict__ bq,
                           const float* __restrict__ bk, const float* __restrict__ bv) {
    int idx = blockIdx.x * blockDim.x + threadIdx.x;
    if (idx < 3 * 128 * 128) {
        int e = idx >> 7;
        int d = idx & 127;
        int qv = e >> 7;
        int hk = e & 127;
        int h = hk >> 4;
        int kk = hk & 15;
        const float* src = (qv == 0) ? Wq : (qv == 1 ? Wk : Wv);
        g_Wqkv[idx] = src[((size_t)h * 128 + d) * 16 + kk];
    }
    if (idx < 384) {
        int qv = idx >> 7;
        int hk = idx & 127;
        const float* srcb = (qv == 0) ? bq : (qv == 1 ? bk : bv);
        g_bqkv[idx] = srcb[hk];
    }
}

// ----------------------------- attention core ------------------------------
__global__ void __launch_bounds__(256) k_attn(const float* __restrict__ qkv,
                                              const float* __restrict__ mask,
                                              float* __restrict__ o, int L) {
    const int KT = 64;
    __shared__ u64 ks[KT][9], vs[KT][9];
    __shared__ float ms[KT];
    int tid = threadIdx.x;
    int bh = blockIdx.y;
    int b = bh >> 3;
    int h = bh & 7;
    int i = blockIdx.x * 256 + tid;
    bool act = i < L;

    u64 q2[8];
    if (act) {
        const float* qp = qkv + ((size_t)b * 384 + h * 16) * L + i;
#pragma unroll
        for (int c = 0; c < 8; c++)
            q2[c] = pk2(qp[(size_t)(2 * c) * L] * 0.25f, qp[(size_t)(2 * c + 1) * L] * 0.25f);
    }
    float m = -INFINITY, lsum = 0.f;
    u64 acc[8] = {0, 0, 0, 0, 0, 0, 0, 0};

    for (int j0 = 0; j0 < L; j0 += KT) {
        int cnt = min(KT, L - j0);
        for (int idx = tid; idx < 8 * KT; idx += 256) {
            int c = idx >> 6;
            int t = idx & 63;
            if (t < cnt) {
                const float* kp = qkv + ((size_t)b * 384 + 128 + h * 16 + 2 * c) * L + j0 + t;
                ks[t][c] = pk2(kp[0], kp[(size_t)L]);
                const float* vp = kp + (size_t)128 * L;
                vs[t][c] = pk2(vp[0], vp[(size_t)L]);
            } else {
                ks[t][c] = 0;
                vs[t][c] = 0;
            }
        }
        if (tid < KT) ms[tid] = (tid < cnt) ? mask[(size_t)b * L + j0 + tid] : 0.f;
        __syncthreads();
        if (act) {
            for (int g = 0; g < cnt; g += 8) {
                float sreg[8];
#pragma unroll
                for (int t2 = 0; t2 < 8; t2++) {
                    int t = g + t2;
                    u64 s2 = 0;
#pragma unroll
                    for (int c = 0; c < 8; c++) s2 = fma2(q2[c], ks[t][c], s2);
                    float slo, shi;
                    upk2(s2, slo, shi);
                    sreg[t2] = slo + shi - 1e30f * (1.f - ms[t]);
                }
                float gm = sreg[0];
#pragma unroll
                for (int t2 = 1; t2 < 8; t2++) gm = fmaxf(gm, sreg[t2]);
                float nm = fmaxf(m, gm);
                float sc = __expf(m - nm);
                lsum *= sc;
                u64 scp = pk2(sc, sc);
#pragma unroll
                for (int c = 0; c < 8; c++) acc[c] = mul2(scp, acc[c]);
#pragma unroll
                for (int t2 = 0; t2 < 8; t2++) {
                    int t = g + t2;
                    float p = __expf(sreg[t2] - nm);
                    lsum += p;
                    u64 pp = pk2(p, p);
#pragma unroll
                    for (int c = 0; c < 8; c++) acc[c] = fma2(pp, vs[t][c], acc[c]);
                }
                m = nm;
            }
        }
        __syncthreads();
    }
    if (act) {
        float r = 1.f / lsum;
        float* op = o + ((size_t)b * 128 + h * 16) * L + i;
#pragma unroll
        for (int c = 0; c < 8; c++) {
            float lo, hi;
            upk2(acc[c], lo, hi);
            op[(size_t)(2 * c) * L] = lo * r;
            op[(size_t)(2 * c + 1) * L] = hi * r;
        }
    }
}

// ------------------------------ transposes ---------------------------------
__global__ void k_trC(const float* __restrict__ X, float* __restrict__ Y, int L) {
    __shared__ float t[32][33];
    int b = blockIdx.z, d0 = blockIdx.y * 32, l0 = blockIdx.x * 32;
    int tx = threadIdx.x, ty = threadIdx.y;
#pragma unroll
    for (int k = 0; k < 4; k++) {
        int l = l0 + tx;
        t[ty + 8 * k][tx] = (l < L) ? X[((size_t)b * 128 + d0 + ty + 8 * k) * L + l] : 0.f;
    }
    __syncthreads();
#pragma unroll
    for (int k = 0; k < 4; k++) {
        int l = l0 + ty + 8 * k;
        if (l < L) Y[((size_t)b * L + l) * 128 + d0 + tx] = t[tx][ty + 8 * k];
    }
}

__global__ void k_trQ(const float* __restrict__ X, float* __restrict__ Yt,
                      float* __restrict__ Yw, const float* __restrict__ wm) {
    __shared__ float t[32][33];
    int b = blockIdx.z, d0 = blockIdx.y * 32, l0 = blockIdx.x * 32;
    int tx = threadIdx.x, ty = threadIdx.y;
#pragma unroll
    for (int k = 0; k < 4; k++) {
        int l = l0 + tx;
        t[ty + 8 * k][tx] = (l < kM) ? X[((size_t)b * 128 + d0 + ty + 8 * k) * kM + l] : 0.f;
    }
    __syncthreads();
    float w = wm[d0 + tx];
#pragma unroll
    for (int k = 0; k < 4; k++) {
        int l = l0 + ty + 8 * k;
        if (l < kM) {
            float v = t[tx][ty + 8 * k];
            size_t oi = ((size_t)b * kM + l) * 128 + d0 + tx;
            Yt[oi] = v;
            Yw[oi] = v * w;
        }
    }
}

// ------------------------------ CQ attention -------------------------------
__global__ void k_dot(const float* __restrict__ X, const float* __restrict__ w,
                      float* __restrict__ out, int L) {
    int idx = blockIdx.x * blockDim.x + threadIdx.x;
    if (idx >= kB * L) return;
    int b = idx / L;
    int pos = idx % L;
    const float* xp = X + (size_t)b * kD * L + pos;
    float a = 0.f;
#pragma unroll 8
    for (int d = 0; d < kD; d++) a += w[d] * xp[(size_t)d * L];
    out[idx] = a;
}

__global__ void __launch_bounds__(256) k_sgemm(const float* __restrict__ X,
                                               const float* __restrict__ Qw,
                                               const float* __restrict__ cc,
                                               const float* __restrict__ qq,
                                               const float* __restrict__ b0,
                                               float* __restrict__ S) {
    __shared__ float Xs[32][33];
    __shared__ float Ws[32][68];
    int tid = threadIdx.x;
    int l = tid & 31;
    int eg = tid >> 5;
    int l0 = blockIdx.x * 32;
    int b = blockIdx.y;
    u64 acc[4] = {0, 0, 0, 0};

    for (int d0 = 0; d0 < 128; d0 += 32) {
#pragma unroll
        for (int r = 0; r < 4; r++) {
            int idx = tid + r * 256;
            int dd = idx >> 5, ll = idx & 31;
            int lg = l0 + ll;
            Xs[dd][ll] = (lg < kN) ? X[((size_t)b * 128 + d0 + dd) * kN + lg] : 0.f;
        }
#pragma unroll
        for (int r = 0; r < 8; r++) {
            int idx = tid + r * 256;
            int dd = idx >> 6;
            int e = idx & 63;
            Ws[dd][e] = (e < kM) ? Qw[((size_t)b * kM + e) * 128 + d0 + dd] : 0.f;
        }
        __syncthreads();
#pragma unroll
        for (int dd = 0; dd < 32; dd++) {
            float xv = Xs[dd][l];
            u64 xx = pk2(xv, xv);
            const ulonglong2* wr = (const ulonglong2*)&Ws[dd][eg * 8];
            ulonglong2 w0 = wr[0], w1 = wr[1];
            acc[0] = fma2(xx, w0.x, acc[0]);
            acc[1] = fma2(xx, w0.y, acc[1]);
            acc[2] = fma2(xx, w1.x, acc[2]);
            acc[3] = fma2(xx, w1.y, acc[3]);
        }
        __syncthreads();
    }
    int lg = l0 + l;
    if (lg < kN) {
        float base = cc[b * kN + lg] + b0[0];
#pragma unroll
        for (int j = 0; j < 4; j++) {
            float v0, v1;
            upk2(acc[j], v0, v1);
            int e0 = eg * 8 + 2 * j;
            if (e0 < kM) S[((size_t)b * kM + e0) * kN + lg] = v0 + base + qq[b * kM + e0];
            if (e0 + 1 < kM) S[((size_t)b * kM + e0 + 1) * kN + lg] = v1 + base + qq[b * kM + e0 + 1];
        }
    }
}

__global__ void k_smrow(const float* __restrict__ qmask) {
    int idx = blockIdx.x * blockDim.x + threadIdx.x;
    if (idx >= kB * kN) return;
    int b = idx / kN;
    int n = idx % kN;
    float v[kM];
    float mx = -INFINITY;
#pragma unroll
    for (int m = 0; m < kM; m++) {
        v[m] = g_S[((size_t)b * kM + m) * kN + n] - 1e30f * (1.f - qmask[b * kM + m]);
        mx = fmaxf(mx, v[m]);
    }
    float s = 0.f;
#pragma unroll
    for (int m = 0; m < kM; m++) {
        v[m] = __expf(v[m] - mx);
        s += v[m];
    }
    float r = 1.f / s;
#pragma unroll
    for (int m = 0; m < kM; m++) g_Sr[((size_t)b * kM + m) * kN + n] = v[m] * r;
}

__global__ void k_smcol(const float* __restrict__ cmask) {
    int w = (blockIdx.x * blockDim.x + threadIdx.x) >> 5;
    int lane = threadIdx.x & 31;
    if (w >= kB * kM) return;
    int b = w / kM;
    const float* row = g_S + (size_t)w * kN;
    const float* mrow = cmask + (size_t)b * kN;
    float v[13];
#pragma unroll
    for (int k = 0; k < 13; k++) {
        int n = lane + k * 32;
        v[k] = (n < kN) ? row[n] - 1e30f * (1.f - mrow[n]) : -INFINITY;
    }
    float mx = v[0];
#pragma unroll
    for (int k = 1; k < 13; k++) mx = fmaxf(mx, v[k]);
#pragma unroll
    for (int o = 16; o; o >>= 1) mx = fmaxf(mx, __shfl_xor_sync(0xffffffff, mx, o));
    float s = 0.f;
    float e[13];
#pragma unroll
    for (int k = 0; k < 13; k++) {
        int n = lane + k * 32;
        e[k] = (n < kN) ? __expf(v[k] - mx) : 0.f;
        s += e[k];
    }
#pragma unroll
    for (int o = 16; o; o >>= 1) s += __shfl_xor_sync(0xffffffff, s, o);
    float r = 1.f / s;
    float* orow = g_Sc + (size_t)w * kN;
#pragma unroll
    for (int k = 0; k < 13; k++) {
        int n = lane + k * 32;
        if (n < kN) orow[n] = e[k] * r;
    }
}

__global__ void __launch_bounds__(512) k_U(const float* __restrict__ Ct) {
    int b = blockIdx.x;
    int tid = threadIdx.x;
    int d = tid & 127;
    int mq = tid >> 7;
    __shared__ float cts[16][128];
    __shared__ float scs[16][56];
    u64 acc[7] = {0, 0, 0, 0, 0, 0, 0};

    for (int n0 = 0; n0 < kN; n0 += 16) {
#pragma unroll
        for (int r = 0; r < 4; r++) {
            int idx = tid + r * 512;
            int n = idx >> 7, dd = idx & 127;
            cts[n][dd] = Ct[((size_t)b * kN + n0 + n) * 128 + dd];
        }
        for (int idx = tid; idx < 16 * 56; idx += 512) {
            int n = idx & 15;
            int m = idx >> 4;
            scs[n][m] = (m < kM) ? g_Sc[((size_t)b * kM + m) * kN + n0 + n] : 0.f;
        }
        __syncthreads();
#pragma unroll
        for (int n = 0; n < 16; n++) {
            float ct = cts[n][d];
            u64 c2 = pk2(ct, ct);
            const u64* sp = (const u64*)&scs[n][mq * 14];
#pragma unroll
            for (int j = 0; j < 7; j++) acc[j] = fma2(c2, sp[j], acc[j]);
        }
        __syncthreads();
    }
#pragma unroll
    for (int j = 0; j < 7; j++) {
        float v0, v1;
        upk2(acc[j], v0, v1);
        int m = mq * 14 + 2 * j;
        if (m < kM) g_U[((size_t)b * kM + m) * 128 + d] = v0;
        if (m + 1 < kM) g_U[((size_t)b * kM + m + 1) * 128 + d] = v1;
    }
}

__global__ void __launch_bounds__(256) k_out(const float* __restrict__ Ct,
                                             float* __restrict__ out) {
    int b = blockIdx.x / 25;
    int n0 = (blockIdx.x % 25) * 16;
    int tid = threadIdx.x;
    int d = tid & 127;
    int nq = tid >> 7;
    __shared__ float srs[kM][16];
    for (int idx = tid; idx < kM * 16; idx += 256) {
        int m = idx >> 4, nj = idx & 15;
        srs[m][nj] = g_Sr[((size_t)b * kM + m) * kN + n0 + nj];
    }
    __syncthreads();
    u64 a2[4] = {0, 0, 0, 0};
    u64 b2[4] = {0, 0, 0, 0};
    for (int m = 0; m < kM; m++) {
        float qv = g_Qt[((size_t)b * kM + m) * 128 + d];
        float uv = g_U[((size_t)b * kM + m) * 128 + d];
        u64 q2 = pk2(qv, qv), u2 = pk2(uv, uv);
        const u64* sp = (const u64*)&srs[m][nq * 8];
#pragma unroll
        for (int j = 0; j < 4; j++) {
            a2[j] = fma2(sp[j], q2, a2[j]);
            b2[j] = fma2(sp[j], u2, b2[j]);
        }
    }
#pragma unroll
    for (int j = 0; j < 4; j++) {
        float a0, a1, bt0, bt1;
        upk2(a2[j], a0, a1);
        upk2(b2[j], bt0, bt1);
#pragma unroll
        for (int t = 0; t < 2; t++) {
            int n = n0 + nq * 8 + 2 * j + t;
            float a = (t == 0) ? a0 : a1;
            float bt = (t == 0) ? bt0 : bt1;
            float c = Ct[((size_t)b * kN + n) * 128 + d];
            size_t base = ((size_t)b * kN + n) * 512;
            out[base + d] = c;
            out[base + 128 + d] = a;
            out[base + 256 + d] = c * a;
            out[base + 384 + d] = c * bt;
        }
    }
}

// ------------------------------- host side ---------------------------------
static inline int ceil_div(int a, int b) { return (a + b - 1) / b; }

extern "C" void kernel_launch(void* const* d_in, const int* in_sizes, int n_in,
                              void* d_out, int out_size) {
    (void)in_sizes; (void)n_in; (void)out_size;
    const float* ctx   = (const float*)d_in[0];
    const float* qst   = (const float*)d_in[1];
    const float* cmask = (const float*)d_in[2];
    const float* qmask = (const float*)d_in[3];
    const float* ln_g  = (const float*)d_in[4];
    const float* ln_b  = (const float*)d_in[5];
    const float* dww   = (const float*)d_in[6];
    const float* dwb   = (const float*)d_in[7];
    const float* pww   = (const float*)d_in[8];
    const float* pwb   = (const float*)d_in[9];
    const float* Wq    = (const float*)d_in[10];
    const float* bq    = (const float*)d_in[11];
    const float* Wk    = (const float*)d_in[12];
    const float* bk    = (const float*)d_in[13];
    const float* Wv    = (const float*)d_in[14];
    const float* bv    = (const float*)d_in[15];
    const float* Wo    = (const float*)d_in[16];
    const float* bo    = (const float*)d_in[17];
    const float* Wfc   = (const float*)d_in[18];
    const float* bfc   = (const float*)d_in[19];
    const float* cq_wc = (const float*)d_in[20];
    const float* cq_wq = (const float*)d_in[21];
    const float* cq_wm = (const float*)d_in[22];
    const float* cq_b  = (const float*)d_in[23];

    float *pC, *pQ, *pdw, *pQ2, *pqkv, *pao, *pcc, *pqq, *pCt, *pQt, *pQw, *pmu, *pri;
    cudaGetSymbolAddress((void**)&pC, g_C);
    cudaGetSymbolAddress((void**)&pQ, g_Q);
    cudaGetSymbolAddress((void**)&pdw, g_dw);
    cudaGetSymbolAddress((void**)&pQ2, g_Q2);
    cudaGetSymbolAddress((void**)&pqkv, g_qkv);
    cudaGetSymbolAddress((void**)&pao, g_ao);
    cudaGetSymbolAddress((void**)&pcc, g_cc);
    cudaGetSymbolAddress((void**)&pqq, g_qq);
    cudaGetSymbolAddress((void**)&pCt, g_Ct);
    cudaGetSymbolAddress((void**)&pQt, g_Qt);
    cudaGetSymbolAddress((void**)&pQw, g_Qw);
    cudaGetSymbolAddress((void**)&pmu, g_mu);
    cudaGetSymbolAddress((void**)&pri, g_ri);
    float* pWqkv; cudaGetSymbolAddress((void**)&pWqkv, g_Wqkv);
    float* pbqkv; cudaGetSymbolAddress((void**)&pbqkv, g_bqkv);
    float* pS;    cudaGetSymbolAddress((void**)&pS, g_S);

    k_pe<<<ceil_div(kD * kN, 256), 256>>>();
    k_pack_qkv<<<ceil_div(3 * 128 * 128, 256), 256>>>(Wq, Wk, Wv, bq, bk, bv);

    auto run_block = [&](const float* emb, float* act, float* alt, const float* msk, int L) {
        int lt = ceil_div(L, 64);
        k_add_pe_stats<<<ceil_div(kB * L, 32), 128>>>(emb, act, pmu, pri, L);
        float* bufs[2] = {act, alt};
        for (int i = 0; i < kNC; i++) {
            float* src = bufs[i & 1];
            float* dst = bufs[(i + 1) & 1];
            k_cgemm<<<dim3(lt, 1, kB), 256>>>(
                src, pww + (size_t)i * kD * kD, pwb + (size_t)i * kD,
                dww + (size_t)i * kD * kKW, dwb + (size_t)i * kD,
                ln_g, ln_b, pmu, pri, dst, pmu, pri, L);
        }
        k_gemm<false, false, false, true, false><<<dim3(lt, 3, kB), 256>>>(
            act, pWqkv, pbqkv, nullptr, pqkv, L, 384, pmu, pri, ln_g, ln_b, nullptr, nullptr);
        k_attn<<<dim3(ceil_div(L, 256), kB * kH), 256>>>(pqkv, msk, pao, L);
        k_gemm<true, false, true, false, true><<<dim3(lt, 1, kB), 256>>>(
            pao, Wo, bo, act, act, L, kD, nullptr, nullptr, nullptr, nullptr, pmu, pri);
        k_gemm<false, false, true, true, false><<<dim3(lt, 1, kB), 256>>>(
            act, Wfc, bfc, act, act, L, kD, pmu, pri, ln_g, ln_b, nullptr, nullptr);
    };

    run_block(ctx, pC, pdw, cmask, kN);
    run_block(qst, pQ, pQ2, qmask, kM);

    // --------- context-query attention ---------
    k_dot<<<ceil_div(kB * kN, 256), 256>>>(pC, cq_wc, pcc, kN);
    k_dot<<<ceil_div(kB * kM, 256), 256>>>(pQ, cq_wq, pqq, kM);
    k_trC<<<dim3(13, 4, kB), dim3(32, 8)>>>(pC, pCt, kN);
    k_trQ<<<dim3(2, 4, kB), dim3(32, 8)>>>(pQ, pQt, pQw, cq_wm);
    k_sgemm<<<dim3(13, kB), 256>>>(pC, pQw, pcc, pqq, cq_b, pS);
    k_smrow<<<ceil_div(kB * kN, 256), 256>>>(qmask);
    k_smcol<<<ceil_div(kB * kM * 32, 256), 256>>>(cmask);
    k_U<<<kB, 512>>>(pCt);
    k_out<<<kB * 25, 256>>>(pCt, (float*)d_out);
}

// round 11
// speedup vs baseline: 1.7327x; 1.0319x over previous
#include <cuda_runtime.h>
#include <math.h>

// ---------------------------------------------------------------------------
// QANet forward, fp32 on sm_103a.
// R11: R10 + __launch_bounds__(256,3) on GEMM family -> 24 warps/SM and
//      single-wave scheduling (448 blocks vs 444 concurrent).
// ---------------------------------------------------------------------------
#define kB 64
#define kD 128
#define kN 400
#define kM 50
#define kH 8
#define kKD 16
#define kNC 4
#define kKW 7
#define kPAD 3

typedef unsigned long long u64;

__device__ __forceinline__ u64 pk2(float lo, float hi) {
    u64 r; asm("mov.b64 %0,{%1,%2};" : "=l"(r) : "f"(lo), "f"(hi)); return r;
}
__device__ __forceinline__ void upk2(u64 v, float& lo, float& hi) {
    asm("mov.b64 {%0,%1},%2;" : "=f"(lo), "=f"(hi) : "l"(v));
}
__device__ __forceinline__ u64 fma2(u64 a, u64 b, u64 c) {
    u64 d; asm("fma.rn.f32x2 %0,%1,%2,%3;" : "=l"(d) : "l"(a), "l"(b), "l"(c)); return d;
}
__device__ __forceinline__ u64 mul2(u64 a, u64 b) {
    u64 d; asm("mul.rn.f32x2 %0,%1,%2;" : "=l"(d) : "l"(a), "l"(b)); return d;
}

// ------------------------- device scratch (static) -------------------------
__device__ float g_C[kB * kD * kN];
__device__ float g_Q[kB * kD * kM];
__device__ float g_dw[kB * kD * kN];
__device__ float g_Q2[kB * kD * kM];
__device__ float g_qkv[kB * 3 * kD * kN];
__device__ float g_ao[kB * kD * kN];
__device__ float g_Wqkv[3 * kD * kD];   // [e][d]
__device__ float g_bqkv[3 * kD];
__device__ float g_pe[kD * kN];
__device__ float g_mu[kB * kN];
__device__ float g_ri[kB * kN];
__device__ float g_S[kB * kM * kN];
__device__ float g_Sr[kB * kM * kN];
__device__ float g_Sc[kB * kM * kN];
__device__ float g_U[kB * kM * kD];
__device__ float g_Ct[kB * kN * kD];
__device__ float g_Qt[kB * kM * kD];
__device__ float g_Qw[kB * kM * kD];
__device__ float g_cc[kB * kN];
__device__ float g_qq[kB * kM];

// ------------------------------ PE table ----------------------------------
__global__ void k_pe() {
    int idx = blockIdx.x * blockDim.x + threadIdx.x;
    if (idx >= kD * kN) return;
    int d = idx / kN;
    int l = idx % kN;
    int d0 = d & ~1;
    double f = pow(10000.0, -(double)d0 / (double)kD);
    double a = (double)l * f;
    g_pe[idx] = (d & 1) ? (float)cos(a) : (float)sin(a);
}

// ----------------- add PE + compute LN stats in one pass -------------------
__global__ void __launch_bounds__(128) k_add_pe_stats(const float* __restrict__ x,
                                                      float* __restrict__ y,
                                                      float* __restrict__ omu,
                                                      float* __restrict__ ori, int L) {
    int tid = threadIdx.x;
    int lsub = tid & 31;
    int grp = tid >> 5;
    int pos = blockIdx.x * 32 + lsub;
    int P = kB * L;
    bool ok = pos < P;
    int b = ok ? pos / L : 0;
    int l = ok ? pos % L : 0;

    float s = 0.f, sq = 0.f;
    if (ok) {
        const float* xp = x + ((size_t)b * kD + grp * 32) * L + l;
        float* yp = y + ((size_t)b * kD + grp * 32) * L + l;
#pragma unroll
        for (int k = 0; k < 32; k++) {
            int d = grp * 32 + k;
            float v = xp[(size_t)k * L] + g_pe[d * kN + l];
            yp[(size_t)k * L] = v;
            s += v;
            sq += v * v;
        }
    }
    __shared__ float ss[4][32], sb[4][32];
    ss[grp][lsub] = s;
    sb[grp][lsub] = sq;
    __syncthreads();
    if (grp == 0 && ok) {
        float ts = ss[0][lsub] + ss[1][lsub] + ss[2][lsub] + ss[3][lsub];
        float tq = sb[0][lsub] + sb[1][lsub] + sb[2][lsub] + sb[3][lsub];
        float mu = ts * (1.f / 128.f);
        float var = (tq - 128.f * mu * mu) * (1.f / 127.f);
        var = fmaxf(var, 0.f);
        omu[pos] = mu;
        ori[pos] = 1.f / (sqrtf(var) + 1e-6f);
    }
}

// ---------------- fused LN + depthwise conv + pointwise GEMM ----------------
// 256 threads = 8 warps. Block tile 128e x 64l.
// eq = tid>>5 (warp -> 16 e's, warp-uniform W); lq = tid&31 (lane -> 2 l's).
__global__ void __launch_bounds__(256, 3) k_cgemm(const float* __restrict__ X,
                                                  const float* __restrict__ Wpw,  // [e][d]
                                                  const float* __restrict__ pwb,
                                                  const float* __restrict__ cw,
                                                  const float* __restrict__ cb,
                                                  const float* __restrict__ gamma,
                                                  const float* __restrict__ beta,
                                                  const float* __restrict__ mu,
                                                  const float* __restrict__ ri,
                                                  float* __restrict__ out,
                                                  float* __restrict__ omu,
                                                  float* __restrict__ ori, int L) {
    __shared__ __align__(16) float Xl[32][72];
    __shared__ __align__(16) float Xs[32][68];
    __shared__ __align__(16) float Ws[32][132];
    __shared__ float mus[72], ris[72];
    __shared__ float gs[128], bs2[128];
    __shared__ float cws[128][8];

    int tid = threadIdx.x;
    int eq = tid >> 5;
    int lq = tid & 31;
    int l0 = blockIdx.x * 64;
    int b = blockIdx.z;

    if (tid < 70) {
        int gl = l0 + tid - 3;
        bool in = (gl >= 0 && gl < L);
        mus[tid] = in ? mu[(size_t)b * L + gl] : 0.f;
        ris[tid] = in ? ri[(size_t)b * L + gl] : 0.f;
    }
    if (tid < 128) {
        gs[tid] = gamma[tid];
        bs2[tid] = beta[tid];
#pragma unroll
        for (int k = 0; k < 7; k++) cws[tid][k] = cw[tid * 7 + k];
        cws[tid][7] = cb[tid];
    }
    __syncthreads();

    float acc[32];
#pragma unroll
    for (int j = 0; j < 32; j++) acc[j] = 0.f;

    for (int k = 0; k < 4; k++) {
        int d0 = k * 32;
        // LN'd halo tile (32 x 70)
#pragma unroll
        for (int r = 0; r < 9; r++) {
            int idx = tid + r * 256;
            if (idx < 2240) {
                int dd = idx / 70;
                int ll = idx - dd * 70;
                int gl = l0 + ll - 3;
                float v = 0.f;
                if (gl >= 0 && gl < L) {
                    float xv = X[((size_t)b * 128 + d0 + dd) * L + gl];
                    v = gs[d0 + dd] * (xv - mus[ll]) * ris[ll] + bs2[d0 + dd];
                }
                Xl[dd][ll] = v;
            }
        }
        // pw weights: Ws[dd][e]
#pragma unroll
        for (int r = 0; r < 16; r++) {
            int idx = tid + r * 256;
            int e = idx >> 5;
            int dd = idx & 31;
            Ws[dd][e] = Wpw[(size_t)e * 128 + d0 + dd];
        }
        __syncthreads();
        // depthwise conv -> Xs
#pragma unroll
        for (int r = 0; r < 8; r++) {
            int idx = tid + r * 256;
            int dd = idx >> 6;
            int ll = idx & 63;
            int d = d0 + dd;
            float a = cws[d][7];
#pragma unroll
            for (int kk = 0; kk < 7; kk++) a += cws[d][kk] * Xl[dd][ll + kk];
            Xs[dd][ll] = a;
        }
        __syncthreads();
        // scalar FFMA main loop: 16e x 2l per thread, W warp-uniform
#pragma unroll
        for (int dd = 0; dd < 32; dd++) {
            float2 xv = *(const float2*)&Xs[dd][lq * 2];
            const float4* wp = (const float4*)&Ws[dd][eq * 16];
            float4 w0 = wp[0], w1 = wp[1], w2 = wp[2], w3 = wp[3];
            acc[0]  += w0.x * xv.x;  acc[1]  += w0.x * xv.y;
            acc[2]  += w0.y * xv.x;  acc[3]  += w0.y * xv.y;
            acc[4]  += w0.z * xv.x;  acc[5]  += w0.z * xv.y;
            acc[6]  += w0.w * xv.x;  acc[7]  += w0.w * xv.y;
            acc[8]  += w1.x * xv.x;  acc[9]  += w1.x * xv.y;
            acc[10] += w1.y * xv.x;  acc[11] += w1.y * xv.y;
            acc[12] += w1.z * xv.x;  acc[13] += w1.z * xv.y;
            acc[14] += w1.w * xv.x;  acc[15] += w1.w * xv.y;
            acc[16] += w2.x * xv.x;  acc[17] += w2.x * xv.y;
            acc[18] += w2.y * xv.x;  acc[19] += w2.y * xv.y;
            acc[20] += w2.z * xv.x;  acc[21] += w2.z * xv.y;
            acc[22] += w2.w * xv.x;  acc[23] += w2.w * xv.y;
            acc[24] += w3.x * xv.x;  acc[25] += w3.x * xv.y;
            acc[26] += w3.y * xv.x;  acc[27] += w3.y * xv.y;
            acc[28] += w3.z * xv.x;  acc[29] += w3.z * xv.y;
            acc[30] += w3.w * xv.x;  acc[31] += w3.w * xv.y;
        }
        __syncthreads();
    }

    float sum_l[2] = {0.f, 0.f};
    float sq_l[2] = {0.f, 0.f};
#pragma unroll
    for (int p = 0; p < 16; p++) {
        int e0 = eq * 16 + p;
        float bv = pwb[e0];
#pragma unroll
        for (int q = 0; q < 2; q++) {
            float v = fmaxf(acc[p * 2 + q] + bv, 0.f);
            int lg = l0 + lq * 2 + q;
            if (lg < L) {
                size_t oi = ((size_t)b * 128 + e0) * L + lg;
                v += X[oi];
                out[oi] = v;
            }
            sum_l[q] += v;
            sq_l[q] += v * v;
        }
    }
    // stats reduction overlay on Ws (dead)
    float* red = &Ws[0][0];
    red[eq * 64 + lq * 2 + 0] = sum_l[0];
    red[eq * 64 + lq * 2 + 1] = sum_l[1];
    red[512 + eq * 64 + lq * 2 + 0] = sq_l[0];
    red[512 + eq * 64 + lq * 2 + 1] = sq_l[1];
    __syncthreads();
    if (tid < 64) {
        int lg = l0 + tid;
        if (lg < L) {
            float s = 0.f, ss = 0.f;
#pragma unroll
            for (int g = 0; g < 8; g++) {
                s += red[g * 64 + tid];
                ss += red[512 + g * 64 + tid];
            }
            float muv = s * (1.f / 128.f);
            float var = (ss - 128.f * muv * muv) * (1.f / 127.f);
            var = fmaxf(var, 0.f);
            omu[(size_t)b * L + lg] = muv;
            ori[(size_t)b * L + lg] = 1.f / (sqrtf(var) + 1e-6f);
        }
    }
}

// ------------------------------- GEMM --------------------------------------
template <bool TR, bool RELU, bool RES, bool LNX, bool STATS>
__global__ void __launch_bounds__(256, 3) k_gemm(const float* __restrict__ X,
                                                 const float* __restrict__ W,
                                                 const float* __restrict__ bias,
                                                 const float* res, float* out,
                                                 int L, int Etot,
                                                 const float* __restrict__ mu,
                                                 const float* __restrict__ ri,
                                                 const float* __restrict__ gamma,
                                                 const float* __restrict__ beta,
                                                 float* omu, float* ori) {
    __shared__ __align__(16) float Xs[32][68];
    __shared__ __align__(16) float Ws[32][132];
    __shared__ float mus[64], ris[64];
    __shared__ float gs[128], bs2[128];

    int tid = threadIdx.x;
    int eq = tid >> 5;
    int lq = tid & 31;
    int l0 = blockIdx.x * 64;
    int et = blockIdx.y * 128;
    int b = blockIdx.z;

    if (LNX) {
        if (tid < 64) {
            int p = l0 + tid;
            mus[tid] = (p < L) ? mu[(size_t)b * L + p] : 0.f;
            ris[tid] = (p < L) ? ri[(size_t)b * L + p] : 0.f;
        }
        if (tid < 128) {
            gs[tid] = gamma[tid];
            bs2[tid] = beta[tid];
        }
        __syncthreads();
    }

    float acc[32];
#pragma unroll
    for (int j = 0; j < 32; j++) acc[j] = 0.f;

    for (int k = 0; k < 4; k++) {
        int d0 = k * 32;
#pragma unroll
        for (int r = 0; r < 8; r++) {
            int idx = tid + r * 256;
            int dd = idx >> 6;
            int ll = idx & 63;
            int lg = l0 + ll;
            float v = 0.f;
            if (lg < L) {
                v = X[((size_t)b * 128 + d0 + dd) * L + lg];
                if (LNX) v = gs[d0 + dd] * (v - mus[ll]) * ris[ll] + bs2[d0 + dd];
            }
            Xs[dd][ll] = v;
        }
#pragma unroll
        for (int r = 0; r < 16; r++) {
            int idx = tid + r * 256;
            if (TR) {
                int dd = idx >> 7;
                int e = idx & 127;
                Ws[dd][e] = W[(size_t)(d0 + dd) * Etot + et + e];
            } else {
                int e = idx >> 5;
                int dd = idx & 31;
                Ws[dd][e] = W[(size_t)(et + e) * 128 + d0 + dd];
            }
        }
        __syncthreads();
#pragma unroll
        for (int dd = 0; dd < 32; dd++) {
            float2 xv = *(const float2*)&Xs[dd][lq * 2];
            const float4* wp = (const float4*)&Ws[dd][eq * 16];
            float4 w0 = wp[0], w1 = wp[1], w2 = wp[2], w3 = wp[3];
            acc[0]  += w0.x * xv.x;  acc[1]  += w0.x * xv.y;
            acc[2]  += w0.y * xv.x;  acc[3]  += w0.y * xv.y;
            acc[4]  += w0.z * xv.x;  acc[5]  += w0.z * xv.y;
            acc[6]  += w0.w * xv.x;  acc[7]  += w0.w * xv.y;
            acc[8]  += w1.x * xv.x;  acc[9]  += w1.x * xv.y;
            acc[10] += w1.y * xv.x;  acc[11] += w1.y * xv.y;
            acc[12] += w1.z * xv.x;  acc[13] += w1.z * xv.y;
            acc[14] += w1.w * xv.x;  acc[15] += w1.w * xv.y;
            acc[16] += w2.x * xv.x;  acc[17] += w2.x * xv.y;
            acc[18] += w2.y * xv.x;  acc[19] += w2.y * xv.y;
            acc[20] += w2.z * xv.x;  acc[21] += w2.z * xv.y;
            acc[22] += w2.w * xv.x;  acc[23] += w2.w * xv.y;
            acc[24] += w3.x * xv.x;  acc[25] += w3.x * xv.y;
            acc[26] += w3.y * xv.x;  acc[27] += w3.y * xv.y;
            acc[28] += w3.z * xv.x;  acc[29] += w3.z * xv.y;
            acc[30] += w3.w * xv.x;  acc[31] += w3.w * xv.y;
        }
        __syncthreads();
    }

    float sum_l[2] = {0.f, 0.f};
    float sq_l[2] = {0.f, 0.f};
#pragma unroll
    for (int p = 0; p < 16; p++) {
        int e0 = et + eq * 16 + p;
        float bv = bias[e0];
#pragma unroll
        for (int q = 0; q < 2; q++) {
            float v = acc[p * 2 + q] + bv;
            if (RELU) v = fmaxf(v, 0.f);
            int lg = l0 + lq * 2 + q;
            if (lg < L) {
                size_t oi = ((size_t)b * Etot + e0) * L + lg;
                if (RES) v += res[oi];
                out[oi] = v;
            }
            if (STATS) {
                sum_l[q] += v;
                sq_l[q] += v * v;
            }
        }
    }
    if (STATS) {
        float* red = &Ws[0][0];
        red[eq * 64 + lq * 2 + 0] = sum_l[0];
        red[eq * 64 + lq * 2 + 1] = sum_l[1];
        red[512 + eq * 64 + lq * 2 + 0] = sq_l[0];
        red[512 + eq * 64 + lq * 2 + 1] = sq_l[1];
        __syncthreads();
        if (tid < 64) {
            int lg = l0 + tid;
            if (lg < L) {
                float s = 0.f, ss = 0.f;
#pragma unroll
                for (int g = 0; g < 8; g++) {
                    s += red[g * 64 + tid];
                    ss += red[512 + g * 64 + tid];
                }
                float muv = s * (1.f / 128.f);
                float var = (ss - 128.f * muv * muv) * (1.f / 127.f);
                var = fmaxf(var, 0.f);
                omu[(size_t)b * L + lg] = muv;
                ori[(size_t)b * L + lg] = 1.f / (sqrtf(var) + 1e-6f);
            }
        }
    }
}

// ----------------------------- QKV packing ---------------------------------
__global__ void k_pack_qkv(const float* __restrict__ Wq, const float* __restrict__ Wk,
                           const float* __restrict__ Wv, const float* __restrict__ bq,
                           const float* __restrict__ bk, const float* __restrict__ bv) {
    int idx = blockIdx.x * blockDim.x + threadIdx.x;
    if (idx < 3 * 128 * 128) {
        int e = idx >> 7;
        int d = idx & 127;
        int qv = e >> 7;
        int hk = e & 127;
        int h = hk >> 4;
        int kk = hk & 15;
        const float* src = (qv == 0) ? Wq : (qv == 1 ? Wk : Wv);
        g_Wqkv[idx] = src[((size_t)h * 128 + d) * 16 + kk];
    }
    if (idx < 384) {
        int qv = idx >> 7;
        int hk = idx & 127;
        const float* srcb = (qv == 0) ? bq : (qv == 1 ? bk : bv);
        g_bqkv[idx] = srcb[hk];
    }
}

// ----------------------------- attention core ------------------------------
__global__ void __launch_bounds__(256) k_attn(const float* __restrict__ qkv,
                                              const float* __restrict__ mask,
                                              float* __restrict__ o, int L) {
    const int KT = 64;
    __shared__ u64 ks[KT][9], vs[KT][9];
    __shared__ float ms[KT];
    int tid = threadIdx.x;
    int bh = blockIdx.y;
    int b = bh >> 3;
    int h = bh & 7;
    int i = blockIdx.x * 256 + tid;
    bool act = i < L;

    u64 q2[8];
    if (act) {
        const float* qp = qkv + ((size_t)b * 384 + h * 16) * L + i;
#pragma unroll
        for (int c = 0; c < 8; c++)
            q2[c] = pk2(qp[(size_t)(2 * c) * L] * 0.25f, qp[(size_t)(2 * c + 1) * L] * 0.25f);
    }
    float m = -INFINITY, lsum = 0.f;
    u64 acc[8] = {0, 0, 0, 0, 0, 0, 0, 0};

    for (int j0 = 0; j0 < L; j0 += KT) {
        int cnt = min(KT, L - j0);
        for (int idx = tid; idx < 8 * KT; idx += 256) {
            int c = idx >> 6;
            int t = idx & 63;
            if (t < cnt) {
                const float* kp = qkv + ((size_t)b * 384 + 128 + h * 16 + 2 * c) * L + j0 + t;
                ks[t][c] = pk2(kp[0], kp[(size_t)L]);
                const float* vp = kp + (size_t)128 * L;
                vs[t][c] = pk2(vp[0], vp[(size_t)L]);
            } else {
                ks[t][c] = 0;
                vs[t][c] = 0;
            }
        }
        if (tid < KT) ms[tid] = (tid < cnt) ? mask[(size_t)b * L + j0 + tid] : 0.f;
        __syncthreads();
        if (act) {
            for (int g = 0; g < cnt; g += 8) {
                float sreg[8];
#pragma unroll
                for (int t2 = 0; t2 < 8; t2++) {
                    int t = g + t2;
                    u64 s2 = 0;
#pragma unroll
                    for (int c = 0; c < 8; c++) s2 = fma2(q2[c], ks[t][c], s2);
                    float slo, shi;
                    upk2(s2, slo, shi);
                    sreg[t2] = slo + shi - 1e30f * (1.f - ms[t]);
                }
                float gm = sreg[0];
#pragma unroll
                for (int t2 = 1; t2 < 8; t2++) gm = fmaxf(gm, sreg[t2]);
                float nm = fmaxf(m, gm);
                float sc = __expf(m - nm);
                lsum *= sc;
                u64 scp = pk2(sc, sc);
#pragma unroll
                for (int c = 0; c < 8; c++) acc[c] = mul2(scp, acc[c]);
#pragma unroll
                for (int t2 = 0; t2 < 8; t2++) {
                    int t = g + t2;
                    float p = __expf(sreg[t2] - nm);
                    lsum += p;
                    u64 pp = pk2(p, p);
#pragma unroll
                    for (int c = 0; c < 8; c++) acc[c] = fma2(pp, vs[t][c], acc[c]);
                }
                m = nm;
            }
        }
        __syncthreads();
    }
    if (act) {
        float r = 1.f / lsum;
        float* op = o + ((size_t)b * 128 + h * 16) * L + i;
#pragma unroll
        for (int c = 0; c < 8; c++) {
            float lo, hi;
            upk2(acc[c], lo, hi);
            op[(size_t)(2 * c) * L] = lo * r;
            op[(size_t)(2 * c + 1) * L] = hi * r;
        }
    }
}

// ------------------------------ transposes ---------------------------------
__global__ void k_trC(const float* __restrict__ X, float* __restrict__ Y, int L) {
    __shared__ float t[32][33];
    int b = blockIdx.z, d0 = blockIdx.y * 32, l0 = blockIdx.x * 32;
    int tx = threadIdx.x, ty = threadIdx.y;
#pragma unroll
    for (int k = 0; k < 4; k++) {
        int l = l0 + tx;
        t[ty + 8 * k][tx] = (l < L) ? X[((size_t)b * 128 + d0 + ty + 8 * k) * L + l] : 0.f;
    }
    __syncthreads();
#pragma unroll
    for (int k = 0; k < 4; k++) {
        int l = l0 + ty + 8 * k;
        if (l < L) Y[((size_t)b * L + l) * 128 + d0 + tx] = t[tx][ty + 8 * k];
    }
}

__global__ void k_trQ(const float* __restrict__ X, float* __restrict__ Yt,
                      float* __restrict__ Yw, const float* __restrict__ wm) {
    __shared__ float t[32][33];
    int b = blockIdx.z, d0 = blockIdx.y * 32, l0 = blockIdx.x * 32;
    int tx = threadIdx.x, ty = threadIdx.y;
#pragma unroll
    for (int k = 0; k < 4; k++) {
        int l = l0 + tx;
        t[ty + 8 * k][tx] = (l < kM) ? X[((size_t)b * 128 + d0 + ty + 8 * k) * kM + l] : 0.f;
    }
    __syncthreads();
    float w = wm[d0 + tx];
#pragma unroll
    for (int k = 0; k < 4; k++) {
        int l = l0 + ty + 8 * k;
        if (l < kM) {
            float v = t[tx][ty + 8 * k];
            size_t oi = ((size_t)b * kM + l) * 128 + d0 + tx;
            Yt[oi] = v;
            Yw[oi] = v * w;
        }
    }
}

// ------------------------------ CQ attention -------------------------------
__global__ void k_dot(const float* __restrict__ X, const float* __restrict__ w,
                      float* __restrict__ out, int L) {
    int idx = blockIdx.x * blockDim.x + threadIdx.x;
    if (idx >= kB * L) return;
    int b = idx / L;
    int pos = idx % L;
    const float* xp = X + (size_t)b * kD * L + pos;
    float a = 0.f;
#pragma unroll 8
    for (int d = 0; d < kD; d++) a += w[d] * xp[(size_t)d * L];
    out[idx] = a;
}

__global__ void __launch_bounds__(256) k_sgemm(const float* __restrict__ X,
                                               const float* __restrict__ Qw,
                                               const float* __restrict__ cc,
                                               const float* __restrict__ qq,
                                               const float* __restrict__ b0,
                                               float* __restrict__ S) {
    __shared__ float Xs[32][33];
    __shared__ float Ws[32][68];
    int tid = threadIdx.x;
    int l = tid & 31;
    int eg = tid >> 5;
    int l0 = blockIdx.x * 32;
    int b = blockIdx.y;
    u64 acc[4] = {0, 0, 0, 0};

    for (int d0 = 0; d0 < 128; d0 += 32) {
#pragma unroll
        for (int r = 0; r < 4; r++) {
            int idx = tid + r * 256;
            int dd = idx >> 5, ll = idx & 31;
            int lg = l0 + ll;
            Xs[dd][ll] = (lg < kN) ? X[((size_t)b * 128 + d0 + dd) * kN + lg] : 0.f;
        }
#pragma unroll
        for (int r = 0; r < 8; r++) {
            int idx = tid + r * 256;
            int dd = idx >> 6;
            int e = idx & 63;
            Ws[dd][e] = (e < kM) ? Qw[((size_t)b * kM + e) * 128 + d0 + dd] : 0.f;
        }
        __syncthreads();
#pragma unroll
        for (int dd = 0; dd < 32; dd++) {
            float xv = Xs[dd][l];
            u64 xx = pk2(xv, xv);
            const ulonglong2* wr = (const ulonglong2*)&Ws[dd][eg * 8];
            ulonglong2 w0 = wr[0], w1 = wr[1];
            acc[0] = fma2(xx, w0.x, acc[0]);
            acc[1] = fma2(xx, w0.y, acc[1]);
            acc[2] = fma2(xx, w1.x, acc[2]);
            acc[3] = fma2(xx, w1.y, acc[3]);
        }
        __syncthreads();
    }
    int lg = l0 + l;
    if (lg < kN) {
        float base = cc[b * kN + lg] + b0[0];
#pragma unroll
        for (int j = 0; j < 4; j++) {
            float v0, v1;
            upk2(acc[j], v0, v1);
            int e0 = eg * 8 + 2 * j;
            if (e0 < kM) S[((size_t)b * kM + e0) * kN + lg] = v0 + base + qq[b * kM + e0];
            if (e0 + 1 < kM) S[((size_t)b * kM + e0 + 1) * kN + lg] = v1 + base + qq[b * kM + e0 + 1];
        }
    }
}

__global__ void k_smrow(const float* __restrict__ qmask) {
    int idx = blockIdx.x * blockDim.x + threadIdx.x;
    if (idx >= kB * kN) return;
    int b = idx / kN;
    int n = idx % kN;
    float v[kM];
    float mx = -INFINITY;
#pragma unroll
    for (int m = 0; m < kM; m++) {
        v[m] = g_S[((size_t)b * kM + m) * kN + n] - 1e30f * (1.f - qmask[b * kM + m]);
        mx = fmaxf(mx, v[m]);
    }
    float s = 0.f;
#pragma unroll
    for (int m = 0; m < kM; m++) {
        v[m] = __expf(v[m] - mx);
        s += v[m];
    }
    float r = 1.f / s;
#pragma unroll
    for (int m = 0; m < kM; m++) g_Sr[((size_t)b * kM + m) * kN + n] = v[m] * r;
}

__global__ void k_smcol(const float* __restrict__ cmask) {
    int w = (blockIdx.x * blockDim.x + threadIdx.x) >> 5;
    int lane = threadIdx.x & 31;
    if (w >= kB * kM) return;
    int b = w / kM;
    const float* row = g_S + (size_t)w * kN;
    const float* mrow = cmask + (size_t)b * kN;
    float v[13];
#pragma unroll
    for (int k = 0; k < 13; k++) {
        int n = lane + k * 32;
        v[k] = (n < kN) ? row[n] - 1e30f * (1.f - mrow[n]) : -INFINITY;
    }
    float mx = v[0];
#pragma unroll
    for (int k = 1; k < 13; k++) mx = fmaxf(mx, v[k]);
#pragma unroll
    for (int o = 16; o; o >>= 1) mx = fmaxf(mx, __shfl_xor_sync(0xffffffff, mx, o));
    float s = 0.f;
    float e[13];
#pragma unroll
    for (int k = 0; k < 13; k++) {
        int n = lane + k * 32;
        e[k] = (n < kN) ? __expf(v[k] - mx) : 0.f;
        s += e[k];
    }
#pragma unroll
    for (int o = 16; o; o >>= 1) s += __shfl_xor_sync(0xffffffff, s, o);
    float r = 1.f / s;
    float* orow = g_Sc + (size_t)w * kN;
#pragma unroll
    for (int k = 0; k < 13; k++) {
        int n = lane + k * 32;
        if (n < kN) orow[n] = e[k] * r;
    }
}

__global__ void __launch_bounds__(512) k_U(const float* __restrict__ Ct) {
    int b = blockIdx.x;
    int tid = threadIdx.x;
    int d = tid & 127;
    int mq = tid >> 7;
    __shared__ float cts[16][128];
    __shared__ float scs[16][56];
    u64 acc[7] = {0, 0, 0, 0, 0, 0, 0};

    for (int n0 = 0; n0 < kN; n0 += 16) {
#pragma unroll
        for (int r = 0; r < 4; r++) {
            int idx = tid + r * 512;
            int n = idx >> 7, dd = idx & 127;
            cts[n][dd] = Ct[((size_t)b * kN + n0 + n) * 128 + dd];
        }
        for (int idx = tid; idx < 16 * 56; idx += 512) {
            int n = idx & 15;
            int m = idx >> 4;
            scs[n][m] = (m < kM) ? g_Sc[((size_t)b * kM + m) * kN + n0 + n] : 0.f;
        }
        __syncthreads();
#pragma unroll
        for (int n = 0; n < 16; n++) {
            float ct = cts[n][d];
            u64 c2 = pk2(ct, ct);
            const u64* sp = (const u64*)&scs[n][mq * 14];
#pragma unroll
            for (int j = 0; j < 7; j++) acc[j] = fma2(c2, sp[j], acc[j]);
        }
        __syncthreads();
    }
#pragma unroll
    for (int j = 0; j < 7; j++) {
        float v0, v1;
        upk2(acc[j], v0, v1);
        int m = mq * 14 + 2 * j;
        if (m < kM) g_U[((size_t)b * kM + m) * 128 + d] = v0;
        if (m + 1 < kM) g_U[((size_t)b * kM + m + 1) * 128 + d] = v1;
    }
}

__global__ void __launch_bounds__(256) k_out(const float* __restrict__ Ct,
                                             float* __restrict__ out) {
    int b = blockIdx.x / 25;
    int n0 = (blockIdx.x % 25) * 16;
    int tid = threadIdx.x;
    int d = tid & 127;
    int nq = tid >> 7;
    __shared__ float srs[kM][16];
    for (int idx = tid; idx < kM * 16; idx += 256) {
        int m = idx >> 4, nj = idx & 15;
        srs[m][nj] = g_Sr[((size_t)b * kM + m) * kN + n0 + nj];
    }
    __syncthreads();
    u64 a2[4] = {0, 0, 0, 0};
    u64 b2[4] = {0, 0, 0, 0};
    for (int m = 0; m < kM; m++) {
        float qv = g_Qt[((size_t)b * kM + m) * 128 + d];
        float uv = g_U[((size_t)b * kM + m) * 128 + d];
        u64 q2 = pk2(qv, qv), u2 = pk2(uv, uv);
        const u64* sp = (const u64*)&srs[m][nq * 8];
#pragma unroll
        for (int j = 0; j < 4; j++) {
            a2[j] = fma2(sp[j], q2, a2[j]);
            b2[j] = fma2(sp[j], u2, b2[j]);
        }
    }
#pragma unroll
    for (int j = 0; j < 4; j++) {
        float a0, a1, bt0, bt1;
        upk2(a2[j], a0, a1);
        upk2(b2[j], bt0, bt1);
#pragma unroll
        for (int t = 0; t < 2; t++) {
            int n = n0 + nq * 8 + 2 * j + t;
            float a = (t == 0) ? a0 : a1;
            float bt = (t == 0) ? bt0 : bt1;
            float c = Ct[((size_t)b * kN + n) * 128 + d];
            size_t base = ((size_t)b * kN + n) * 512;
            out[base + d] = c;
            out[base + 128 + d] = a;
            out[base + 256 + d] = c * a;
            out[base + 384 + d] = c * bt;
        }
    }
}

// ------------------------------- host side ---------------------------------
static inline int ceil_div(int a, int b) { return (a + b - 1) / b; }

extern "C" void kernel_launch(void* const* d_in, const int* in_sizes, int n_in,
                              void* d_out, int out_size) {
    (void)in_sizes; (void)n_in; (void)out_size;
    const float* ctx   = (const float*)d_in[0];
    const float* qst   = (const float*)d_in[1];
    const float* cmask = (const float*)d_in[2];
    const float* qmask = (const float*)d_in[3];
    const float* ln_g  = (const float*)d_in[4];
    const float* ln_b  = (const float*)d_in[5];
    const float* dww   = (const float*)d_in[6];
    const float* dwb   = (const float*)d_in[7];
    const float* pww   = (const float*)d_in[8];
    const float* pwb   = (const float*)d_in[9];
    const float* Wq    = (const float*)d_in[10];
    const float* bq    = (const float*)d_in[11];
    const float* Wk    = (const float*)d_in[12];
    const float* bk    = (const float*)d_in[13];
    const float* Wv    = (const float*)d_in[14];
    const float* bv    = (const float*)d_in[15];
    const float* Wo    = (const float*)d_in[16];
    const float* bo    = (const float*)d_in[17];
    const float* Wfc   = (const float*)d_in[18];
    const float* bfc   = (const float*)d_in[19];
    const float* cq_wc = (const float*)d_in[20];
    const float* cq_wq = (const float*)d_in[21];
    const float* cq_wm = (const float*)d_in[22];
    const float* cq_b  = (const float*)d_in[23];

    float *pC, *pQ, *pdw, *pQ2, *pqkv, *pao, *pcc, *pqq, *pCt, *pQt, *pQw, *pmu, *pri;
    cudaGetSymbolAddress((void**)&pC, g_C);
    cudaGetSymbolAddress((void**)&pQ, g_Q);
    cudaGetSymbolAddress((void**)&pdw, g_dw);
    cudaGetSymbolAddress((void**)&pQ2, g_Q2);
    cudaGetSymbolAddress((void**)&pqkv, g_qkv);
    cudaGetSymbolAddress((void**)&pao, g_ao);
    cudaGetSymbolAddress((void**)&pcc, g_cc);
    cudaGetSymbolAddress((void**)&pqq, g_qq);
    cudaGetSymbolAddress((void**)&pCt, g_Ct);
    cudaGetSymbolAddress((void**)&pQt, g_Qt);
    cudaGetSymbolAddress((void**)&pQw, g_Qw);
    cudaGetSymbolAddress((void**)&pmu, g_mu);
    cudaGetSymbolAddress((void**)&pri, g_ri);
    float* pWqkv; cudaGetSymbolAddress((void**)&pWqkv, g_Wqkv);
    float* pbqkv; cudaGetSymbolAddress((void**)&pbqkv, g_bqkv);
    float* pS;    cudaGetSymbolAddress((void**)&pS, g_S);

    k_pe<<<ceil_div(kD * kN, 256), 256>>>();
    k_pack_qkv<<<ceil_div(3 * 128 * 128, 256), 256>>>(Wq, Wk, Wv, bq, bk, bv);

    auto run_block = [&](const float* emb, float* act, float* alt, const float* msk, int L) {
        int lt = ceil_div(L, 64);
        k_add_pe_stats<<<ceil_div(kB * L, 32), 128>>>(emb, act, pmu, pri, L);
        float* bufs[2] = {act, alt};
        for (int i = 0; i < kNC; i++) {
            float* src = bufs[i & 1];
            float* dst = bufs[(i + 1) & 1];
            k_cgemm<<<dim3(lt, 1, kB), 256>>>(
                src, pww + (size_t)i * kD * kD, pwb + (size_t)i * kD,
                dww + (size_t)i * kD * kKW, dwb + (size_t)i * kD,
                ln_g, ln_b, pmu, pri, dst, pmu, pri, L);
        }
        k_gemm<false, false, false, true, false><<<dim3(lt, 3, kB), 256>>>(
            act, pWqkv, pbqkv, nullptr, pqkv, L, 384, pmu, pri, ln_g, ln_b, nullptr, nullptr);
        k_attn<<<dim3(ceil_div(L, 256), kB * kH), 256>>>(pqkv, msk, pao, L);
        k_gemm<true, false, true, false, true><<<dim3(lt, 1, kB), 256>>>(
            pao, Wo, bo, act, act, L, kD, nullptr, nullptr, nullptr, nullptr, pmu, pri);
        k_gemm<false, false, true, true, false><<<dim3(lt, 1, kB), 256>>>(
            act, Wfc, bfc, act, act, L, kD, pmu, pri, ln_g, ln_b, nullptr, nullptr);
    };

    run_block(ctx, pC, pdw, cmask, kN);
    run_block(qst, pQ, pQ2, qmask, kM);

    // --------- context-query attention ---------
    k_dot<<<ceil_div(kB * kN, 256), 256>>>(pC, cq_wc, pcc, kN);
    k_dot<<<ceil_div(kB * kM, 256), 256>>>(pQ, cq_wq, pqq, kM);
    k_trC<<<dim3(13, 4, kB), dim3(32, 8)>>>(pC, pCt, kN);
    k_trQ<<<dim3(2, 4, kB), dim3(32, 8)>>>(pQ, pQt, pQw, cq_wm);
    k_sgemm<<<dim3(13, kB), 256>>>(pC, pQw, pcc, pqq, cq_b, pS);
    k_smrow<<<ceil_div(kB * kN, 256), 256>>>(qmask);
    k_smcol<<<ceil_div(kB * kM * 32, 256), 256>>>(cmask);
    k_U<<<kB, 512>>>(pCt);
    k_out<<<kB * 25, 256>>>(pCt, (float*)d_out);
}

// round 12
// speedup vs baseline: 1.7794x; 1.0269x over previous
#include <cuda_runtime.h>
#include <math.h>

// ---------------------------------------------------------------------------
// QANet forward, fp32 on sm_103a.
// R12: R11 + dual-sequence fusion: each encoder kernel processes context
//      (z<64, L=400) and question (z>=64, L=50) in ONE launch.
// ---------------------------------------------------------------------------
#define kB 64
#define kD 128
#define kN 400
#define kM 50
#define kH 8
#define kKD 16
#define kNC 4
#define kKW 7
#define kPAD 3

typedef unsigned long long u64;

__device__ __forceinline__ u64 pk2(float lo, float hi) {
    u64 r; asm("mov.b64 %0,{%1,%2};" : "=l"(r) : "f"(lo), "f"(hi)); return r;
}
__device__ __forceinline__ void upk2(u64 v, float& lo, float& hi) {
    asm("mov.b64 {%0,%1},%2;" : "=f"(lo), "=f"(hi) : "l"(v));
}
__device__ __forceinline__ u64 fma2(u64 a, u64 b, u64 c) {
    u64 d; asm("fma.rn.f32x2 %0,%1,%2,%3;" : "=l"(d) : "l"(a), "l"(b), "l"(c)); return d;
}
__device__ __forceinline__ u64 mul2(u64 a, u64 b) {
    u64 d; asm("mul.rn.f32x2 %0,%1,%2;" : "=l"(d) : "l"(a), "l"(b)); return d;
}

// ------------------------- device scratch (static) -------------------------
__device__ float g_C[kB * kD * kN];
__device__ float g_Q[kB * kD * kM];
__device__ float g_dw[kB * kD * kN];
__device__ float g_Q2[kB * kD * kM];
__device__ float g_qkv[kB * 3 * kD * kN];
__device__ float g_qkv_q[kB * 3 * kD * kM];
__device__ float g_ao[kB * kD * kN];
__device__ float g_ao_q[kB * kD * kM];
__device__ float g_Wqkv[3 * kD * kD];   // [e][d]
__device__ float g_bqkv[3 * kD];
__device__ float g_pe[kD * kN];
__device__ float g_mu[kB * kN];
__device__ float g_ri[kB * kN];
__device__ float g_mu2[kB * kM];
__device__ float g_ri2[kB * kM];
__device__ float g_S[kB * kM * kN];
__device__ float g_Sr[kB * kM * kN];
__device__ float g_Sc[kB * kM * kN];
__device__ float g_U[kB * kM * kD];
__device__ float g_Ct[kB * kN * kD];
__device__ float g_Qt[kB * kM * kD];
__device__ float g_Qw[kB * kM * kD];
__device__ float g_cc[kB * kN];
__device__ float g_qq[kB * kM];

// ------------------------------ PE table ----------------------------------
__global__ void k_pe() {
    int idx = blockIdx.x * blockDim.x + threadIdx.x;
    if (idx >= kD * kN) return;
    int d = idx / kN;
    int l = idx % kN;
    int d0 = d & ~1;
    double f = pow(10000.0, -(double)d0 / (double)kD);
    double a = (double)l * f;
    g_pe[idx] = (d & 1) ? (float)cos(a) : (float)sin(a);
}

// ----------------- add PE + compute LN stats in one pass -------------------
__global__ void __launch_bounds__(128) k_add_pe_stats(const float* __restrict__ x,
                                                      float* __restrict__ y,
                                                      float* __restrict__ omu,
                                                      float* __restrict__ ori, int L) {
    int tid = threadIdx.x;
    int lsub = tid & 31;
    int grp = tid >> 5;
    int pos = blockIdx.x * 32 + lsub;
    int P = kB * L;
    bool ok = pos < P;
    int b = ok ? pos / L : 0;
    int l = ok ? pos % L : 0;

    float s = 0.f, sq = 0.f;
    if (ok) {
        const float* xp = x + ((size_t)b * kD + grp * 32) * L + l;
        float* yp = y + ((size_t)b * kD + grp * 32) * L + l;
#pragma unroll
        for (int k = 0; k < 32; k++) {
            int d = grp * 32 + k;
            float v = xp[(size_t)k * L] + g_pe[d * kN + l];
            yp[(size_t)k * L] = v;
            s += v;
            sq += v * v;
        }
    }
    __shared__ float ss[4][32], sb[4][32];
    ss[grp][lsub] = s;
    sb[grp][lsub] = sq;
    __syncthreads();
    if (grp == 0 && ok) {
        float ts = ss[0][lsub] + ss[1][lsub] + ss[2][lsub] + ss[3][lsub];
        float tq = sb[0][lsub] + sb[1][lsub] + sb[2][lsub] + sb[3][lsub];
        float mu = ts * (1.f / 128.f);
        float var = (tq - 128.f * mu * mu) * (1.f / 127.f);
        var = fmaxf(var, 0.f);
        omu[pos] = mu;
        ori[pos] = 1.f / (sqrtf(var) + 1e-6f);
    }
}

// ---------------- fused LN + depthwise conv + pointwise GEMM (dual) ---------
__global__ void __launch_bounds__(256, 3) k_cgemm(const float* __restrict__ Xc,
                                                  const float* __restrict__ Xq,
                                                  float* __restrict__ outc,
                                                  float* __restrict__ outq,
                                                  const float* __restrict__ Wpw,  // [e][d]
                                                  const float* __restrict__ pwb,
                                                  const float* __restrict__ cw,
                                                  const float* __restrict__ cb,
                                                  const float* __restrict__ gamma,
                                                  const float* __restrict__ beta,
                                                  float* __restrict__ muc,
                                                  float* __restrict__ ric,
                                                  float* __restrict__ muq,
                                                  float* __restrict__ riq) {
    int z = blockIdx.z;
    bool isq = z >= kB;
    int b = isq ? z - kB : z;
    int L = isq ? kM : kN;
    int l0 = blockIdx.x * 64;
    if (l0 >= L) return;
    const float* X = isq ? Xq : Xc;
    float* out = isq ? outq : outc;
    float* muP = isq ? muq : muc;
    float* riP = isq ? riq : ric;

    __shared__ __align__(16) float Xl[32][72];
    __shared__ __align__(16) float Xs[32][68];
    __shared__ __align__(16) float Ws[32][132];
    __shared__ float mus[72], ris[72];
    __shared__ float gs[128], bs2[128];
    __shared__ float cws[128][8];

    int tid = threadIdx.x;
    int eq = tid >> 5;
    int lq = tid & 31;

    if (tid < 70) {
        int gl = l0 + tid - 3;
        bool in = (gl >= 0 && gl < L);
        mus[tid] = in ? muP[(size_t)b * L + gl] : 0.f;
        ris[tid] = in ? riP[(size_t)b * L + gl] : 0.f;
    }
    if (tid < 128) {
        gs[tid] = gamma[tid];
        bs2[tid] = beta[tid];
#pragma unroll
        for (int k = 0; k < 7; k++) cws[tid][k] = cw[tid * 7 + k];
        cws[tid][7] = cb[tid];
    }
    __syncthreads();

    float acc[32];
#pragma unroll
    for (int j = 0; j < 32; j++) acc[j] = 0.f;

    for (int k = 0; k < 4; k++) {
        int d0 = k * 32;
#pragma unroll
        for (int r = 0; r < 9; r++) {
            int idx = tid + r * 256;
            if (idx < 2240) {
                int dd = idx / 70;
                int ll = idx - dd * 70;
                int gl = l0 + ll - 3;
                float v = 0.f;
                if (gl >= 0 && gl < L) {
                    float xv = X[((size_t)b * 128 + d0 + dd) * L + gl];
                    v = gs[d0 + dd] * (xv - mus[ll]) * ris[ll] + bs2[d0 + dd];
                }
                Xl[dd][ll] = v;
            }
        }
#pragma unroll
        for (int r = 0; r < 16; r++) {
            int idx = tid + r * 256;
            int e = idx >> 5;
            int dd = idx & 31;
            Ws[dd][e] = Wpw[(size_t)e * 128 + d0 + dd];
        }
        __syncthreads();
#pragma unroll
        for (int r = 0; r < 8; r++) {
            int idx = tid + r * 256;
            int dd = idx >> 6;
            int ll = idx & 63;
            int d = d0 + dd;
            float a = cws[d][7];
#pragma unroll
            for (int kk = 0; kk < 7; kk++) a += cws[d][kk] * Xl[dd][ll + kk];
            Xs[dd][ll] = a;
        }
        __syncthreads();
#pragma unroll
        for (int dd = 0; dd < 32; dd++) {
            float2 xv = *(const float2*)&Xs[dd][lq * 2];
            const float4* wp = (const float4*)&Ws[dd][eq * 16];
            float4 w0 = wp[0], w1 = wp[1], w2 = wp[2], w3 = wp[3];
            acc[0]  += w0.x * xv.x;  acc[1]  += w0.x * xv.y;
            acc[2]  += w0.y * xv.x;  acc[3]  += w0.y * xv.y;
            acc[4]  += w0.z * xv.x;  acc[5]  += w0.z * xv.y;
            acc[6]  += w0.w * xv.x;  acc[7]  += w0.w * xv.y;
            acc[8]  += w1.x * xv.x;  acc[9]  += w1.x * xv.y;
            acc[10] += w1.y * xv.x;  acc[11] += w1.y * xv.y;
            acc[12] += w1.z * xv.x;  acc[13] += w1.z * xv.y;
            acc[14] += w1.w * xv.x;  acc[15] += w1.w * xv.y;
            acc[16] += w2.x * xv.x;  acc[17] += w2.x * xv.y;
            acc[18] += w2.y * xv.x;  acc[19] += w2.y * xv.y;
            acc[20] += w2.z * xv.x;  acc[21] += w2.z * xv.y;
            acc[22] += w2.w * xv.x;  acc[23] += w2.w * xv.y;
            acc[24] += w3.x * xv.x;  acc[25] += w3.x * xv.y;
            acc[26] += w3.y * xv.x;  acc[27] += w3.y * xv.y;
            acc[28] += w3.z * xv.x;  acc[29] += w3.z * xv.y;
            acc[30] += w3.w * xv.x;  acc[31] += w3.w * xv.y;
        }
        __syncthreads();
    }

    float sum_l[2] = {0.f, 0.f};
    float sq_l[2] = {0.f, 0.f};
#pragma unroll
    for (int p = 0; p < 16; p++) {
        int e0 = eq * 16 + p;
        float bv = pwb[e0];
#pragma unroll
        for (int q = 0; q < 2; q++) {
            float v = fmaxf(acc[p * 2 + q] + bv, 0.f);
            int lg = l0 + lq * 2 + q;
            if (lg < L) {
                size_t oi = ((size_t)b * 128 + e0) * L + lg;
                v += X[oi];
                out[oi] = v;
            }
            sum_l[q] += v;
            sq_l[q] += v * v;
        }
    }
    float* red = &Ws[0][0];
    red[eq * 64 + lq * 2 + 0] = sum_l[0];
    red[eq * 64 + lq * 2 + 1] = sum_l[1];
    red[512 + eq * 64 + lq * 2 + 0] = sq_l[0];
    red[512 + eq * 64 + lq * 2 + 1] = sq_l[1];
    __syncthreads();
    if (tid < 64) {
        int lg = l0 + tid;
        if (lg < L) {
            float s = 0.f, ss = 0.f;
#pragma unroll
            for (int g = 0; g < 8; g++) {
                s += red[g * 64 + tid];
                ss += red[512 + g * 64 + tid];
            }
            float muv = s * (1.f / 128.f);
            float var = (ss - 128.f * muv * muv) * (1.f / 127.f);
            var = fmaxf(var, 0.f);
            muP[(size_t)b * L + lg] = muv;
            riP[(size_t)b * L + lg] = 1.f / (sqrtf(var) + 1e-6f);
        }
    }
}

// ------------------------------- GEMM (dual) --------------------------------
template <bool TR, bool RELU, bool RES, bool LNX, bool STATS>
__global__ void __launch_bounds__(256, 3) k_gemm(const float* __restrict__ Xc,
                                                 const float* __restrict__ Xq,
                                                 const float* __restrict__ W,
                                                 const float* __restrict__ bias,
                                                 const float* resc, const float* resq,
                                                 float* outc, float* outq,
                                                 int Etot,
                                                 float* __restrict__ muc,
                                                 float* __restrict__ ric,
                                                 float* __restrict__ muq,
                                                 float* __restrict__ riq,
                                                 const float* __restrict__ gamma,
                                                 const float* __restrict__ beta) {
    int z = blockIdx.z;
    bool isq = z >= kB;
    int b = isq ? z - kB : z;
    int L = isq ? kM : kN;
    int l0 = blockIdx.x * 64;
    if (l0 >= L) return;
    const float* X = isq ? Xq : Xc;
    const float* res = isq ? resq : resc;
    float* out = isq ? outq : outc;
    float* muP = isq ? muq : muc;
    float* riP = isq ? riq : ric;

    __shared__ __align__(16) float Xs[32][68];
    __shared__ __align__(16) float Ws[32][132];
    __shared__ float mus[64], ris[64];
    __shared__ float gs[128], bs2[128];

    int tid = threadIdx.x;
    int eq = tid >> 5;
    int lq = tid & 31;
    int et = blockIdx.y * 128;

    if (LNX) {
        if (tid < 64) {
            int p = l0 + tid;
            mus[tid] = (p < L) ? muP[(size_t)b * L + p] : 0.f;
            ris[tid] = (p < L) ? riP[(size_t)b * L + p] : 0.f;
        }
        if (tid < 128) {
            gs[tid] = gamma[tid];
            bs2[tid] = beta[tid];
        }
        __syncthreads();
    }

    float acc[32];
#pragma unroll
    for (int j = 0; j < 32; j++) acc[j] = 0.f;

    for (int k = 0; k < 4; k++) {
        int d0 = k * 32;
#pragma unroll
        for (int r = 0; r < 8; r++) {
            int idx = tid + r * 256;
            int dd = idx >> 6;
            int ll = idx & 63;
            int lg = l0 + ll;
            float v = 0.f;
            if (lg < L) {
                v = X[((size_t)b * 128 + d0 + dd) * L + lg];
                if (LNX) v = gs[d0 + dd] * (v - mus[ll]) * ris[ll] + bs2[d0 + dd];
            }
            Xs[dd][ll] = v;
        }
#pragma unroll
        for (int r = 0; r < 16; r++) {
            int idx = tid + r * 256;
            if (TR) {
                int dd = idx >> 7;
                int e = idx & 127;
                Ws[dd][e] = W[(size_t)(d0 + dd) * Etot + et + e];
            } else {
                int e = idx >> 5;
                int dd = idx & 31;
                Ws[dd][e] = W[(size_t)(et + e) * 128 + d0 + dd];
            }
        }
        __syncthreads();
#pragma unroll
        for (int dd = 0; dd < 32; dd++) {
            float2 xv = *(const float2*)&Xs[dd][lq * 2];
            const float4* wp = (const float4*)&Ws[dd][eq * 16];
            float4 w0 = wp[0], w1 = wp[1], w2 = wp[2], w3 = wp[3];
            acc[0]  += w0.x * xv.x;  acc[1]  += w0.x * xv.y;
            acc[2]  += w0.y * xv.x;  acc[3]  += w0.y * xv.y;
            acc[4]  += w0.z * xv.x;  acc[5]  += w0.z * xv.y;
            acc[6]  += w0.w * xv.x;  acc[7]  += w0.w * xv.y;
            acc[8]  += w1.x * xv.x;  acc[9]  += w1.x * xv.y;
            acc[10] += w1.y * xv.x;  acc[11] += w1.y * xv.y;
            acc[12] += w1.z * xv.x;  acc[13] += w1.z * xv.y;
            acc[14] += w1.w * xv.x;  acc[15] += w1.w * xv.y;
            acc[16] += w2.x * xv.x;  acc[17] += w2.x * xv.y;
            acc[18] += w2.y * xv.x;  acc[19] += w2.y * xv.y;
            acc[20] += w2.z * xv.x;  acc[21] += w2.z * xv.y;
            acc[22] += w2.w * xv.x;  acc[23] += w2.w * xv.y;
            acc[24] += w3.x * xv.x;  acc[25] += w3.x * xv.y;
            acc[26] += w3.y * xv.x;  acc[27] += w3.y * xv.y;
            acc[28] += w3.z * xv.x;  acc[29] += w3.z * xv.y;
            acc[30] += w3.w * xv.x;  acc[31] += w3.w * xv.y;
        }
        __syncthreads();
    }

    float sum_l[2] = {0.f, 0.f};
    float sq_l[2] = {0.f, 0.f};
#pragma unroll
    for (int p = 0; p < 16; p++) {
        int e0 = et + eq * 16 + p;
        float bv = bias[e0];
#pragma unroll
        for (int q = 0; q < 2; q++) {
            float v = acc[p * 2 + q] + bv;
            if (RELU) v = fmaxf(v, 0.f);
            int lg = l0 + lq * 2 + q;
            if (lg < L) {
                size_t oi = ((size_t)b * Etot + e0) * L + lg;
                if (RES) v += res[oi];
                out[oi] = v;
            }
            if (STATS) {
                sum_l[q] += v;
                sq_l[q] += v * v;
            }
        }
    }
    if (STATS) {
        float* red = &Ws[0][0];
        red[eq * 64 + lq * 2 + 0] = sum_l[0];
        red[eq * 64 + lq * 2 + 1] = sum_l[1];
        red[512 + eq * 64 + lq * 2 + 0] = sq_l[0];
        red[512 + eq * 64 + lq * 2 + 1] = sq_l[1];
        __syncthreads();
        if (tid < 64) {
            int lg = l0 + tid;
            if (lg < L) {
                float s = 0.f, ss = 0.f;
#pragma unroll
                for (int g = 0; g < 8; g++) {
                    s += red[g * 64 + tid];
                    ss += red[512 + g * 64 + tid];
                }
                float muv = s * (1.f / 128.f);
                float var = (ss - 128.f * muv * muv) * (1.f / 127.f);
                var = fmaxf(var, 0.f);
                muP[(size_t)b * L + lg] = muv;
                riP[(size_t)b * L + lg] = 1.f / (sqrtf(var) + 1e-6f);
            }
        }
    }
}

// ----------------------------- QKV packing ---------------------------------
__global__ void k_pack_qkv(const float* __restrict__ Wq, const float* __restrict__ Wk,
                           const float* __restrict__ Wv, const float* __restrict__ bq,
                           const float* __restrict__ bk, const float* __restrict__ bv) {
    int idx = blockIdx.x * blockDim.x + threadIdx.x;
    if (idx < 3 * 128 * 128) {
        int e = idx >> 7;
        int d = idx & 127;
        int qv = e >> 7;
        int hk = e & 127;
        int h = hk >> 4;
        int kk = hk & 15;
        const float* src = (qv == 0) ? Wq : (qv == 1 ? Wk : Wv);
        g_Wqkv[idx] = src[((size_t)h * 128 + d) * 16 + kk];
    }
    if (idx < 384) {
        int qv = idx >> 7;
        int hk = idx & 127;
        const float* srcb = (qv == 0) ? bq : (qv == 1 ? bk : bv);
        g_bqkv[idx] = srcb[hk];
    }
}

// ----------------------------- attention core (dual) ------------------------
__global__ void __launch_bounds__(256) k_attn(const float* __restrict__ qkvc,
                                              const float* __restrict__ qkvq,
                                              const float* __restrict__ cmask,
                                              const float* __restrict__ qmask,
                                              float* __restrict__ oc,
                                              float* __restrict__ oq) {
    const int KT = 64;
    __shared__ u64 ks[KT][9], vs[KT][9];
    __shared__ float ms[KT];
    int tid = threadIdx.x;
    int bh = blockIdx.y;
    int z = bh >> 3;
    bool isq = z >= kB;
    int b = isq ? z - kB : z;
    int h = bh & 7;
    int L = isq ? kM : kN;
    int i = blockIdx.x * 256 + tid;
    if (blockIdx.x * 256 >= L) return;
    const float* qkv = isq ? qkvq : qkvc;
    const float* mask = isq ? qmask : cmask;
    float* o = isq ? oq : oc;
    bool act = i < L;

    u64 q2[8];
    if (act) {
        const float* qp = qkv + ((size_t)b * 384 + h * 16) * L + i;
#pragma unroll
        for (int c = 0; c < 8; c++)
            q2[c] = pk2(qp[(size_t)(2 * c) * L] * 0.25f, qp[(size_t)(2 * c + 1) * L] * 0.25f);
    }
    float m = -INFINITY, lsum = 0.f;
    u64 acc[8] = {0, 0, 0, 0, 0, 0, 0, 0};

    for (int j0 = 0; j0 < L; j0 += KT) {
        int cnt = min(KT, L - j0);
        for (int idx = tid; idx < 8 * KT; idx += 256) {
            int c = idx >> 6;
            int t = idx & 63;
            if (t < cnt) {
                const float* kp = qkv + ((size_t)b * 384 + 128 + h * 16 + 2 * c) * L + j0 + t;
                ks[t][c] = pk2(kp[0], kp[(size_t)L]);
                const float* vp = kp + (size_t)128 * L;
                vs[t][c] = pk2(vp[0], vp[(size_t)L]);
            } else {
                ks[t][c] = 0;
                vs[t][c] = 0;
            }
        }
        if (tid < KT) ms[tid] = (tid < cnt) ? mask[(size_t)b * L + j0 + tid] : 0.f;
        __syncthreads();
        if (act) {
            for (int g = 0; g < cnt; g += 8) {
                float sreg[8];
#pragma unroll
                for (int t2 = 0; t2 < 8; t2++) {
                    int t = g + t2;
                    u64 s2 = 0;
#pragma unroll
                    for (int c = 0; c < 8; c++) s2 = fma2(q2[c], ks[t][c], s2);
                    float slo, shi;
                    upk2(s2, slo, shi);
                    sreg[t2] = slo + shi - 1e30f * (1.f - ms[t]);
                }
                float gm = sreg[0];
#pragma unroll
                for (int t2 = 1; t2 < 8; t2++) gm = fmaxf(gm, sreg[t2]);
                float nm = fmaxf(m, gm);
                float sc = __expf(m - nm);
                lsum *= sc;
                u64 scp = pk2(sc, sc);
#pragma unroll
                for (int c = 0; c < 8; c++) acc[c] = mul2(scp, acc[c]);
#pragma unroll
                for (int t2 = 0; t2 < 8; t2++) {
                    int t = g + t2;
                    float p = __expf(sreg[t2] - nm);
                    lsum += p;
                    u64 pp = pk2(p, p);
#pragma unroll
                    for (int c = 0; c < 8; c++) acc[c] = fma2(pp, vs[t][c], acc[c]);
                }
                m = nm;
            }
        }
        __syncthreads();
    }
    if (act) {
        float r = 1.f / lsum;
        float* op = o + ((size_t)b * 128 + h * 16) * L + i;
#pragma unroll
        for (int c = 0; c < 8; c++) {
            float lo, hi;
            upk2(acc[c], lo, hi);
            op[(size_t)(2 * c) * L] = lo * r;
            op[(size_t)(2 * c + 1) * L] = hi * r;
        }
    }
}

// ------------------------------ transposes ---------------------------------
__global__ void k_trC(const float* __restrict__ X, float* __restrict__ Y, int L) {
    __shared__ float t[32][33];
    int b = blockIdx.z, d0 = blockIdx.y * 32, l0 = blockIdx.x * 32;
    int tx = threadIdx.x, ty = threadIdx.y;
#pragma unroll
    for (int k = 0; k < 4; k++) {
        int l = l0 + tx;
        t[ty + 8 * k][tx] = (l < L) ? X[((size_t)b * 128 + d0 + ty + 8 * k) * L + l] : 0.f;
    }
    __syncthreads();
#pragma unroll
    for (int k = 0; k < 4; k++) {
        int l = l0 + ty + 8 * k;
        if (l < L) Y[((size_t)b * L + l) * 128 + d0 + tx] = t[tx][ty + 8 * k];
    }
}

__global__ void k_trQ(const float* __restrict__ X, float* __restrict__ Yt,
                      float* __restrict__ Yw, const float* __restrict__ wm) {
    __shared__ float t[32][33];
    int b = blockIdx.z, d0 = blockIdx.y * 32, l0 = blockIdx.x * 32;
    int tx = threadIdx.x, ty = threadIdx.y;
#pragma unroll
    for (int k = 0; k < 4; k++) {
        int l = l0 + tx;
        t[ty + 8 * k][tx] = (l < kM) ? X[((size_t)b * 128 + d0 + ty + 8 * k) * kM + l] : 0.f;
    }
    __syncthreads();
    float w = wm[d0 + tx];
#pragma unroll
    for (int k = 0; k < 4; k++) {
        int l = l0 + ty + 8 * k;
        if (l < kM) {
            float v = t[tx][ty + 8 * k];
            size_t oi = ((size_t)b * kM + l) * 128 + d0 + tx;
            Yt[oi] = v;
            Yw[oi] = v * w;
        }
    }
}

// ------------------------------ CQ attention -------------------------------
__global__ void k_dot(const float* __restrict__ X, const float* __restrict__ w,
                      float* __restrict__ out, int L) {
    int idx = blockIdx.x * blockDim.x + threadIdx.x;
    if (idx >= kB * L) return;
    int b = idx / L;
    int pos = idx % L;
    const float* xp = X + (size_t)b * kD * L + pos;
    float a = 0.f;
#pragma unroll 8
    for (int d = 0; d < kD; d++) a += w[d] * xp[(size_t)d * L];
    out[idx] = a;
}

__global__ void __launch_bounds__(256) k_sgemm(const float* __restrict__ X,
                                               const float* __restrict__ Qw,
                                               const float* __restrict__ cc,
                                               const float* __restrict__ qq,
                                               const float* __restrict__ b0,
                                               float* __restrict__ S) {
    __shared__ float Xs[32][33];
    __shared__ float Ws[32][68];
    int tid = threadIdx.x;
    int l = tid & 31;
    int eg = tid >> 5;
    int l0 = blockIdx.x * 32;
    int b = blockIdx.y;
    u64 acc[4] = {0, 0, 0, 0};

    for (int d0 = 0; d0 < 128; d0 += 32) {
#pragma unroll
        for (int r = 0; r < 4; r++) {
            int idx = tid + r * 256;
            int dd = idx >> 5, ll = idx & 31;
            int lg = l0 + ll;
            Xs[dd][ll] = (lg < kN) ? X[((size_t)b * 128 + d0 + dd) * kN + lg] : 0.f;
        }
#pragma unroll
        for (int r = 0; r < 8; r++) {
            int idx = tid + r * 256;
            int dd = idx >> 6;
            int e = idx & 63;
            Ws[dd][e] = (e < kM) ? Qw[((size_t)b * kM + e) * 128 + d0 + dd] : 0.f;
        }
        __syncthreads();
#pragma unroll
        for (int dd = 0; dd < 32; dd++) {
            float xv = Xs[dd][l];
            u64 xx = pk2(xv, xv);
            const ulonglong2* wr = (const ulonglong2*)&Ws[dd][eg * 8];
            ulonglong2 w0 = wr[0], w1 = wr[1];
            acc[0] = fma2(xx, w0.x, acc[0]);
            acc[1] = fma2(xx, w0.y, acc[1]);
            acc[2] = fma2(xx, w1.x, acc[2]);
            acc[3] = fma2(xx, w1.y, acc[3]);
        }
        __syncthreads();
    }
    int lg = l0 + l;
    if (lg < kN) {
        float base = cc[b * kN + lg] + b0[0];
#pragma unroll
        for (int j = 0; j < 4; j++) {
            float v0, v1;
            upk2(acc[j], v0, v1);
            int e0 = eg * 8 + 2 * j;
            if (e0 < kM) S[((size_t)b * kM + e0) * kN + lg] = v0 + base + qq[b * kM + e0];
            if (e0 + 1 < kM) S[((size_t)b * kM + e0 + 1) * kN + lg] = v1 + base + qq[b * kM + e0 + 1];
        }
    }
}

__global__ void k_smrow(const float* __restrict__ qmask) {
    int idx = blockIdx.x * blockDim.x + threadIdx.x;
    if (idx >= kB * kN) return;
    int b = idx / kN;
    int n = idx % kN;
    float v[kM];
    float mx = -INFINITY;
#pragma unroll
    for (int m = 0; m < kM; m++) {
        v[m] = g_S[((size_t)b * kM + m) * kN + n] - 1e30f * (1.f - qmask[b * kM + m]);
        mx = fmaxf(mx, v[m]);
    }
    float s = 0.f;
#pragma unroll
    for (int m = 0; m < kM; m++) {
        v[m] = __expf(v[m] - mx);
        s += v[m];
    }
    float r = 1.f / s;
#pragma unroll
    for (int m = 0; m < kM; m++) g_Sr[((size_t)b * kM + m) * kN + n] = v[m] * r;
}

__global__ void k_smcol(const float* __restrict__ cmask) {
    int w = (blockIdx.x * blockDim.x + threadIdx.x) >> 5;
    int lane = threadIdx.x & 31;
    if (w >= kB * kM) return;
    int b = w / kM;
    const float* row = g_S + (size_t)w * kN;
    const float* mrow = cmask + (size_t)b * kN;
    float v[13];
#pragma unroll
    for (int k = 0; k < 13; k++) {
        int n = lane + k * 32;
        v[k] = (n < kN) ? row[n] - 1e30f * (1.f - mrow[n]) : -INFINITY;
    }
    float mx = v[0];
#pragma unroll
    for (int k = 1; k < 13; k++) mx = fmaxf(mx, v[k]);
#pragma unroll
    for (int o = 16; o; o >>= 1) mx = fmaxf(mx, __shfl_xor_sync(0xffffffff, mx, o));
    float s = 0.f;
    float e[13];
#pragma unroll
    for (int k = 0; k < 13; k++) {
        int n = lane + k * 32;
        e[k] = (n < kN) ? __expf(v[k] - mx) : 0.f;
        s += e[k];
    }
#pragma unroll
    for (int o = 16; o; o >>= 1) s += __shfl_xor_sync(0xffffffff, s, o);
    float r = 1.f / s;
    float* orow = g_Sc + (size_t)w * kN;
#pragma unroll
    for (int k = 0; k < 13; k++) {
        int n = lane + k * 32;
        if (n < kN) orow[n] = e[k] * r;
    }
}

__global__ void __launch_bounds__(512) k_U(const float* __restrict__ Ct) {
    int b = blockIdx.x;
    int tid = threadIdx.x;
    int d = tid & 127;
    int mq = tid >> 7;
    __shared__ float cts[16][128];
    __shared__ float scs[16][56];
    u64 acc[7] = {0, 0, 0, 0, 0, 0, 0};

    for (int n0 = 0; n0 < kN; n0 += 16) {
#pragma unroll
        for (int r = 0; r < 4; r++) {
            int idx = tid + r * 512;
            int n = idx >> 7, dd = idx & 127;
            cts[n][dd] = Ct[((size_t)b * kN + n0 + n) * 128 + dd];
        }
        for (int idx = tid; idx < 16 * 56; idx += 512) {
            int n = idx & 15;
            int m = idx >> 4;
            scs[n][m] = (m < kM) ? g_Sc[((size_t)b * kM + m) * kN + n0 + n] : 0.f;
        }
        __syncthreads();
#pragma unroll
        for (int n = 0; n < 16; n++) {
            float ct = cts[n][d];
            u64 c2 = pk2(ct, ct);
            const u64* sp = (const u64*)&scs[n][mq * 14];
#pragma unroll
            for (int j = 0; j < 7; j++) acc[j] = fma2(c2, sp[j], acc[j]);
        }
        __syncthreads();
    }
#pragma unroll
    for (int j = 0; j < 7; j++) {
        float v0, v1;
        upk2(acc[j], v0, v1);
        int m = mq * 14 + 2 * j;
        if (m < kM) g_U[((size_t)b * kM + m) * 128 + d] = v0;
        if (m + 1 < kM) g_U[((size_t)b * kM + m + 1) * 128 + d] = v1;
    }
}

__global__ void __launch_bounds__(256) k_out(const float* __restrict__ Ct,
                                             float* __restrict__ out) {
    int b = blockIdx.x / 25;
    int n0 = (blockIdx.x % 25) * 16;
    int tid = threadIdx.x;
    int d = tid & 127;
    int nq = tid >> 7;
    __shared__ float srs[kM][16];
    for (int idx = tid; idx < kM * 16; idx += 256) {
        int m = idx >> 4, nj = idx & 15;
        srs[m][nj] = g_Sr[((size_t)b * kM + m) * kN + n0 + nj];
    }
    __syncthreads();
    u64 a2[4] = {0, 0, 0, 0};
    u64 b2[4] = {0, 0, 0, 0};
    for (int m = 0; m < kM; m++) {
        float qv = g_Qt[((size_t)b * kM + m) * 128 + d];
        float uv = g_U[((size_t)b * kM + m) * 128 + d];
        u64 q2 = pk2(qv, qv), u2 = pk2(uv, uv);
        const u64* sp = (const u64*)&srs[m][nq * 8];
#pragma unroll
        for (int j = 0; j < 4; j++) {
            a2[j] = fma2(sp[j], q2, a2[j]);
            b2[j] = fma2(sp[j], u2, b2[j]);
        }
    }
#pragma unroll
    for (int j = 0; j < 4; j++) {
        float a0, a1, bt0, bt1;
        upk2(a2[j], a0, a1);
        upk2(b2[j], bt0, bt1);
#pragma unroll
        for (int t = 0; t < 2; t++) {
            int n = n0 + nq * 8 + 2 * j + t;
            float a = (t == 0) ? a0 : a1;
            float bt = (t == 0) ? bt0 : bt1;
            float c = Ct[((size_t)b * kN + n) * 128 + d];
            size_t base = ((size_t)b * kN + n) * 512;
            out[base + d] = c;
            out[base + 128 + d] = a;
            out[base + 256 + d] = c * a;
            out[base + 384 + d] = c * bt;
        }
    }
}

// ------------------------------- host side ---------------------------------
static inline int ceil_div(int a, int b) { return (a + b - 1) / b; }

extern "C" void kernel_launch(void* const* d_in, const int* in_sizes, int n_in,
                              void* d_out, int out_size) {
    (void)in_sizes; (void)n_in; (void)out_size;
    const float* ctx   = (const float*)d_in[0];
    const float* qst   = (const float*)d_in[1];
    const float* cmask = (const float*)d_in[2];
    const float* qmask = (const float*)d_in[3];
    const float* ln_g  = (const float*)d_in[4];
    const float* ln_b  = (const float*)d_in[5];
    const float* dww   = (const float*)d_in[6];
    const float* dwb   = (const float*)d_in[7];
    const float* pww   = (const float*)d_in[8];
    const float* pwb   = (const float*)d_in[9];
    const float* Wq    = (const float*)d_in[10];
    const float* bq    = (const float*)d_in[11];
    const float* Wk    = (const float*)d_in[12];
    const float* bk    = (const float*)d_in[13];
    const float* Wv    = (const float*)d_in[14];
    const float* bv    = (const float*)d_in[15];
    const float* Wo    = (const float*)d_in[16];
    const float* bo    = (const float*)d_in[17];
    const float* Wfc   = (const float*)d_in[18];
    const float* bfc   = (const float*)d_in[19];
    const float* cq_wc = (const float*)d_in[20];
    const float* cq_wq = (const float*)d_in[21];
    const float* cq_wm = (const float*)d_in[22];
    const float* cq_b  = (const float*)d_in[23];

    float *pC, *pQ, *pdw, *pQ2, *pqkv, *pqkvq, *pao, *paoq, *pcc, *pqq;
    float *pCt, *pQt, *pQw, *pmu, *pri, *pmu2, *pri2;
    cudaGetSymbolAddress((void**)&pC, g_C);
    cudaGetSymbolAddress((void**)&pQ, g_Q);
    cudaGetSymbolAddress((void**)&pdw, g_dw);
    cudaGetSymbolAddress((void**)&pQ2, g_Q2);
    cudaGetSymbolAddress((void**)&pqkv, g_qkv);
    cudaGetSymbolAddress((void**)&pqkvq, g_qkv_q);
    cudaGetSymbolAddress((void**)&pao, g_ao);
    cudaGetSymbolAddress((void**)&paoq, g_ao_q);
    cudaGetSymbolAddress((void**)&pcc, g_cc);
    cudaGetSymbolAddress((void**)&pqq, g_qq);
    cudaGetSymbolAddress((void**)&pCt, g_Ct);
    cudaGetSymbolAddress((void**)&pQt, g_Qt);
    cudaGetSymbolAddress((void**)&pQw, g_Qw);
    cudaGetSymbolAddress((void**)&pmu, g_mu);
    cudaGetSymbolAddress((void**)&pri, g_ri);
    cudaGetSymbolAddress((void**)&pmu2, g_mu2);
    cudaGetSymbolAddress((void**)&pri2, g_ri2);
    float* pWqkv; cudaGetSymbolAddress((void**)&pWqkv, g_Wqkv);
    float* pbqkv; cudaGetSymbolAddress((void**)&pbqkv, g_bqkv);
    float* pS;    cudaGetSymbolAddress((void**)&pS, g_S);

    k_pe<<<ceil_div(kD * kN, 256), 256>>>();
    k_pack_qkv<<<ceil_div(3 * 128 * 128, 256), 256>>>(Wq, Wk, Wv, bq, bk, bv);

    // PE + LN stats for both sequences
    k_add_pe_stats<<<ceil_div(kB * kN, 32), 128>>>(ctx, pC, pmu, pri, kN);
    k_add_pe_stats<<<ceil_div(kB * kM, 32), 128>>>(qst, pQ, pmu2, pri2, kM);

    // Dual-sequence encoder: grid.z 0..63 = context, 64..127 = question
    int lt = ceil_div(kN, 64);   // 7
    dim3 gz(lt, 1, 2 * kB);
    float* cb_[2] = {pC, pdw};
    float* qb_[2] = {pQ, pQ2};
    for (int i = 0; i < kNC; i++) {
        float* srcC = cb_[i & 1];
        float* dstC = cb_[(i + 1) & 1];
        float* srcQ = qb_[i & 1];
        float* dstQ = qb_[(i + 1) & 1];
        k_cgemm<<<gz, 256>>>(srcC, srcQ, dstC, dstQ,
                             pww + (size_t)i * kD * kD, pwb + (size_t)i * kD,
                             dww + (size_t)i * kD * kKW, dwb + (size_t)i * kD,
                             ln_g, ln_b, pmu, pri, pmu2, pri2);
    }
    // after 4 layers activations are back in pC / pQ
    k_gemm<false, false, false, true, false><<<dim3(lt, 3, 2 * kB), 256>>>(
        pC, pQ, pWqkv, pbqkv, nullptr, nullptr, pqkv, pqkvq, 384,
        pmu, pri, pmu2, pri2, ln_g, ln_b);
    k_attn<<<dim3(ceil_div(kN, 256), 2 * kB * kH), 256>>>(
        pqkv, pqkvq, cmask, qmask, pao, paoq);
    k_gemm<true, false, true, false, true><<<dim3(lt, 1, 2 * kB), 256>>>(
        pao, paoq, Wo, bo, pC, pQ, pC, pQ, kD,
        pmu, pri, pmu2, pri2, nullptr, nullptr);
    k_gemm<false, false, true, true, false><<<dim3(lt, 1, 2 * kB), 256>>>(
        pC, pQ, Wfc, bfc, pC, pQ, pC, pQ, kD,
        pmu, pri, pmu2, pri2, ln_g, ln_b);

    // --------- context-query attention ---------
    k_dot<<<ceil_div(kB * kN, 256), 256>>>(pC, cq_wc, pcc, kN);
    k_dot<<<ceil_div(kB * kM, 256), 256>>>(pQ, cq_wq, pqq, kM);
    k_trC<<<dim3(13, 4, kB), dim3(32, 8)>>>(pC, pCt, kN);
    k_trQ<<<dim3(2, 4, kB), dim3(32, 8)>>>(pQ, pQt, pQw, cq_wm);
    k_sgemm<<<dim3(13, kB), 256>>>(pC, pQw, pcc, pqq, cq_b, pS);
    k_smrow<<<ceil_div(kB * kN, 256), 256>>>(qmask);
    k_smcol<<<ceil_div(kB * kM * 32, 256), 256>>>(cmask);
    k_U<<<kB, 512>>>(pCt);
    k_out<<<kB * 25, 256>>>(pCt, (float*)d_out);
}

// round 13
// speedup vs baseline: 1.8268x; 1.0267x over previous
#include <cuda_runtime.h>
#include <math.h>

// ---------------------------------------------------------------------------
// QANet forward, fp32 on sm_103a.
// R13: R12 + fused dual pe_stats launch + attention with 2 queries/thread.
// ---------------------------------------------------------------------------
#define kB 64
#define kD 128
#define kN 400
#define kM 50
#define kH 8
#define kKD 16
#define kNC 4
#define kKW 7
#define kPAD 3

typedef unsigned long long u64;

__device__ __forceinline__ u64 pk2(float lo, float hi) {
    u64 r; asm("mov.b64 %0,{%1,%2};" : "=l"(r) : "f"(lo), "f"(hi)); return r;
}
__device__ __forceinline__ void upk2(u64 v, float& lo, float& hi) {
    asm("mov.b64 {%0,%1},%2;" : "=f"(lo), "=f"(hi) : "l"(v));
}
__device__ __forceinline__ u64 fma2(u64 a, u64 b, u64 c) {
    u64 d; asm("fma.rn.f32x2 %0,%1,%2,%3;" : "=l"(d) : "l"(a), "l"(b), "l"(c)); return d;
}
__device__ __forceinline__ u64 mul2(u64 a, u64 b) {
    u64 d; asm("mul.rn.f32x2 %0,%1,%2;" : "=l"(d) : "l"(a), "l"(b)); return d;
}

// ------------------------- device scratch (static) -------------------------
__device__ float g_C[kB * kD * kN];
__device__ float g_Q[kB * kD * kM];
__device__ float g_dw[kB * kD * kN];
__device__ float g_Q2[kB * kD * kM];
__device__ float g_qkv[kB * 3 * kD * kN];
__device__ float g_qkv_q[kB * 3 * kD * kM];
__device__ float g_ao[kB * kD * kN];
__device__ float g_ao_q[kB * kD * kM];
__device__ float g_Wqkv[3 * kD * kD];   // [e][d]
__device__ float g_bqkv[3 * kD];
__device__ float g_pe[kD * kN];
__device__ float g_mu[kB * kN];
__device__ float g_ri[kB * kN];
__device__ float g_mu2[kB * kM];
__device__ float g_ri2[kB * kM];
__device__ float g_S[kB * kM * kN];
__device__ float g_Sr[kB * kM * kN];
__device__ float g_Sc[kB * kM * kN];
__device__ float g_U[kB * kM * kD];
__device__ float g_Ct[kB * kN * kD];
__device__ float g_Qt[kB * kM * kD];
__device__ float g_Qw[kB * kM * kD];
__device__ float g_cc[kB * kN];
__device__ float g_qq[kB * kM];

// ------------------------------ PE table ----------------------------------
__global__ void k_pe() {
    int idx = blockIdx.x * blockDim.x + threadIdx.x;
    if (idx >= kD * kN) return;
    int d = idx / kN;
    int l = idx % kN;
    int d0 = d & ~1;
    double f = pow(10000.0, -(double)d0 / (double)kD);
    double a = (double)l * f;
    g_pe[idx] = (d & 1) ? (float)cos(a) : (float)sin(a);
}

// ----------- add PE + compute LN stats, DUAL sequence, one launch ----------
__global__ void __launch_bounds__(128) k_pe_stats(const float* __restrict__ xc,
                                                  const float* __restrict__ xq,
                                                  float* __restrict__ yc,
                                                  float* __restrict__ yq,
                                                  float* __restrict__ muc,
                                                  float* __restrict__ ric,
                                                  float* __restrict__ muq,
                                                  float* __restrict__ riq) {
    const int CBLK = (kB * kN) / 32;  // 800
    int blk = blockIdx.x;
    bool isq = blk >= CBLK;
    int L = isq ? kM : kN;
    const float* x = isq ? xq : xc;
    float* y = isq ? yq : yc;
    float* omu = isq ? muq : muc;
    float* ori = isq ? riq : ric;
    int pos0 = (isq ? blk - CBLK : blk) * 32;

    int tid = threadIdx.x;
    int lsub = tid & 31;
    int grp = tid >> 5;
    int pos = pos0 + lsub;
    int P = kB * L;
    bool ok = pos < P;
    int b = ok ? pos / L : 0;
    int l = ok ? pos % L : 0;

    float s = 0.f, sq = 0.f;
    if (ok) {
        const float* xp = x + ((size_t)b * kD + grp * 32) * L + l;
        float* yp = y + ((size_t)b * kD + grp * 32) * L + l;
#pragma unroll
        for (int k = 0; k < 32; k++) {
            int d = grp * 32 + k;
            float v = xp[(size_t)k * L] + g_pe[d * kN + l];
            yp[(size_t)k * L] = v;
            s += v;
            sq += v * v;
        }
    }
    __shared__ float ss[4][32], sb[4][32];
    ss[grp][lsub] = s;
    sb[grp][lsub] = sq;
    __syncthreads();
    if (grp == 0 && ok) {
        float ts = ss[0][lsub] + ss[1][lsub] + ss[2][lsub] + ss[3][lsub];
        float tq = sb[0][lsub] + sb[1][lsub] + sb[2][lsub] + sb[3][lsub];
        float mu = ts * (1.f / 128.f);
        float var = (tq - 128.f * mu * mu) * (1.f / 127.f);
        var = fmaxf(var, 0.f);
        omu[pos] = mu;
        ori[pos] = 1.f / (sqrtf(var) + 1e-6f);
    }
}

// ---------------- fused LN + depthwise conv + pointwise GEMM (dual) ---------
__global__ void __launch_bounds__(256, 3) k_cgemm(const float* __restrict__ Xc,
                                                  const float* __restrict__ Xq,
                                                  float* __restrict__ outc,
                                                  float* __restrict__ outq,
                                                  const float* __restrict__ Wpw,
                                                  const float* __restrict__ pwb,
                                                  const float* __restrict__ cw,
                                                  const float* __restrict__ cb,
                                                  const float* __restrict__ gamma,
                                                  const float* __restrict__ beta,
                                                  float* __restrict__ muc,
                                                  float* __restrict__ ric,
                                                  float* __restrict__ muq,
                                                  float* __restrict__ riq) {
    int z = blockIdx.z;
    bool isq = z >= kB;
    int b = isq ? z - kB : z;
    int L = isq ? kM : kN;
    int l0 = blockIdx.x * 64;
    if (l0 >= L) return;
    const float* X = isq ? Xq : Xc;
    float* out = isq ? outq : outc;
    float* muP = isq ? muq : muc;
    float* riP = isq ? riq : ric;

    __shared__ __align__(16) float Xl[32][72];
    __shared__ __align__(16) float Xs[32][68];
    __shared__ __align__(16) float Ws[32][132];
    __shared__ float mus[72], ris[72];
    __shared__ float gs[128], bs2[128];
    __shared__ float cws[128][8];

    int tid = threadIdx.x;
    int eq = tid >> 5;
    int lq = tid & 31;

    if (tid < 70) {
        int gl = l0 + tid - 3;
        bool in = (gl >= 0 && gl < L);
        mus[tid] = in ? muP[(size_t)b * L + gl] : 0.f;
        ris[tid] = in ? riP[(size_t)b * L + gl] : 0.f;
    }
    if (tid < 128) {
        gs[tid] = gamma[tid];
        bs2[tid] = beta[tid];
#pragma unroll
        for (int k = 0; k < 7; k++) cws[tid][k] = cw[tid * 7 + k];
        cws[tid][7] = cb[tid];
    }
    __syncthreads();

    float acc[32];
#pragma unroll
    for (int j = 0; j < 32; j++) acc[j] = 0.f;

    for (int k = 0; k < 4; k++) {
        int d0 = k * 32;
#pragma unroll
        for (int r = 0; r < 9; r++) {
            int idx = tid + r * 256;
            if (idx < 2240) {
                int dd = idx / 70;
                int ll = idx - dd * 70;
                int gl = l0 + ll - 3;
                float v = 0.f;
                if (gl >= 0 && gl < L) {
                    float xv = X[((size_t)b * 128 + d0 + dd) * L + gl];
                    v = gs[d0 + dd] * (xv - mus[ll]) * ris[ll] + bs2[d0 + dd];
                }
                Xl[dd][ll] = v;
            }
        }
#pragma unroll
        for (int r = 0; r < 16; r++) {
            int idx = tid + r * 256;
            int e = idx >> 5;
            int dd = idx & 31;
            Ws[dd][e] = Wpw[(size_t)e * 128 + d0 + dd];
        }
        __syncthreads();
#pragma unroll
        for (int r = 0; r < 8; r++) {
            int idx = tid + r * 256;
            int dd = idx >> 6;
            int ll = idx & 63;
            int d = d0 + dd;
            float a = cws[d][7];
#pragma unroll
            for (int kk = 0; kk < 7; kk++) a += cws[d][kk] * Xl[dd][ll + kk];
            Xs[dd][ll] = a;
        }
        __syncthreads();
#pragma unroll
        for (int dd = 0; dd < 32; dd++) {
            float2 xv = *(const float2*)&Xs[dd][lq * 2];
            const float4* wp = (const float4*)&Ws[dd][eq * 16];
            float4 w0 = wp[0], w1 = wp[1], w2 = wp[2], w3 = wp[3];
            acc[0]  += w0.x * xv.x;  acc[1]  += w0.x * xv.y;
            acc[2]  += w0.y * xv.x;  acc[3]  += w0.y * xv.y;
            acc[4]  += w0.z * xv.x;  acc[5]  += w0.z * xv.y;
            acc[6]  += w0.w * xv.x;  acc[7]  += w0.w * xv.y;
            acc[8]  += w1.x * xv.x;  acc[9]  += w1.x * xv.y;
            acc[10] += w1.y * xv.x;  acc[11] += w1.y * xv.y;
            acc[12] += w1.z * xv.x;  acc[13] += w1.z * xv.y;
            acc[14] += w1.w * xv.x;  acc[15] += w1.w * xv.y;
            acc[16] += w2.x * xv.x;  acc[17] += w2.x * xv.y;
            acc[18] += w2.y * xv.x;  acc[19] += w2.y * xv.y;
            acc[20] += w2.z * xv.x;  acc[21] += w2.z * xv.y;
            acc[22] += w2.w * xv.x;  acc[23] += w2.w * xv.y;
            acc[24] += w3.x * xv.x;  acc[25] += w3.x * xv.y;
            acc[26] += w3.y * xv.x;  acc[27] += w3.y * xv.y;
            acc[28] += w3.z * xv.x;  acc[29] += w3.z * xv.y;
            acc[30] += w3.w * xv.x;  acc[31] += w3.w * xv.y;
        }
        __syncthreads();
    }

    float sum_l[2] = {0.f, 0.f};
    float sq_l[2] = {0.f, 0.f};
#pragma unroll
    for (int p = 0; p < 16; p++) {
        int e0 = eq * 16 + p;
        float bv = pwb[e0];
#pragma unroll
        for (int q = 0; q < 2; q++) {
            float v = fmaxf(acc[p * 2 + q] + bv, 0.f);
            int lg = l0 + lq * 2 + q;
            if (lg < L) {
                size_t oi = ((size_t)b * 128 + e0) * L + lg;
                v += X[oi];
                out[oi] = v;
            }
            sum_l[q] += v;
            sq_l[q] += v * v;
        }
    }
    float* red = &Ws[0][0];
    red[eq * 64 + lq * 2 + 0] = sum_l[0];
    red[eq * 64 + lq * 2 + 1] = sum_l[1];
    red[512 + eq * 64 + lq * 2 + 0] = sq_l[0];
    red[512 + eq * 64 + lq * 2 + 1] = sq_l[1];
    __syncthreads();
    if (tid < 64) {
        int lg = l0 + tid;
        if (lg < L) {
            float s = 0.f, ss = 0.f;
#pragma unroll
            for (int g = 0; g < 8; g++) {
                s += red[g * 64 + tid];
                ss += red[512 + g * 64 + tid];
            }
            float muv = s * (1.f / 128.f);
            float var = (ss - 128.f * muv * muv) * (1.f / 127.f);
            var = fmaxf(var, 0.f);
            muP[(size_t)b * L + lg] = muv;
            riP[(size_t)b * L + lg] = 1.f / (sqrtf(var) + 1e-6f);
        }
    }
}

// ------------------------------- GEMM (dual) --------------------------------
template <bool TR, bool RELU, bool RES, bool LNX, bool STATS>
__global__ void __launch_bounds__(256, 3) k_gemm(const float* __restrict__ Xc,
                                                 const float* __restrict__ Xq,
                                                 const float* __restrict__ W,
                                                 const float* __restrict__ bias,
                                                 const float* resc, const float* resq,
                                                 float* outc, float* outq,
                                                 int Etot,
                                                 float* __restrict__ muc,
                                                 float* __restrict__ ric,
                                                 float* __restrict__ muq,
                                                 float* __restrict__ riq,
                                                 const float* __restrict__ gamma,
                                                 const float* __restrict__ beta) {
    int z = blockIdx.z;
    bool isq = z >= kB;
    int b = isq ? z - kB : z;
    int L = isq ? kM : kN;
    int l0 = blockIdx.x * 64;
    if (l0 >= L) return;
    const float* X = isq ? Xq : Xc;
    const float* res = isq ? resq : resc;
    float* out = isq ? outq : outc;
    float* muP = isq ? muq : muc;
    float* riP = isq ? riq : ric;

    __shared__ __align__(16) float Xs[32][68];
    __shared__ __align__(16) float Ws[32][132];
    __shared__ float mus[64], ris[64];
    __shared__ float gs[128], bs2[128];

    int tid = threadIdx.x;
    int eq = tid >> 5;
    int lq = tid & 31;
    int et = blockIdx.y * 128;

    if (LNX) {
        if (tid < 64) {
            int p = l0 + tid;
            mus[tid] = (p < L) ? muP[(size_t)b * L + p] : 0.f;
            ris[tid] = (p < L) ? riP[(size_t)b * L + p] : 0.f;
        }
        if (tid < 128) {
            gs[tid] = gamma[tid];
            bs2[tid] = beta[tid];
        }
        __syncthreads();
    }

    float acc[32];
#pragma unroll
    for (int j = 0; j < 32; j++) acc[j] = 0.f;

    for (int k = 0; k < 4; k++) {
        int d0 = k * 32;
#pragma unroll
        for (int r = 0; r < 8; r++) {
            int idx = tid + r * 256;
            int dd = idx >> 6;
            int ll = idx & 63;
            int lg = l0 + ll;
            float v = 0.f;
            if (lg < L) {
                v = X[((size_t)b * 128 + d0 + dd) * L + lg];
                if (LNX) v = gs[d0 + dd] * (v - mus[ll]) * ris[ll] + bs2[d0 + dd];
            }
            Xs[dd][ll] = v;
        }
#pragma unroll
        for (int r = 0; r < 16; r++) {
            int idx = tid + r * 256;
            if (TR) {
                int dd = idx >> 7;
                int e = idx & 127;
                Ws[dd][e] = W[(size_t)(d0 + dd) * Etot + et + e];
            } else {
                int e = idx >> 5;
                int dd = idx & 31;
                Ws[dd][e] = W[(size_t)(et + e) * 128 + d0 + dd];
            }
        }
        __syncthreads();
#pragma unroll
        for (int dd = 0; dd < 32; dd++) {
            float2 xv = *(const float2*)&Xs[dd][lq * 2];
            const float4* wp = (const float4*)&Ws[dd][eq * 16];
            float4 w0 = wp[0], w1 = wp[1], w2 = wp[2], w3 = wp[3];
            acc[0]  += w0.x * xv.x;  acc[1]  += w0.x * xv.y;
            acc[2]  += w0.y * xv.x;  acc[3]  += w0.y * xv.y;
            acc[4]  += w0.z * xv.x;  acc[5]  += w0.z * xv.y;
            acc[6]  += w0.w * xv.x;  acc[7]  += w0.w * xv.y;
            acc[8]  += w1.x * xv.x;  acc[9]  += w1.x * xv.y;
            acc[10] += w1.y * xv.x;  acc[11] += w1.y * xv.y;
            acc[12] += w1.z * xv.x;  acc[13] += w1.z * xv.y;
            acc[14] += w1.w * xv.x;  acc[15] += w1.w * xv.y;
            acc[16] += w2.x * xv.x;  acc[17] += w2.x * xv.y;
            acc[18] += w2.y * xv.x;  acc[19] += w2.y * xv.y;
            acc[20] += w2.z * xv.x;  acc[21] += w2.z * xv.y;
            acc[22] += w2.w * xv.x;  acc[23] += w2.w * xv.y;
            acc[24] += w3.x * xv.x;  acc[25] += w3.x * xv.y;
            acc[26] += w3.y * xv.x;  acc[27] += w3.y * xv.y;
            acc[28] += w3.z * xv.x;  acc[29] += w3.z * xv.y;
            acc[30] += w3.w * xv.x;  acc[31] += w3.w * xv.y;
        }
        __syncthreads();
    }

    float sum_l[2] = {0.f, 0.f};
    float sq_l[2] = {0.f, 0.f};
#pragma unroll
    for (int p = 0; p < 16; p++) {
        int e0 = et + eq * 16 + p;
        float bv = bias[e0];
#pragma unroll
        for (int q = 0; q < 2; q++) {
            float v = acc[p * 2 + q] + bv;
            if (RELU) v = fmaxf(v, 0.f);
            int lg = l0 + lq * 2 + q;
            if (lg < L) {
                size_t oi = ((size_t)b * Etot + e0) * L + lg;
                if (RES) v += res[oi];
                out[oi] = v;
            }
            if (STATS) {
                sum_l[q] += v;
                sq_l[q] += v * v;
            }
        }
    }
    if (STATS) {
        float* red = &Ws[0][0];
        red[eq * 64 + lq * 2 + 0] = sum_l[0];
        red[eq * 64 + lq * 2 + 1] = sum_l[1];
        red[512 + eq * 64 + lq * 2 + 0] = sq_l[0];
        red[512 + eq * 64 + lq * 2 + 1] = sq_l[1];
        __syncthreads();
        if (tid < 64) {
            int lg = l0 + tid;
            if (lg < L) {
                float s = 0.f, ss = 0.f;
#pragma unroll
                for (int g = 0; g < 8; g++) {
                    s += red[g * 64 + tid];
                    ss += red[512 + g * 64 + tid];
                }
                float muv = s * (1.f / 128.f);
                float var = (ss - 128.f * muv * muv) * (1.f / 127.f);
                var = fmaxf(var, 0.f);
                muP[(size_t)b * L + lg] = muv;
                riP[(size_t)b * L + lg] = 1.f / (sqrtf(var) + 1e-6f);
            }
        }
    }
}

// ----------------------------- QKV packing ---------------------------------
__global__ void k_pack_qkv(const float* __restrict__ Wq, const float* __restrict__ Wk,
                           const float* __restrict__ Wv, const float* __restrict__ bq,
                           const float* __restrict__ bk, const float* __restrict__ bv) {
    int idx = blockIdx.x * blockDim.x + threadIdx.x;
    if (idx < 3 * 128 * 128) {
        int e = idx >> 7;
        int d = idx & 127;
        int qv = e >> 7;
        int hk = e & 127;
        int h = hk >> 4;
        int kk = hk & 15;
        const float* src = (qv == 0) ? Wq : (qv == 1 ? Wk : Wv);
        g_Wqkv[idx] = src[((size_t)h * 128 + d) * 16 + kk];
    }
    if (idx < 384) {
        int qv = idx >> 7;
        int hk = idx & 127;
        const float* srcb = (qv == 0) ? bq : (qv == 1 ? bk : bv);
        g_bqkv[idx] = srcb[hk];
    }
}

// --------------------- attention core (dual, 2 queries/thread) --------------
__global__ void __launch_bounds__(256) k_attn(const float* __restrict__ qkvc,
                                              const float* __restrict__ qkvq,
                                              const float* __restrict__ cmask,
                                              const float* __restrict__ qmask,
                                              float* __restrict__ oc,
                                              float* __restrict__ oq) {
    const int KT = 64;
    __shared__ u64 ks[KT][9], vs[KT][9];
    __shared__ float ms[KT];
    int tid = threadIdx.x;
    int bh = blockIdx.y;
    int z = bh >> 3;
    bool isq = z >= kB;
    int b = isq ? z - kB : z;
    int h = bh & 7;
    int L = isq ? kM : kN;
    int i0 = blockIdx.x * 512 + tid;
    int i1 = i0 + 256;
    if (blockIdx.x * 512 >= L) return;
    const float* qkv = isq ? qkvq : qkvc;
    const float* mask = isq ? qmask : cmask;
    float* o = isq ? oq : oc;
    bool a0 = i0 < L, a1 = i1 < L;

    u64 qa[8], qb[8];
#pragma unroll
    for (int c = 0; c < 8; c++) { qa[c] = 0; qb[c] = 0; }
    if (a0) {
        const float* qp = qkv + ((size_t)b * 384 + h * 16) * L + i0;
#pragma unroll
        for (int c = 0; c < 8; c++)
            qa[c] = pk2(qp[(size_t)(2 * c) * L] * 0.25f, qp[(size_t)(2 * c + 1) * L] * 0.25f);
    }
    if (a1) {
        const float* qp = qkv + ((size_t)b * 384 + h * 16) * L + i1;
#pragma unroll
        for (int c = 0; c < 8; c++)
            qb[c] = pk2(qp[(size_t)(2 * c) * L] * 0.25f, qp[(size_t)(2 * c + 1) * L] * 0.25f);
    }
    float mA = -INFINITY, lA = 0.f;
    float mB = -INFINITY, lB = 0.f;
    u64 accA[8] = {0, 0, 0, 0, 0, 0, 0, 0};
    u64 accB[8] = {0, 0, 0, 0, 0, 0, 0, 0};

    for (int j0 = 0; j0 < L; j0 += KT) {
        int cnt = min(KT, L - j0);
        for (int idx = tid; idx < 8 * KT; idx += 256) {
            int c = idx >> 6;
            int t = idx & 63;
            if (t < cnt) {
                const float* kp = qkv + ((size_t)b * 384 + 128 + h * 16 + 2 * c) * L + j0 + t;
                ks[t][c] = pk2(kp[0], kp[(size_t)L]);
                const float* vp = kp + (size_t)128 * L;
                vs[t][c] = pk2(vp[0], vp[(size_t)L]);
            } else {
                ks[t][c] = 0;
                vs[t][c] = 0;
            }
        }
        if (tid < KT) ms[tid] = (tid < cnt) ? mask[(size_t)b * L + j0 + tid] : 0.f;
        __syncthreads();
        for (int g = 0; g < cnt; g += 8) {
            float sA[8], sB[8];
#pragma unroll
            for (int t2 = 0; t2 < 8; t2++) {
                int t = g + t2;
                u64 s2a = 0, s2b = 0;
#pragma unroll
                for (int c = 0; c < 8; c++) {
                    u64 kv = ks[t][c];
                    s2a = fma2(qa[c], kv, s2a);
                    s2b = fma2(qb[c], kv, s2b);
                }
                float lo, hi;
                float pen = 1e30f * (1.f - ms[t]);
                upk2(s2a, lo, hi);
                sA[t2] = lo + hi - pen;
                upk2(s2b, lo, hi);
                sB[t2] = lo + hi - pen;
            }
            float gA = sA[0], gB = sB[0];
#pragma unroll
            for (int t2 = 1; t2 < 8; t2++) {
                gA = fmaxf(gA, sA[t2]);
                gB = fmaxf(gB, sB[t2]);
            }
            float nA = fmaxf(mA, gA), nB = fmaxf(mB, gB);
            float scA = __expf(mA - nA), scB = __expf(mB - nB);
            lA *= scA;
            lB *= scB;
            u64 sa2 = pk2(scA, scA), sb2 = pk2(scB, scB);
#pragma unroll
            for (int c = 0; c < 8; c++) {
                accA[c] = mul2(sa2, accA[c]);
                accB[c] = mul2(sb2, accB[c]);
            }
#pragma unroll
            for (int t2 = 0; t2 < 8; t2++) {
                int t = g + t2;
                float pA = __expf(sA[t2] - nA);
                float pB = __expf(sB[t2] - nB);
                lA += pA;
                lB += pB;
                u64 pa2 = pk2(pA, pA), pb2 = pk2(pB, pB);
#pragma unroll
                for (int c = 0; c < 8; c++) {
                    u64 vv = vs[t][c];
                    accA[c] = fma2(pa2, vv, accA[c]);
                    accB[c] = fma2(pb2, vv, accB[c]);
                }
            }
            mA = nA;
            mB = nB;
        }
        __syncthreads();
    }
    if (a0) {
        float r = 1.f / lA;
        float* op = o + ((size_t)b * 128 + h * 16) * L + i0;
#pragma unroll
        for (int c = 0; c < 8; c++) {
            float lo, hi;
            upk2(accA[c], lo, hi);
            op[(size_t)(2 * c) * L] = lo * r;
            op[(size_t)(2 * c + 1) * L] = hi * r;
        }
    }
    if (a1) {
        float r = 1.f / lB;
        float* op = o + ((size_t)b * 128 + h * 16) * L + i1;
#pragma unroll
        for (int c = 0; c < 8; c++) {
            float lo, hi;
            upk2(accB[c], lo, hi);
            op[(size_t)(2 * c) * L] = lo * r;
            op[(size_t)(2 * c + 1) * L] = hi * r;
        }
    }
}

// ------------------------------ transposes ---------------------------------
__global__ void k_trC(const float* __restrict__ X, float* __restrict__ Y, int L) {
    __shared__ float t[32][33];
    int b = blockIdx.z, d0 = blockIdx.y * 32, l0 = blockIdx.x * 32;
    int tx = threadIdx.x, ty = threadIdx.y;
#pragma unroll
    for (int k = 0; k < 4; k++) {
        int l = l0 + tx;
        t[ty + 8 * k][tx] = (l < L) ? X[((size_t)b * 128 + d0 + ty + 8 * k) * L + l] : 0.f;
    }
    __syncthreads();
#pragma unroll
    for (int k = 0; k < 4; k++) {
        int l = l0 + ty + 8 * k;
        if (l < L) Y[((size_t)b * L + l) * 128 + d0 + tx] = t[tx][ty + 8 * k];
    }
}

__global__ void k_trQ(const float* __restrict__ X, float* __restrict__ Yt,
                      float* __restrict__ Yw, const float* __restrict__ wm) {
    __shared__ float t[32][33];
    int b = blockIdx.z, d0 = blockIdx.y * 32, l0 = blockIdx.x * 32;
    int tx = threadIdx.x, ty = threadIdx.y;
#pragma unroll
    for (int k = 0; k < 4; k++) {
        int l = l0 + tx;
        t[ty + 8 * k][tx] = (l < kM) ? X[((size_t)b * 128 + d0 + ty + 8 * k) * kM + l] : 0.f;
    }
    __syncthreads();
    float w = wm[d0 + tx];
#pragma unroll
    for (int k = 0; k < 4; k++) {
        int l = l0 + ty + 8 * k;
        if (l < kM) {
            float v = t[tx][ty + 8 * k];
            size_t oi = ((size_t)b * kM + l) * 128 + d0 + tx;
            Yt[oi] = v;
            Yw[oi] = v * w;
        }
    }
}

// ------------------------------ CQ attention -------------------------------
__global__ void k_dot(const float* __restrict__ X, const float* __restrict__ w,
                      float* __restrict__ out, int L) {
    int idx = blockIdx.x * blockDim.x + threadIdx.x;
    if (idx >= kB * L) return;
    int b = idx / L;
    int pos = idx % L;
    const float* xp = X + (size_t)b * kD * L + pos;
    float a = 0.f;
#pragma unroll 8
    for (int d = 0; d < kD; d++) a += w[d] * xp[(size_t)d * L];
    out[idx] = a;
}

__global__ void __launch_bounds__(256) k_sgemm(const float* __restrict__ X,
                                               const float* __restrict__ Qw,
                                               const float* __restrict__ cc,
                                               const float* __restrict__ qq,
                                               const float* __restrict__ b0,
                                               float* __restrict__ S) {
    __shared__ float Xs[32][33];
    __shared__ float Ws[32][68];
    int tid = threadIdx.x;
    int l = tid & 31;
    int eg = tid >> 5;
    int l0 = blockIdx.x * 32;
    int b = blockIdx.y;
    u64 acc[4] = {0, 0, 0, 0};

    for (int d0 = 0; d0 < 128; d0 += 32) {
#pragma unroll
        for (int r = 0; r < 4; r++) {
            int idx = tid + r * 256;
            int dd = idx >> 5, ll = idx & 31;
            int lg = l0 + ll;
            Xs[dd][ll] = (lg < kN) ? X[((size_t)b * 128 + d0 + dd) * kN + lg] : 0.f;
        }
#pragma unroll
        for (int r = 0; r < 8; r++) {
            int idx = tid + r * 256;
            int dd = idx >> 6;
            int e = idx & 63;
            Ws[dd][e] = (e < kM) ? Qw[((size_t)b * kM + e) * 128 + d0 + dd] : 0.f;
        }
        __syncthreads();
#pragma unroll
        for (int dd = 0; dd < 32; dd++) {
            float xv = Xs[dd][l];
            u64 xx = pk2(xv, xv);
            const ulonglong2* wr = (const ulonglong2*)&Ws[dd][eg * 8];
            ulonglong2 w0 = wr[0], w1 = wr[1];
            acc[0] = fma2(xx, w0.x, acc[0]);
            acc[1] = fma2(xx, w0.y, acc[1]);
            acc[2] = fma2(xx, w1.x, acc[2]);
            acc[3] = fma2(xx, w1.y, acc[3]);
        }
        __syncthreads();
    }
    int lg = l0 + l;
    if (lg < kN) {
        float base = cc[b * kN + lg] + b0[0];
#pragma unroll
        for (int j = 0; j < 4; j++) {
            float v0, v1;
            upk2(acc[j], v0, v1);
            int e0 = eg * 8 + 2 * j;
            if (e0 < kM) S[((size_t)b * kM + e0) * kN + lg] = v0 + base + qq[b * kM + e0];
            if (e0 + 1 < kM) S[((size_t)b * kM + e0 + 1) * kN + lg] = v1 + base + qq[b * kM + e0 + 1];
        }
    }
}

__global__ void k_smrow(const float* __restrict__ qmask) {
    int idx = blockIdx.x * blockDim.x + threadIdx.x;
    if (idx >= kB * kN) return;
    int b = idx / kN;
    int n = idx % kN;
    float v[kM];
    float mx = -INFINITY;
#pragma unroll
    for (int m = 0; m < kM; m++) {
        v[m] = g_S[((size_t)b * kM + m) * kN + n] - 1e30f * (1.f - qmask[b * kM + m]);
        mx = fmaxf(mx, v[m]);
    }
    float s = 0.f;
#pragma unroll
    for (int m = 0; m < kM; m++) {
        v[m] = __expf(v[m] - mx);
        s += v[m];
    }
    float r = 1.f / s;
#pragma unroll
    for (int m = 0; m < kM; m++) g_Sr[((size_t)b * kM + m) * kN + n] = v[m] * r;
}

__global__ void k_smcol(const float* __restrict__ cmask) {
    int w = (blockIdx.x * blockDim.x + threadIdx.x) >> 5;
    int lane = threadIdx.x & 31;
    if (w >= kB * kM) return;
    int b = w / kM;
    const float* row = g_S + (size_t)w * kN;
    const float* mrow = cmask + (size_t)b * kN;
    float v[13];
#pragma unroll
    for (int k = 0; k < 13; k++) {
        int n = lane + k * 32;
        v[k] = (n < kN) ? row[n] - 1e30f * (1.f - mrow[n]) : -INFINITY;
    }
    float mx = v[0];
#pragma unroll
    for (int k = 1; k < 13; k++) mx = fmaxf(mx, v[k]);
#pragma unroll
    for (int o = 16; o; o >>= 1) mx = fmaxf(mx, __shfl_xor_sync(0xffffffff, mx, o));
    float s = 0.f;
    float e[13];
#pragma unroll
    for (int k = 0; k < 13; k++) {
        int n = lane + k * 32;
        e[k] = (n < kN) ? __expf(v[k] - mx) : 0.f;
        s += e[k];
    }
#pragma unroll
    for (int o = 16; o; o >>= 1) s += __shfl_xor_sync(0xffffffff, s, o);
    float r = 1.f / s;
    float* orow = g_Sc + (size_t)w * kN;
#pragma unroll
    for (int k = 0; k < 13; k++) {
        int n = lane + k * 32;
        if (n < kN) orow[n] = e[k] * r;
    }
}

__global__ void __launch_bounds__(512) k_U(const float* __restrict__ Ct) {
    int b = blockIdx.x;
    int tid = threadIdx.x;
    int d = tid & 127;
    int mq = tid >> 7;
    __shared__ float cts[16][128];
    __shared__ float scs[16][56];
    u64 acc[7] = {0, 0, 0, 0, 0, 0, 0};

    for (int n0 = 0; n0 < kN; n0 += 16) {
#pragma unroll
        for (int r = 0; r < 4; r++) {
            int idx = tid + r * 512;
            int n = idx >> 7, dd = idx & 127;
            cts[n][dd] = Ct[((size_t)b * kN + n0 + n) * 128 + dd];
        }
        for (int idx = tid; idx < 16 * 56; idx += 512) {
            int n = idx & 15;
            int m = idx >> 4;
            scs[n][m] = (m < kM) ? g_Sc[((size_t)b * kM + m) * kN + n0 + n] : 0.f;
        }
        __syncthreads();
#pragma unroll
        for (int n = 0; n < 16; n++) {
            float ct = cts[n][d];
            u64 c2 = pk2(ct, ct);
            const u64* sp = (const u64*)&scs[n][mq * 14];
#pragma unroll
            for (int j = 0; j < 7; j++) acc[j] = fma2(c2, sp[j], acc[j]);
        }
        __syncthreads();
    }
#pragma unroll
    for (int j = 0; j < 7; j++) {
        float v0, v1;
        upk2(acc[j], v0, v1);
        int m = mq * 14 + 2 * j;
        if (m < kM) g_U[((size_t)b * kM + m) * 128 + d] = v0;
        if (m + 1 < kM) g_U[((size_t)b * kM + m + 1) * 128 + d] = v1;
    }
}

__global__ void __launch_bounds__(256) k_out(const float* __restrict__ Ct,
                                             float* __restrict__ out) {
    int b = blockIdx.x / 25;
    int n0 = (blockIdx.x % 25) * 16;
    int tid = threadIdx.x;
    int d = tid & 127;
    int nq = tid >> 7;
    __shared__ float srs[kM][16];
    for (int idx = tid; idx < kM * 16; idx += 256) {
        int m = idx >> 4, nj = idx & 15;
        srs[m][nj] = g_Sr[((size_t)b * kM + m) * kN + n0 + nj];
    }
    __syncthreads();
    u64 a2[4] = {0, 0, 0, 0};
    u64 b2[4] = {0, 0, 0, 0};
    for (int m = 0; m < kM; m++) {
        float qv = g_Qt[((size_t)b * kM + m) * 128 + d];
        float uv = g_U[((size_t)b * kM + m) * 128 + d];
        u64 q2 = pk2(qv, qv), u2 = pk2(uv, uv);
        const u64* sp = (const u64*)&srs[m][nq * 8];
#pragma unroll
        for (int j = 0; j < 4; j++) {
            a2[j] = fma2(sp[j], q2, a2[j]);
            b2[j] = fma2(sp[j], u2, b2[j]);
        }
    }
#pragma unroll
    for (int j = 0; j < 4; j++) {
        float a0, a1, bt0, bt1;
        upk2(a2[j], a0, a1);
        upk2(b2[j], bt0, bt1);
#pragma unroll
        for (int t = 0; t < 2; t++) {
            int n = n0 + nq * 8 + 2 * j + t;
            float a = (t == 0) ? a0 : a1;
            float bt = (t == 0) ? bt0 : bt1;
            float c = Ct[((size_t)b * kN + n) * 128 + d];
            size_t base = ((size_t)b * kN + n) * 512;
            out[base + d] = c;
            out[base + 128 + d] = a;
            out[base + 256 + d] = c * a;
            out[base + 384 + d] = c * bt;
        }
    }
}

// ------------------------------- host side ---------------------------------
static inline int ceil_div(int a, int b) { return (a + b - 1) / b; }

extern "C" void kernel_launch(void* const* d_in, const int* in_sizes, int n_in,
                              void* d_out, int out_size) {
    (void)in_sizes; (void)n_in; (void)out_size;
    const float* ctx   = (const float*)d_in[0];
    const float* qst   = (const float*)d_in[1];
    const float* cmask = (const float*)d_in[2];
    const float* qmask = (const float*)d_in[3];
    const float* ln_g  = (const float*)d_in[4];
    const float* ln_b  = (const float*)d_in[5];
    const float* dww   = (const float*)d_in[6];
    const float* dwb   = (const float*)d_in[7];
    const float* pww   = (const float*)d_in[8];
    const float* pwb   = (const float*)d_in[9];
    const float* Wq    = (const float*)d_in[10];
    const float* bq    = (const float*)d_in[11];
    const float* Wk    = (const float*)d_in[12];
    const float* bk    = (const float*)d_in[13];
    const float* Wv    = (const float*)d_in[14];
    const float* bv    = (const float*)d_in[15];
    const float* Wo    = (const float*)d_in[16];
    const float* bo    = (const float*)d_in[17];
    const float* Wfc   = (const float*)d_in[18];
    const float* bfc   = (const float*)d_in[19];
    const float* cq_wc = (const float*)d_in[20];
    const float* cq_wq = (const float*)d_in[21];
    const float* cq_wm = (const float*)d_in[22];
    const float* cq_b  = (const float*)d_in[23];

    float *pC, *pQ, *pdw, *pQ2, *pqkv, *pqkvq, *pao, *paoq, *pcc, *pqq;
    float *pCt, *pQt, *pQw, *pmu, *pri, *pmu2, *pri2;
    cudaGetSymbolAddress((void**)&pC, g_C);
    cudaGetSymbolAddress((void**)&pQ, g_Q);
    cudaGetSymbolAddress((void**)&pdw, g_dw);
    cudaGetSymbolAddress((void**)&pQ2, g_Q2);
    cudaGetSymbolAddress((void**)&pqkv, g_qkv);
    cudaGetSymbolAddress((void**)&pqkvq, g_qkv_q);
    cudaGetSymbolAddress((void**)&pao, g_ao);
    cudaGetSymbolAddress((void**)&paoq, g_ao_q);
    cudaGetSymbolAddress((void**)&pcc, g_cc);
    cudaGetSymbolAddress((void**)&pqq, g_qq);
    cudaGetSymbolAddress((void**)&pCt, g_Ct);
    cudaGetSymbolAddress((void**)&pQt, g_Qt);
    cudaGetSymbolAddress((void**)&pQw, g_Qw);
    cudaGetSymbolAddress((void**)&pmu, g_mu);
    cudaGetSymbolAddress((void**)&pri, g_ri);
    cudaGetSymbolAddress((void**)&pmu2, g_mu2);
    cudaGetSymbolAddress((void**)&pri2, g_ri2);
    float* pWqkv; cudaGetSymbolAddress((void**)&pWqkv, g_Wqkv);
    float* pbqkv; cudaGetSymbolAddress((void**)&pbqkv, g_bqkv);
    float* pS;    cudaGetSymbolAddress((void**)&pS, g_S);

    k_pe<<<ceil_div(kD * kN, 256), 256>>>();
    k_pack_qkv<<<ceil_div(3 * 128 * 128, 256), 256>>>(Wq, Wk, Wv, bq, bk, bv);

    // PE + LN stats, both sequences, one launch
    k_pe_stats<<<(kB * kN) / 32 + ceil_div(kB * kM, 32), 128>>>(
        ctx, qst, pC, pQ, pmu, pri, pmu2, pri2);

    // Dual-sequence encoder
    int lt = ceil_div(kN, 64);   // 7
    dim3 gz(lt, 1, 2 * kB);
    float* cb_[2] = {pC, pdw};
    float* qb_[2] = {pQ, pQ2};
    for (int i = 0; i < kNC; i++) {
        float* srcC = cb_[i & 1];
        float* dstC = cb_[(i + 1) & 1];
        float* srcQ = qb_[i & 1];
        float* dstQ = qb_[(i + 1) & 1];
        k_cgemm<<<gz, 256>>>(srcC, srcQ, dstC, dstQ,
                             pww + (size_t)i * kD * kD, pwb + (size_t)i * kD,
                             dww + (size_t)i * kD * kKW, dwb + (size_t)i * kD,
                             ln_g, ln_b, pmu, pri, pmu2, pri2);
    }
    k_gemm<false, false, false, true, false><<<dim3(lt, 3, 2 * kB), 256>>>(
        pC, pQ, pWqkv, pbqkv, nullptr, nullptr, pqkv, pqkvq, 384,
        pmu, pri, pmu2, pri2, ln_g, ln_b);
    k_attn<<<dim3(ceil_div(kN, 512), 2 * kB * kH), 256>>>(
        pqkv, pqkvq, cmask, qmask, pao, paoq);
    k_gemm<true, false, true, false, true><<<dim3(lt, 1, 2 * kB), 256>>>(
        pao, paoq, Wo, bo, pC, pQ, pC, pQ, kD,
        pmu, pri, pmu2, pri2, nullptr, nullptr);
    k_gemm<false, false, true, true, false><<<dim3(lt, 1, 2 * kB), 256>>>(
        pC, pQ, Wfc, bfc, pC, pQ, pC, pQ, kD,
        pmu, pri, pmu2, pri2, ln_g, ln_b);

    // --------- context-query attention ---------
    k_dot<<<ceil_div(kB * kN, 256), 256>>>(pC, cq_wc, pcc, kN);
    k_dot<<<ceil_div(kB * kM, 256), 256>>>(pQ, cq_wq, pqq, kM);
    k_trC<<<dim3(13, 4, kB), dim3(32, 8)>>>(pC, pCt, kN);
    k_trQ<<<dim3(2, 4, kB), dim3(32, 8)>>>(pQ, pQt, pQw, cq_wm);
    k_sgemm<<<dim3(13, kB), 256>>>(pC, pQw, pcc, pqq, cq_b, pS);
    k_smrow<<<ceil_div(kB * kN, 256), 256>>>(qmask);
    k_smcol<<<ceil_div(kB * kM * 32, 256), 256>>>(cmask);
    k_U<<<kB, 512>>>(pCt);
    k_out<<<kB * 25, 256>>>(pCt, (float*)d_out);
}

// round 14
// speedup vs baseline: 1.8952x; 1.0374x over previous
#include <cuda_runtime.h>
#include <math.h>

// ---------------------------------------------------------------------------
// QANet forward, fp32 on sm_103a.
// R14: R13 + flattened dual grids with question-first (light-first) block
//      ordering to kill the straggler second wave.
// ---------------------------------------------------------------------------
#define kB 64
#define kD 128
#define kN 400
#define kM 50
#define kH 8
#define kKD 16
#define kNC 4
#define kKW 7
#define kPAD 3
#define kLT 7   // ceil(kN/64)

typedef unsigned long long u64;

__device__ __forceinline__ u64 pk2(float lo, float hi) {
    u64 r; asm("mov.b64 %0,{%1,%2};" : "=l"(r) : "f"(lo), "f"(hi)); return r;
}
__device__ __forceinline__ void upk2(u64 v, float& lo, float& hi) {
    asm("mov.b64 {%0,%1},%2;" : "=f"(lo), "=f"(hi) : "l"(v));
}
__device__ __forceinline__ u64 fma2(u64 a, u64 b, u64 c) {
    u64 d; asm("fma.rn.f32x2 %0,%1,%2,%3;" : "=l"(d) : "l"(a), "l"(b), "l"(c)); return d;
}
__device__ __forceinline__ u64 mul2(u64 a, u64 b) {
    u64 d; asm("mul.rn.f32x2 %0,%1,%2;" : "=l"(d) : "l"(a), "l"(b)); return d;
}

// ------------------------- device scratch (static) -------------------------
__device__ float g_C[kB * kD * kN];
__device__ float g_Q[kB * kD * kM];
__device__ float g_dw[kB * kD * kN];
__device__ float g_Q2[kB * kD * kM];
__device__ float g_qkv[kB * 3 * kD * kN];
__device__ float g_qkv_q[kB * 3 * kD * kM];
__device__ float g_ao[kB * kD * kN];
__device__ float g_ao_q[kB * kD * kM];
__device__ float g_Wqkv[3 * kD * kD];   // [e][d]
__device__ float g_bqkv[3 * kD];
__device__ float g_pe[kD * kN];
__device__ float g_mu[kB * kN];
__device__ float g_ri[kB * kN];
__device__ float g_mu2[kB * kM];
__device__ float g_ri2[kB * kM];
__device__ float g_S[kB * kM * kN];
__device__ float g_Sr[kB * kM * kN];
__device__ float g_Sc[kB * kM * kN];
__device__ float g_U[kB * kM * kD];
__device__ float g_Ct[kB * kN * kD];
__device__ float g_Qt[kB * kM * kD];
__device__ float g_Qw[kB * kM * kD];
__device__ float g_cc[kB * kN];
__device__ float g_qq[kB * kM];

// ------------------------------ PE table ----------------------------------
__global__ void k_pe() {
    int idx = blockIdx.x * blockDim.x + threadIdx.x;
    if (idx >= kD * kN) return;
    int d = idx / kN;
    int l = idx % kN;
    int d0 = d & ~1;
    double f = pow(10000.0, -(double)d0 / (double)kD);
    double a = (double)l * f;
    g_pe[idx] = (d & 1) ? (float)cos(a) : (float)sin(a);
}

// ----------- add PE + compute LN stats, DUAL sequence, one launch ----------
__global__ void __launch_bounds__(128) k_pe_stats(const float* __restrict__ xc,
                                                  const float* __restrict__ xq,
                                                  float* __restrict__ yc,
                                                  float* __restrict__ yq,
                                                  float* __restrict__ muc,
                                                  float* __restrict__ ric,
                                                  float* __restrict__ muq,
                                                  float* __restrict__ riq) {
    const int QBLK = (kB * kM) / 32;  // 100 (question first)
    int blk = blockIdx.x;
    bool isq = blk < QBLK;
    int L = isq ? kM : kN;
    const float* x = isq ? xq : xc;
    float* y = isq ? yq : yc;
    float* omu = isq ? muq : muc;
    float* ori = isq ? riq : ric;
    int pos0 = (isq ? blk : blk - QBLK) * 32;

    int tid = threadIdx.x;
    int lsub = tid & 31;
    int grp = tid >> 5;
    int pos = pos0 + lsub;
    int P = kB * L;
    bool ok = pos < P;
    int b = ok ? pos / L : 0;
    int l = ok ? pos % L : 0;

    float s = 0.f, sq = 0.f;
    if (ok) {
        const float* xp = x + ((size_t)b * kD + grp * 32) * L + l;
        float* yp = y + ((size_t)b * kD + grp * 32) * L + l;
#pragma unroll
        for (int k = 0; k < 32; k++) {
            int d = grp * 32 + k;
            float v = xp[(size_t)k * L] + g_pe[d * kN + l];
            yp[(size_t)k * L] = v;
            s += v;
            sq += v * v;
        }
    }
    __shared__ float ss[4][32], sb[4][32];
    ss[grp][lsub] = s;
    sb[grp][lsub] = sq;
    __syncthreads();
    if (grp == 0 && ok) {
        float ts = ss[0][lsub] + ss[1][lsub] + ss[2][lsub] + ss[3][lsub];
        float tq = sb[0][lsub] + sb[1][lsub] + sb[2][lsub] + sb[3][lsub];
        float mu = ts * (1.f / 128.f);
        float var = (tq - 128.f * mu * mu) * (1.f / 127.f);
        var = fmaxf(var, 0.f);
        omu[pos] = mu;
        ori[pos] = 1.f / (sqrtf(var) + 1e-6f);
    }
}

// ---------------- fused LN + depthwise conv + pointwise GEMM (dual) ---------
// Flattened grid.x = 64 (question, IDs 0..63) + 448 (context).
__global__ void __launch_bounds__(256, 3) k_cgemm(const float* __restrict__ Xc,
                                                  const float* __restrict__ Xq,
                                                  float* __restrict__ outc,
                                                  float* __restrict__ outq,
                                                  const float* __restrict__ Wpw,
                                                  const float* __restrict__ pwb,
                                                  const float* __restrict__ cw,
                                                  const float* __restrict__ cb,
                                                  const float* __restrict__ gamma,
                                                  const float* __restrict__ beta,
                                                  float* __restrict__ muc,
                                                  float* __restrict__ ric,
                                                  float* __restrict__ muq,
                                                  float* __restrict__ riq) {
    int id = blockIdx.x;
    bool isq = id < kB;
    int b, l0, L;
    if (isq) { b = id; l0 = 0; L = kM; }
    else { int cid = id - kB; b = cid / kLT; l0 = (cid % kLT) * 64; L = kN; }
    const float* X = isq ? Xq : Xc;
    float* out = isq ? outq : outc;
    float* muP = isq ? muq : muc;
    float* riP = isq ? riq : ric;

    __shared__ __align__(16) float Xl[32][72];
    __shared__ __align__(16) float Xs[32][68];
    __shared__ __align__(16) float Ws[32][132];
    __shared__ float mus[72], ris[72];
    __shared__ float gs[128], bs2[128];
    __shared__ float cws[128][8];

    int tid = threadIdx.x;
    int eq = tid >> 5;
    int lq = tid & 31;

    if (tid < 70) {
        int gl = l0 + tid - 3;
        bool in = (gl >= 0 && gl < L);
        mus[tid] = in ? muP[(size_t)b * L + gl] : 0.f;
        ris[tid] = in ? riP[(size_t)b * L + gl] : 0.f;
    }
    if (tid < 128) {
        gs[tid] = gamma[tid];
        bs2[tid] = beta[tid];
#pragma unroll
        for (int k = 0; k < 7; k++) cws[tid][k] = cw[tid * 7 + k];
        cws[tid][7] = cb[tid];
    }
    __syncthreads();

    float acc[32];
#pragma unroll
    for (int j = 0; j < 32; j++) acc[j] = 0.f;

    for (int k = 0; k < 4; k++) {
        int d0 = k * 32;
#pragma unroll
        for (int r = 0; r < 9; r++) {
            int idx = tid + r * 256;
            if (idx < 2240) {
                int dd = idx / 70;
                int ll = idx - dd * 70;
                int gl = l0 + ll - 3;
                float v = 0.f;
                if (gl >= 0 && gl < L) {
                    float xv = X[((size_t)b * 128 + d0 + dd) * L + gl];
                    v = gs[d0 + dd] * (xv - mus[ll]) * ris[ll] + bs2[d0 + dd];
                }
                Xl[dd][ll] = v;
            }
        }
#pragma unroll
        for (int r = 0; r < 16; r++) {
            int idx = tid + r * 256;
            int e = idx >> 5;
            int dd = idx & 31;
            Ws[dd][e] = Wpw[(size_t)e * 128 + d0 + dd];
        }
        __syncthreads();
#pragma unroll
        for (int r = 0; r < 8; r++) {
            int idx = tid + r * 256;
            int dd = idx >> 6;
            int ll = idx & 63;
            int d = d0 + dd;
            float a = cws[d][7];
#pragma unroll
            for (int kk = 0; kk < 7; kk++) a += cws[d][kk] * Xl[dd][ll + kk];
            Xs[dd][ll] = a;
        }
        __syncthreads();
#pragma unroll
        for (int dd = 0; dd < 32; dd++) {
            float2 xv = *(const float2*)&Xs[dd][lq * 2];
            const float4* wp = (const float4*)&Ws[dd][eq * 16];
            float4 w0 = wp[0], w1 = wp[1], w2 = wp[2], w3 = wp[3];
            acc[0]  += w0.x * xv.x;  acc[1]  += w0.x * xv.y;
            acc[2]  += w0.y * xv.x;  acc[3]  += w0.y * xv.y;
            acc[4]  += w0.z * xv.x;  acc[5]  += w0.z * xv.y;
            acc[6]  += w0.w * xv.x;  acc[7]  += w0.w * xv.y;
            acc[8]  += w1.x * xv.x;  acc[9]  += w1.x * xv.y;
            acc[10] += w1.y * xv.x;  acc[11] += w1.y * xv.y;
            acc[12] += w1.z * xv.x;  acc[13] += w1.z * xv.y;
            acc[14] += w1.w * xv.x;  acc[15] += w1.w * xv.y;
            acc[16] += w2.x * xv.x;  acc[17] += w2.x * xv.y;
            acc[18] += w2.y * xv.x;  acc[19] += w2.y * xv.y;
            acc[20] += w2.z * xv.x;  acc[21] += w2.z * xv.y;
            acc[22] += w2.w * xv.x;  acc[23] += w2.w * xv.y;
            acc[24] += w3.x * xv.x;  acc[25] += w3.x * xv.y;
            acc[26] += w3.y * xv.x;  acc[27] += w3.y * xv.y;
            acc[28] += w3.z * xv.x;  acc[29] += w3.z * xv.y;
            acc[30] += w3.w * xv.x;  acc[31] += w3.w * xv.y;
        }
        __syncthreads();
    }

    float sum_l[2] = {0.f, 0.f};
    float sq_l[2] = {0.f, 0.f};
#pragma unroll
    for (int p = 0; p < 16; p++) {
        int e0 = eq * 16 + p;
        float bv = pwb[e0];
#pragma unroll
        for (int q = 0; q < 2; q++) {
            float v = fmaxf(acc[p * 2 + q] + bv, 0.f);
            int lg = l0 + lq * 2 + q;
            if (lg < L) {
                size_t oi = ((size_t)b * 128 + e0) * L + lg;
                v += X[oi];
                out[oi] = v;
            }
            sum_l[q] += v;
            sq_l[q] += v * v;
        }
    }
    float* red = &Ws[0][0];
    red[eq * 64 + lq * 2 + 0] = sum_l[0];
    red[eq * 64 + lq * 2 + 1] = sum_l[1];
    red[512 + eq * 64 + lq * 2 + 0] = sq_l[0];
    red[512 + eq * 64 + lq * 2 + 1] = sq_l[1];
    __syncthreads();
    if (tid < 64) {
        int lg = l0 + tid;
        if (lg < L) {
            float s = 0.f, ss = 0.f;
#pragma unroll
            for (int g = 0; g < 8; g++) {
                s += red[g * 64 + tid];
                ss += red[512 + g * 64 + tid];
            }
            float muv = s * (1.f / 128.f);
            float var = (ss - 128.f * muv * muv) * (1.f / 127.f);
            var = fmaxf(var, 0.f);
            muP[(size_t)b * L + lg] = muv;
            riP[(size_t)b * L + lg] = 1.f / (sqrtf(var) + 1e-6f);
        }
    }
}

// ------------------------------- GEMM (dual) --------------------------------
// Flattened grid.x (question first), grid.y = e-tiles.
template <bool TR, bool RELU, bool RES, bool LNX, bool STATS>
__global__ void __launch_bounds__(256, 3) k_gemm(const float* __restrict__ Xc,
                                                 const float* __restrict__ Xq,
                                                 const float* __restrict__ W,
                                                 const float* __restrict__ bias,
                                                 const float* resc, const float* resq,
                                                 float* outc, float* outq,
                                                 int Etot,
                                                 float* __restrict__ muc,
                                                 float* __restrict__ ric,
                                                 float* __restrict__ muq,
                                                 float* __restrict__ riq,
                                                 const float* __restrict__ gamma,
                                                 const float* __restrict__ beta) {
    int id = blockIdx.x;
    bool isq = id < kB;
    int b, l0, L;
    if (isq) { b = id; l0 = 0; L = kM; }
    else { int cid = id - kB; b = cid / kLT; l0 = (cid % kLT) * 64; L = kN; }
    const float* X = isq ? Xq : Xc;
    const float* res = isq ? resq : resc;
    float* out = isq ? outq : outc;
    float* muP = isq ? muq : muc;
    float* riP = isq ? riq : ric;

    __shared__ __align__(16) float Xs[32][68];
    __shared__ __align__(16) float Ws[32][132];
    __shared__ float mus[64], ris[64];
    __shared__ float gs[128], bs2[128];

    int tid = threadIdx.x;
    int eq = tid >> 5;
    int lq = tid & 31;
    int et = blockIdx.y * 128;

    if (LNX) {
        if (tid < 64) {
            int p = l0 + tid;
            mus[tid] = (p < L) ? muP[(size_t)b * L + p] : 0.f;
            ris[tid] = (p < L) ? riP[(size_t)b * L + p] : 0.f;
        }
        if (tid < 128) {
            gs[tid] = gamma[tid];
            bs2[tid] = beta[tid];
        }
        __syncthreads();
    }

    float acc[32];
#pragma unroll
    for (int j = 0; j < 32; j++) acc[j] = 0.f;

    for (int k = 0; k < 4; k++) {
        int d0 = k * 32;
#pragma unroll
        for (int r = 0; r < 8; r++) {
            int idx = tid + r * 256;
            int dd = idx >> 6;
            int ll = idx & 63;
            int lg = l0 + ll;
            float v = 0.f;
            if (lg < L) {
                v = X[((size_t)b * 128 + d0 + dd) * L + lg];
                if (LNX) v = gs[d0 + dd] * (v - mus[ll]) * ris[ll] + bs2[d0 + dd];
            }
            Xs[dd][ll] = v;
        }
#pragma unroll
        for (int r = 0; r < 16; r++) {
            int idx = tid + r * 256;
            if (TR) {
                int dd = idx >> 7;
                int e = idx & 127;
                Ws[dd][e] = W[(size_t)(d0 + dd) * Etot + et + e];
            } else {
                int e = idx >> 5;
                int dd = idx & 31;
                Ws[dd][e] = W[(size_t)(et + e) * 128 + d0 + dd];
            }
        }
        __syncthreads();
#pragma unroll
        for (int dd = 0; dd < 32; dd++) {
            float2 xv = *(const float2*)&Xs[dd][lq * 2];
            const float4* wp = (const float4*)&Ws[dd][eq * 16];
            float4 w0 = wp[0], w1 = wp[1], w2 = wp[2], w3 = wp[3];
            acc[0]  += w0.x * xv.x;  acc[1]  += w0.x * xv.y;
            acc[2]  += w0.y * xv.x;  acc[3]  += w0.y * xv.y;
            acc[4]  += w0.z * xv.x;  acc[5]  += w0.z * xv.y;
            acc[6]  += w0.w * xv.x;  acc[7]  += w0.w * xv.y;
            acc[8]  += w1.x * xv.x;  acc[9]  += w1.x * xv.y;
            acc[10] += w1.y * xv.x;  acc[11] += w1.y * xv.y;
            acc[12] += w1.z * xv.x;  acc[13] += w1.z * xv.y;
            acc[14] += w1.w * xv.x;  acc[15] += w1.w * xv.y;
            acc[16] += w2.x * xv.x;  acc[17] += w2.x * xv.y;
            acc[18] += w2.y * xv.x;  acc[19] += w2.y * xv.y;
            acc[20] += w2.z * xv.x;  acc[21] += w2.z * xv.y;
            acc[22] += w2.w * xv.x;  acc[23] += w2.w * xv.y;
            acc[24] += w3.x * xv.x;  acc[25] += w3.x * xv.y;
            acc[26] += w3.y * xv.x;  acc[27] += w3.y * xv.y;
            acc[28] += w3.z * xv.x;  acc[29] += w3.z * xv.y;
            acc[30] += w3.w * xv.x;  acc[31] += w3.w * xv.y;
        }
        __syncthreads();
    }

    float sum_l[2] = {0.f, 0.f};
    float sq_l[2] = {0.f, 0.f};
#pragma unroll
    for (int p = 0; p < 16; p++) {
        int e0 = et + eq * 16 + p;
        float bv = bias[e0];
#pragma unroll
        for (int q = 0; q < 2; q++) {
            float v = acc[p * 2 + q] + bv;
            if (RELU) v = fmaxf(v, 0.f);
            int lg = l0 + lq * 2 + q;
            if (lg < L) {
                size_t oi = ((size_t)b * Etot + e0) * L + lg;
                if (RES) v += res[oi];
                out[oi] = v;
            }
            if (STATS) {
                sum_l[q] += v;
                sq_l[q] += v * v;
            }
        }
    }
    if (STATS) {
        float* red = &Ws[0][0];
        red[eq * 64 + lq * 2 + 0] = sum_l[0];
        red[eq * 64 + lq * 2 + 1] = sum_l[1];
        red[512 + eq * 64 + lq * 2 + 0] = sq_l[0];
        red[512 + eq * 64 + lq * 2 + 1] = sq_l[1];
        __syncthreads();
        if (tid < 64) {
            int lg = l0 + tid;
            if (lg < L) {
                float s = 0.f, ss = 0.f;
#pragma unroll
                for (int g = 0; g < 8; g++) {
                    s += red[g * 64 + tid];
                    ss += red[512 + g * 64 + tid];
                }
                float muv = s * (1.f / 128.f);
                float var = (ss - 128.f * muv * muv) * (1.f / 127.f);
                var = fmaxf(var, 0.f);
                muP[(size_t)b * L + lg] = muv;
                riP[(size_t)b * L + lg] = 1.f / (sqrtf(var) + 1e-6f);
            }
        }
    }
}

// ----------------------------- QKV packing ---------------------------------
__global__ void k_pack_qkv(const float* __restrict__ Wq, const float* __restrict__ Wk,
                           const float* __restrict__ Wv, const float* __restrict__ bq,
                           const float* __restrict__ bk, const float* __restrict__ bv) {
    int idx = blockIdx.x * blockDim.x + threadIdx.x;
    if (idx < 3 * 128 * 128) {
        int e = idx >> 7;
        int d = idx & 127;
        int qv = e >> 7;
        int hk = e & 127;
        int h = hk >> 4;
        int kk = hk & 15;
        const float* src = (qv == 0) ? Wq : (qv == 1 ? Wk : Wv);
        g_Wqkv[idx] = src[((size_t)h * 128 + d) * 16 + kk];
    }
    if (idx < 384) {
        int qv = idx >> 7;
        int hk = idx & 127;
        const float* srcb = (qv == 0) ? bq : (qv == 1 ? bk : bv);
        g_bqkv[idx] = srcb[hk];
    }
}

// --------------------- attention core (dual, 2 queries/thread) --------------
// Question bh-indices first (light-first scheduling).
__global__ void __launch_bounds__(256) k_attn(const float* __restrict__ qkvc,
                                              const float* __restrict__ qkvq,
                                              const float* __restrict__ cmask,
                                              const float* __restrict__ qmask,
                                              float* __restrict__ oc,
                                              float* __restrict__ oq) {
    const int KT = 64;
    __shared__ u64 ks[KT][9], vs[KT][9];
    __shared__ float ms[KT];
    int tid = threadIdx.x;
    int bh = blockIdx.y;
    int z = bh >> 3;
    bool isq = z < kB;   // question first
    int b = isq ? z : z - kB;
    int h = bh & 7;
    int L = isq ? kM : kN;
    int i0 = blockIdx.x * 512 + tid;
    int i1 = i0 + 256;
    if (blockIdx.x * 512 >= L) return;
    const float* qkv = isq ? qkvq : qkvc;
    const float* mask = isq ? qmask : cmask;
    float* o = isq ? oq : oc;
    bool a0 = i0 < L, a1 = i1 < L;

    u64 qa[8], qb[8];
#pragma unroll
    for (int c = 0; c < 8; c++) { qa[c] = 0; qb[c] = 0; }
    if (a0) {
        const float* qp = qkv + ((size_t)b * 384 + h * 16) * L + i0;
#pragma unroll
        for (int c = 0; c < 8; c++)
            qa[c] = pk2(qp[(size_t)(2 * c) * L] * 0.25f, qp[(size_t)(2 * c + 1) * L] * 0.25f);
    }
    if (a1) {
        const float* qp = qkv + ((size_t)b * 384 + h * 16) * L + i1;
#pragma unroll
        for (int c = 0; c < 8; c++)
            qb[c] = pk2(qp[(size_t)(2 * c) * L] * 0.25f, qp[(size_t)(2 * c + 1) * L] * 0.25f);
    }
    float mA = -INFINITY, lA = 0.f;
    float mB = -INFINITY, lB = 0.f;
    u64 accA[8] = {0, 0, 0, 0, 0, 0, 0, 0};
    u64 accB[8] = {0, 0, 0, 0, 0, 0, 0, 0};

    for (int j0 = 0; j0 < L; j0 += KT) {
        int cnt = min(KT, L - j0);
        for (int idx = tid; idx < 8 * KT; idx += 256) {
            int c = idx >> 6;
            int t = idx & 63;
            if (t < cnt) {
                const float* kp = qkv + ((size_t)b * 384 + 128 + h * 16 + 2 * c) * L + j0 + t;
                ks[t][c] = pk2(kp[0], kp[(size_t)L]);
                const float* vp = kp + (size_t)128 * L;
                vs[t][c] = pk2(vp[0], vp[(size_t)L]);
            } else {
                ks[t][c] = 0;
                vs[t][c] = 0;
            }
        }
        if (tid < KT) ms[tid] = (tid < cnt) ? mask[(size_t)b * L + j0 + tid] : 0.f;
        __syncthreads();
        for (int g = 0; g < cnt; g += 8) {
            float sA[8], sB[8];
#pragma unroll
            for (int t2 = 0; t2 < 8; t2++) {
                int t = g + t2;
                u64 s2a = 0, s2b = 0;
#pragma unroll
                for (int c = 0; c < 8; c++) {
                    u64 kv = ks[t][c];
                    s2a = fma2(qa[c], kv, s2a);
                    s2b = fma2(qb[c], kv, s2b);
                }
                float lo, hi;
                float pen = 1e30f * (1.f - ms[t]);
                upk2(s2a, lo, hi);
                sA[t2] = lo + hi - pen;
                upk2(s2b, lo, hi);
                sB[t2] = lo + hi - pen;
            }
            float gA = sA[0], gB = sB[0];
#pragma unroll
            for (int t2 = 1; t2 < 8; t2++) {
                gA = fmaxf(gA, sA[t2]);
                gB = fmaxf(gB, sB[t2]);
            }
            float nA = fmaxf(mA, gA), nB = fmaxf(mB, gB);
            float scA = __expf(mA - nA), scB = __expf(mB - nB);
            lA *= scA;
            lB *= scB;
            u64 sa2 = pk2(scA, scA), sb2 = pk2(scB, scB);
#pragma unroll
            for (int c = 0; c < 8; c++) {
                accA[c] = mul2(sa2, accA[c]);
                accB[c] = mul2(sb2, accB[c]);
            }
#pragma unroll
            for (int t2 = 0; t2 < 8; t2++) {
                int t = g + t2;
                float pA = __expf(sA[t2] - nA);
                float pB = __expf(sB[t2] - nB);
                lA += pA;
                lB += pB;
                u64 pa2 = pk2(pA, pA), pb2 = pk2(pB, pB);
#pragma unroll
                for (int c = 0; c < 8; c++) {
                    u64 vv = vs[t][c];
                    accA[c] = fma2(pa2, vv, accA[c]);
                    accB[c] = fma2(pb2, vv, accB[c]);
                }
            }
            mA = nA;
            mB = nB;
        }
        __syncthreads();
    }
    if (a0) {
        float r = 1.f / lA;
        float* op = o + ((size_t)b * 128 + h * 16) * L + i0;
#pragma unroll
        for (int c = 0; c < 8; c++) {
            float lo, hi;
            upk2(accA[c], lo, hi);
            op[(size_t)(2 * c) * L] = lo * r;
            op[(size_t)(2 * c + 1) * L] = hi * r;
        }
    }
    if (a1) {
        float r = 1.f / lB;
        float* op = o + ((size_t)b * 128 + h * 16) * L + i1;
#pragma unroll
        for (int c = 0; c < 8; c++) {
            float lo, hi;
            upk2(accB[c], lo, hi);
            op[(size_t)(2 * c) * L] = lo * r;
            op[(size_t)(2 * c + 1) * L] = hi * r;
        }
    }
}

// ------------------------------ transposes ---------------------------------
__global__ void k_trC(const float* __restrict__ X, float* __restrict__ Y, int L) {
    __shared__ float t[32][33];
    int b = blockIdx.z, d0 = blockIdx.y * 32, l0 = blockIdx.x * 32;
    int tx = threadIdx.x, ty = threadIdx.y;
#pragma unroll
    for (int k = 0; k < 4; k++) {
        int l = l0 + tx;
        t[ty + 8 * k][tx] = (l < L) ? X[((size_t)b * 128 + d0 + ty + 8 * k) * L + l] : 0.f;
    }
    __syncthreads();
#pragma unroll
    for (int k = 0; k < 4; k++) {
        int l = l0 + ty + 8 * k;
        if (l < L) Y[((size_t)b * L + l) * 128 + d0 + tx] = t[tx][ty + 8 * k];
    }
}

__global__ void k_trQ(const float* __restrict__ X, float* __restrict__ Yt,
                      float* __restrict__ Yw, const float* __restrict__ wm) {
    __shared__ float t[32][33];
    int b = blockIdx.z, d0 = blockIdx.y * 32, l0 = blockIdx.x * 32;
    int tx = threadIdx.x, ty = threadIdx.y;
#pragma unroll
    for (int k = 0; k < 4; k++) {
        int l = l0 + tx;
        t[ty + 8 * k][tx] = (l < kM) ? X[((size_t)b * 128 + d0 + ty + 8 * k) * kM + l] : 0.f;
    }
    __syncthreads();
    float w = wm[d0 + tx];
#pragma unroll
    for (int k = 0; k < 4; k++) {
        int l = l0 + ty + 8 * k;
        if (l < kM) {
            float v = t[tx][ty + 8 * k];
            size_t oi = ((size_t)b * kM + l) * 128 + d0 + tx;
            Yt[oi] = v;
            Yw[oi] = v * w;
        }
    }
}

// ------------------------------ CQ attention -------------------------------
__global__ void k_dot(const float* __restrict__ X, const float* __restrict__ w,
                      float* __restrict__ out, int L) {
    int idx = blockIdx.x * blockDim.x + threadIdx.x;
    if (idx >= kB * L) return;
    int b = idx / L;
    int pos = idx % L;
    const float* xp = X + (size_t)b * kD * L + pos;
    float a = 0.f;
#pragma unroll 8
    for (int d = 0; d < kD; d++) a += w[d] * xp[(size_t)d * L];
    out[idx] = a;
}

__global__ void __launch_bounds__(256) k_sgemm(const float* __restrict__ X,
                                               const float* __restrict__ Qw,
                                               const float* __restrict__ cc,
                                               const float* __restrict__ qq,
                                               const float* __restrict__ b0,
                                               float* __restrict__ S) {
    __shared__ float Xs[32][33];
    __shared__ float Ws[32][68];
    int tid = threadIdx.x;
    int l = tid & 31;
    int eg = tid >> 5;
    int l0 = blockIdx.x * 32;
    int b = blockIdx.y;
    u64 acc[4] = {0, 0, 0, 0};

    for (int d0 = 0; d0 < 128; d0 += 32) {
#pragma unroll
        for (int r = 0; r < 4; r++) {
            int idx = tid + r * 256;
            int dd = idx >> 5, ll = idx & 31;
            int lg = l0 + ll;
            Xs[dd][ll] = (lg < kN) ? X[((size_t)b * 128 + d0 + dd) * kN + lg] : 0.f;
        }
#pragma unroll
        for (int r = 0; r < 8; r++) {
            int idx = tid + r * 256;
            int dd = idx >> 6;
            int e = idx & 63;
            Ws[dd][e] = (e < kM) ? Qw[((size_t)b * kM + e) * 128 + d0 + dd] : 0.f;
        }
        __syncthreads();
#pragma unroll
        for (int dd = 0; dd < 32; dd++) {
            float xv = Xs[dd][l];
            u64 xx = pk2(xv, xv);
            const ulonglong2* wr = (const ulonglong2*)&Ws[dd][eg * 8];
            ulonglong2 w0 = wr[0], w1 = wr[1];
            acc[0] = fma2(xx, w0.x, acc[0]);
            acc[1] = fma2(xx, w0.y, acc[1]);
            acc[2] = fma2(xx, w1.x, acc[2]);
            acc[3] = fma2(xx, w1.y, acc[3]);
        }
        __syncthreads();
    }
    int lg = l0 + l;
    if (lg < kN) {
        float base = cc[b * kN + lg] + b0[0];
#pragma unroll
        for (int j = 0; j < 4; j++) {
            float v0, v1;
            upk2(acc[j], v0, v1);
            int e0 = eg * 8 + 2 * j;
            if (e0 < kM) S[((size_t)b * kM + e0) * kN + lg] = v0 + base + qq[b * kM + e0];
            if (e0 + 1 < kM) S[((size_t)b * kM + e0 + 1) * kN + lg] = v1 + base + qq[b * kM + e0 + 1];
        }
    }
}

__global__ void k_smrow(const float* __restrict__ qmask) {
    int idx = blockIdx.x * blockDim.x + threadIdx.x;
    if (idx >= kB * kN) return;
    int b = idx / kN;
    int n = idx % kN;
    float v[kM];
    float mx = -INFINITY;
#pragma unroll
    for (int m = 0; m < kM; m++) {
        v[m] = g_S[((size_t)b * kM + m) * kN + n] - 1e30f * (1.f - qmask[b * kM + m]);
        mx = fmaxf(mx, v[m]);
    }
    float s = 0.f;
#pragma unroll
    for (int m = 0; m < kM; m++) {
        v[m] = __expf(v[m] - mx);
        s += v[m];
    }
    float r = 1.f / s;
#pragma unroll
    for (int m = 0; m < kM; m++) g_Sr[((size_t)b * kM + m) * kN + n] = v[m] * r;
}

__global__ void k_smcol(const float* __restrict__ cmask) {
    int w = (blockIdx.x * blockDim.x + threadIdx.x) >> 5;
    int lane = threadIdx.x & 31;
    if (w >= kB * kM) return;
    int b = w / kM;
    const float* row = g_S + (size_t)w * kN;
    const float* mrow = cmask + (size_t)b * kN;
    float v[13];
#pragma unroll
    for (int k = 0; k < 13; k++) {
        int n = lane + k * 32;
        v[k] = (n < kN) ? row[n] - 1e30f * (1.f - mrow[n]) : -INFINITY;
    }
    float mx = v[0];
#pragma unroll
    for (int k = 1; k < 13; k++) mx = fmaxf(mx, v[k]);
#pragma unroll
    for (int o = 16; o; o >>= 1) mx = fmaxf(mx, __shfl_xor_sync(0xffffffff, mx, o));
    float s = 0.f;
    float e[13];
#pragma unroll
    for (int k = 0; k < 13; k++) {
        int n = lane + k * 32;
        e[k] = (n < kN) ? __expf(v[k] - mx) : 0.f;
        s += e[k];
    }
#pragma unroll
    for (int o = 16; o; o >>= 1) s += __shfl_xor_sync(0xffffffff, s, o);
    float r = 1.f / s;
    float* orow = g_Sc + (size_t)w * kN;
#pragma unroll
    for (int k = 0; k < 13; k++) {
        int n = lane + k * 32;
        if (n < kN) orow[n] = e[k] * r;
    }
}

__global__ void __launch_bounds__(512) k_U(const float* __restrict__ Ct) {
    int b = blockIdx.x;
    int tid = threadIdx.x;
    int d = tid & 127;
    int mq = tid >> 7;
    __shared__ float cts[16][128];
    __shared__ float scs[16][56];
    u64 acc[7] = {0, 0, 0, 0, 0, 0, 0};

    for (int n0 = 0; n0 < kN; n0 += 16) {
#pragma unroll
        for (int r = 0; r < 4; r++) {
            int idx = tid + r * 512;
            int n = idx >> 7, dd = idx & 127;
            cts[n][dd] = Ct[((size_t)b * kN + n0 + n) * 128 + dd];
        }
        for (int idx = tid; idx < 16 * 56; idx += 512) {
            int n = idx & 15;
            int m = idx >> 4;
            scs[n][m] = (m < kM) ? g_Sc[((size_t)b * kM + m) * kN + n0 + n] : 0.f;
        }
        __syncthreads();
#pragma unroll
        for (int n = 0; n < 16; n++) {
            float ct = cts[n][d];
            u64 c2 = pk2(ct, ct);
            const u64* sp = (const u64*)&scs[n][mq * 14];
#pragma unroll
            for (int j = 0; j < 7; j++) acc[j] = fma2(c2, sp[j], acc[j]);
        }
        __syncthreads();
    }
#pragma unroll
    for (int j = 0; j < 7; j++) {
        float v0, v1;
        upk2(acc[j], v0, v1);
        int m = mq * 14 + 2 * j;
        if (m < kM) g_U[((size_t)b * kM + m) * 128 + d] = v0;
        if (m + 1 < kM) g_U[((size_t)b * kM + m + 1) * 128 + d] = v1;
    }
}

__global__ void __launch_bounds__(256) k_out(const float* __restrict__ Ct,
                                             float* __restrict__ out) {
    int b = blockIdx.x / 25;
    int n0 = (blockIdx.x % 25) * 16;
    int tid = threadIdx.x;
    int d = tid & 127;
    int nq = tid >> 7;
    __shared__ float srs[kM][16];
    for (int idx = tid; idx < kM * 16; idx += 256) {
        int m = idx >> 4, nj = idx & 15;
        srs[m][nj] = g_Sr[((size_t)b * kM + m) * kN + n0 + nj];
    }
    __syncthreads();
    u64 a2[4] = {0, 0, 0, 0};
    u64 b2[4] = {0, 0, 0, 0};
    for (int m = 0; m < kM; m++) {
        float qv = g_Qt[((size_t)b * kM + m) * 128 + d];
        float uv = g_U[((size_t)b * kM + m) * 128 + d];
        u64 q2 = pk2(qv, qv), u2 = pk2(uv, uv);
        const u64* sp = (const u64*)&srs[m][nq * 8];
#pragma unroll
        for (int j = 0; j < 4; j++) {
            a2[j] = fma2(sp[j], q2, a2[j]);
            b2[j] = fma2(sp[j], u2, b2[j]);
        }
    }
#pragma unroll
    for (int j = 0; j < 4; j++) {
        float a0, a1, bt0, bt1;
        upk2(a2[j], a0, a1);
        upk2(b2[j], bt0, bt1);
#pragma unroll
        for (int t = 0; t < 2; t++) {
            int n = n0 + nq * 8 + 2 * j + t;
            float a = (t == 0) ? a0 : a1;
            float bt = (t == 0) ? bt0 : bt1;
            float c = Ct[((size_t)b * kN + n) * 128 + d];
            size_t base = ((size_t)b * kN + n) * 512;
            out[base + d] = c;
            out[base + 128 + d] = a;
            out[base + 256 + d] = c * a;
            out[base + 384 + d] = c * bt;
        }
    }
}

// ------------------------------- host side ---------------------------------
static inline int ceil_div(int a, int b) { return (a + b - 1) / b; }

extern "C" void kernel_launch(void* const* d_in, const int* in_sizes, int n_in,
                              void* d_out, int out_size) {
    (void)in_sizes; (void)n_in; (void)out_size;
    const float* ctx   = (const float*)d_in[0];
    const float* qst   = (const float*)d_in[1];
    const float* cmask = (const float*)d_in[2];
    const float* qmask = (const float*)d_in[3];
    const float* ln_g  = (const float*)d_in[4];
    const float* ln_b  = (const float*)d_in[5];
    const float* dww   = (const float*)d_in[6];
    const float* dwb   = (const float*)d_in[7];
    const float* pww   = (const float*)d_in[8];
    const float* pwb   = (const float*)d_in[9];
    const float* Wq    = (const float*)d_in[10];
    const float* bq    = (const float*)d_in[11];
    const float* Wk    = (const float*)d_in[12];
    const float* bk    = (const float*)d_in[13];
    const float* Wv    = (const float*)d_in[14];
    const float* bv    = (const float*)d_in[15];
    const float* Wo    = (const float*)d_in[16];
    const float* bo    = (const float*)d_in[17];
    const float* Wfc   = (const float*)d_in[18];
    const float* bfc   = (const float*)d_in[19];
    const float* cq_wc = (const float*)d_in[20];
    const float* cq_wq = (const float*)d_in[21];
    const float* cq_wm = (const float*)d_in[22];
    const float* cq_b  = (const float*)d_in[23];

    float *pC, *pQ, *pdw, *pQ2, *pqkv, *pqkvq, *pao, *paoq, *pcc, *pqq;
    float *pCt, *pQt, *pQw, *pmu, *pri, *pmu2, *pri2;
    cudaGetSymbolAddress((void**)&pC, g_C);
    cudaGetSymbolAddress((void**)&pQ, g_Q);
    cudaGetSymbolAddress((void**)&pdw, g_dw);
    cudaGetSymbolAddress((void**)&pQ2, g_Q2);
    cudaGetSymbolAddress((void**)&pqkv, g_qkv);
    cudaGetSymbolAddress((void**)&pqkvq, g_qkv_q);
    cudaGetSymbolAddress((void**)&pao, g_ao);
    cudaGetSymbolAddress((void**)&paoq, g_ao_q);
    cudaGetSymbolAddress((void**)&pcc, g_cc);
    cudaGetSymbolAddress((void**)&pqq, g_qq);
    cudaGetSymbolAddress((void**)&pCt, g_Ct);
    cudaGetSymbolAddress((void**)&pQt, g_Qt);
    cudaGetSymbolAddress((void**)&pQw, g_Qw);
    cudaGetSymbolAddress((void**)&pmu, g_mu);
    cudaGetSymbolAddress((void**)&pri, g_ri);
    cudaGetSymbolAddress((void**)&pmu2, g_mu2);
    cudaGetSymbolAddress((void**)&pri2, g_ri2);
    float* pWqkv; cudaGetSymbolAddress((void**)&pWqkv, g_Wqkv);
    float* pbqkv; cudaGetSymbolAddress((void**)&pbqkv, g_bqkv);
    float* pS;    cudaGetSymbolAddress((void**)&pS, g_S);

    k_pe<<<ceil_div(kD * kN, 256), 256>>>();
    k_pack_qkv<<<ceil_div(3 * 128 * 128, 256), 256>>>(Wq, Wk, Wv, bq, bk, bv);

    // PE + LN stats, both sequences, one launch (question blocks first)
    k_pe_stats<<<ceil_div(kB * kM, 32) + (kB * kN) / 32, 128>>>(
        ctx, qst, pC, pQ, pmu, pri, pmu2, pri2);

    // Dual-sequence encoder: flattened grid, question first
    const int GX = kB + kB * kLT;   // 64 + 448 = 512
    float* cb_[2] = {pC, pdw};
    float* qb_[2] = {pQ, pQ2};
    for (int i = 0; i < kNC; i++) {
        float* srcC = cb_[i & 1];
        float* dstC = cb_[(i + 1) & 1];
        float* srcQ = qb_[i & 1];
        float* dstQ = qb_[(i + 1) & 1];
        k_cgemm<<<GX, 256>>>(srcC, srcQ, dstC, dstQ,
                             pww + (size_t)i * kD * kD, pwb + (size_t)i * kD,
                             dww + (size_t)i * kD * kKW, dwb + (size_t)i * kD,
                             ln_g, ln_b, pmu, pri, pmu2, pri2);
    }
    k_gemm<false, false, false, true, false><<<dim3(GX, 3), 256>>>(
        pC, pQ, pWqkv, pbqkv, nullptr, nullptr, pqkv, pqkvq, 384,
        pmu, pri, pmu2, pri2, ln_g, ln_b);
    k_attn<<<dim3(1, 2 * kB * kH), 256>>>(
        pqkv, pqkvq, cmask, qmask, pao, paoq);
    k_gemm<true, false, true, false, true><<<dim3(GX, 1), 256>>>(
        pao, paoq, Wo, bo, pC, pQ, pC, pQ, kD,
        pmu, pri, pmu2, pri2, nullptr, nullptr);
    k_gemm<false, false, true, true, false><<<dim3(GX, 1), 256>>>(
        pC, pQ, Wfc, bfc, pC, pQ, pC, pQ, kD,
        pmu, pri, pmu2, pri2, ln_g, ln_b);

    // --------- context-query attention ---------
    k_dot<<<ceil_div(kB * kN, 256), 256>>>(pC, cq_wc, pcc, kN);
    k_dot<<<ceil_div(kB * kM, 256), 256>>>(pQ, cq_wq, pqq, kM);
    k_trC<<<dim3(13, 4, kB), dim3(32, 8)>>>(pC, pCt, kN);
    k_trQ<<<dim3(2, 4, kB), dim3(32, 8)>>>(pQ, pQt, pQw, cq_wm);
    k_sgemm<<<dim3(13, kB), 256>>>(pC, pQw, pcc, pqq, cq_b, pS);
    k_smrow<<<ceil_div(kB * kN, 256), 256>>>(qmask);
    k_smcol<<<ceil_div(kB * kM * 32, 256), 256>>>(cmask);
    k_U<<<kB, 512>>>(pCt);
    k_out<<<kB * 25, 256>>>(pCt, (float*)d_out);
}

// round 15
// speedup vs baseline: 1.9493x; 1.0285x over previous
#include <cuda_runtime.h>
#include <math.h>

// ---------------------------------------------------------------------------
// QANet forward, fp32 on sm_103a.
// R15: R14 + CQ/setup tail fusions: cc into sgemm, tr fused, softmax fused,
//      pe+pack fused, k_U split 4x via partial buffers.
// ---------------------------------------------------------------------------
#define kB 64
#define kD 128
#define kN 400
#define kM 50
#define kH 8
#define kKD 16
#define kNC 4
#define kKW 7
#define kPAD 3
#define kLT 7   // ceil(kN/64)

typedef unsigned long long u64;

__device__ __forceinline__ u64 pk2(float lo, float hi) {
    u64 r; asm("mov.b64 %0,{%1,%2};" : "=l"(r) : "f"(lo), "f"(hi)); return r;
}
__device__ __forceinline__ void upk2(u64 v, float& lo, float& hi) {
    asm("mov.b64 {%0,%1},%2;" : "=f"(lo), "=f"(hi) : "l"(v));
}
__device__ __forceinline__ u64 fma2(u64 a, u64 b, u64 c) {
    u64 d; asm("fma.rn.f32x2 %0,%1,%2,%3;" : "=l"(d) : "l"(a), "l"(b), "l"(c)); return d;
}
__device__ __forceinline__ u64 mul2(u64 a, u64 b) {
    u64 d; asm("mul.rn.f32x2 %0,%1,%2;" : "=l"(d) : "l"(a), "l"(b)); return d;
}

// ------------------------- device scratch (static) -------------------------
__device__ float g_C[kB * kD * kN];
__device__ float g_Q[kB * kD * kM];
__device__ float g_dw[kB * kD * kN];
__device__ float g_Q2[kB * kD * kM];
__device__ float g_qkv[kB * 3 * kD * kN];
__device__ float g_qkv_q[kB * 3 * kD * kM];
__device__ float g_ao[kB * kD * kN];
__device__ float g_ao_q[kB * kD * kM];
__device__ float g_Wqkv[3 * kD * kD];   // [e][d]
__device__ float g_bqkv[3 * kD];
__device__ float g_pe[kD * kN];
__device__ float g_mu[kB * kN];
__device__ float g_ri[kB * kN];
__device__ float g_mu2[kB * kM];
__device__ float g_ri2[kB * kM];
__device__ float g_S[kB * kM * kN];
__device__ float g_Sr[kB * kM * kN];
__device__ float g_Sc[kB * kM * kN];
__device__ float g_Upart[4 * kB * kM * kD];
__device__ float g_Ct[kB * kN * kD];
__device__ float g_Qt[kB * kM * kD];
__device__ float g_Qw[kB * kM * kD];
__device__ float g_qq[kB * kM];

// --------------------- PE table + QKV pack, one launch ----------------------
__global__ void k_pe_pack(const float* __restrict__ Wq, const float* __restrict__ Wk,
                          const float* __restrict__ Wv, const float* __restrict__ bq,
                          const float* __restrict__ bk, const float* __restrict__ bv) {
    int id = blockIdx.x;
    int tid = threadIdx.x;
    if (id < 192) {            // pack (light first): 192*256 = 49152 = 3*128*128
        int idx = id * 256 + tid;
        int e = idx >> 7;
        int d = idx & 127;
        int qv = e >> 7;
        int hk = e & 127;
        int h = hk >> 4;
        int kk = hk & 15;
        const float* src = (qv == 0) ? Wq : (qv == 1 ? Wk : Wv);
        g_Wqkv[idx] = src[((size_t)h * 128 + d) * 16 + kk];
        if (idx < 384) {
            int qv2 = idx >> 7;
            int hk2 = idx & 127;
            const float* srcb = (qv2 == 0) ? bq : (qv2 == 1 ? bk : bv);
            g_bqkv[idx] = srcb[hk2];
        }
    } else {                   // pe table
        int idx = (id - 192) * 256 + tid;
        if (idx < kD * kN) {
            int d = idx / kN;
            int l = idx % kN;
            int d0 = d & ~1;
            double f = pow(10000.0, -(double)d0 / (double)kD);
            double a = (double)l * f;
            g_pe[idx] = (d & 1) ? (float)cos(a) : (float)sin(a);
        }
    }
}

// ----------- add PE + compute LN stats, DUAL sequence, one launch ----------
__global__ void __launch_bounds__(128) k_pe_stats(const float* __restrict__ xc,
                                                  const float* __restrict__ xq,
                                                  float* __restrict__ yc,
                                                  float* __restrict__ yq,
                                                  float* __restrict__ muc,
                                                  float* __restrict__ ric,
                                                  float* __restrict__ muq,
                                                  float* __restrict__ riq) {
    const int QBLK = (kB * kM) / 32;  // 100 (question first)
    int blk = blockIdx.x;
    bool isq = blk < QBLK;
    int L = isq ? kM : kN;
    const float* x = isq ? xq : xc;
    float* y = isq ? yq : yc;
    float* omu = isq ? muq : muc;
    float* ori = isq ? riq : ric;
    int pos0 = (isq ? blk : blk - QBLK) * 32;

    int tid = threadIdx.x;
    int lsub = tid & 31;
    int grp = tid >> 5;
    int pos = pos0 + lsub;
    int P = kB * L;
    bool ok = pos < P;
    int b = ok ? pos / L : 0;
    int l = ok ? pos % L : 0;

    float s = 0.f, sq = 0.f;
    if (ok) {
        const float* xp = x + ((size_t)b * kD + grp * 32) * L + l;
        float* yp = y + ((size_t)b * kD + grp * 32) * L + l;
#pragma unroll
        for (int k = 0; k < 32; k++) {
            int d = grp * 32 + k;
            float v = xp[(size_t)k * L] + g_pe[d * kN + l];
            yp[(size_t)k * L] = v;
            s += v;
            sq += v * v;
        }
    }
    __shared__ float ss[4][32], sb[4][32];
    ss[grp][lsub] = s;
    sb[grp][lsub] = sq;
    __syncthreads();
    if (grp == 0 && ok) {
        float ts = ss[0][lsub] + ss[1][lsub] + ss[2][lsub] + ss[3][lsub];
        float tq = sb[0][lsub] + sb[1][lsub] + sb[2][lsub] + sb[3][lsub];
        float mu = ts * (1.f / 128.f);
        float var = (tq - 128.f * mu * mu) * (1.f / 127.f);
        var = fmaxf(var, 0.f);
        omu[pos] = mu;
        ori[pos] = 1.f / (sqrtf(var) + 1e-6f);
    }
}

// ---------------- fused LN + depthwise conv + pointwise GEMM (dual) ---------
__global__ void __launch_bounds__(256, 3) k_cgemm(const float* __restrict__ Xc,
                                                  const float* __restrict__ Xq,
                                                  float* __restrict__ outc,
                                                  float* __restrict__ outq,
                                                  const float* __restrict__ Wpw,
                                                  const float* __restrict__ pwb,
                                                  const float* __restrict__ cw,
                                                  const float* __restrict__ cb,
                                                  const float* __restrict__ gamma,
                                                  const float* __restrict__ beta,
                                                  float* __restrict__ muc,
                                                  float* __restrict__ ric,
                                                  float* __restrict__ muq,
                                                  float* __restrict__ riq) {
    int id = blockIdx.x;
    bool isq = id < kB;
    int b, l0, L;
    if (isq) { b = id; l0 = 0; L = kM; }
    else { int cid = id - kB; b = cid / kLT; l0 = (cid % kLT) * 64; L = kN; }
    const float* X = isq ? Xq : Xc;
    float* out = isq ? outq : outc;
    float* muP = isq ? muq : muc;
    float* riP = isq ? riq : ric;

    __shared__ __align__(16) float Xl[32][72];
    __shared__ __align__(16) float Xs[32][68];
    __shared__ __align__(16) float Ws[32][132];
    __shared__ float mus[72], ris[72];
    __shared__ float gs[128], bs2[128];
    __shared__ float cws[128][8];

    int tid = threadIdx.x;
    int eq = tid >> 5;
    int lq = tid & 31;

    if (tid < 70) {
        int gl = l0 + tid - 3;
        bool in = (gl >= 0 && gl < L);
        mus[tid] = in ? muP[(size_t)b * L + gl] : 0.f;
        ris[tid] = in ? riP[(size_t)b * L + gl] : 0.f;
    }
    if (tid < 128) {
        gs[tid] = gamma[tid];
        bs2[tid] = beta[tid];
#pragma unroll
        for (int k = 0; k < 7; k++) cws[tid][k] = cw[tid * 7 + k];
        cws[tid][7] = cb[tid];
    }
    __syncthreads();

    float acc[32];
#pragma unroll
    for (int j = 0; j < 32; j++) acc[j] = 0.f;

    for (int k = 0; k < 4; k++) {
        int d0 = k * 32;
#pragma unroll
        for (int r = 0; r < 9; r++) {
            int idx = tid + r * 256;
            if (idx < 2240) {
                int dd = idx / 70;
                int ll = idx - dd * 70;
                int gl = l0 + ll - 3;
                float v = 0.f;
                if (gl >= 0 && gl < L) {
                    float xv = X[((size_t)b * 128 + d0 + dd) * L + gl];
                    v = gs[d0 + dd] * (xv - mus[ll]) * ris[ll] + bs2[d0 + dd];
                }
                Xl[dd][ll] = v;
            }
        }
#pragma unroll
        for (int r = 0; r < 16; r++) {
            int idx = tid + r * 256;
            int e = idx >> 5;
            int dd = idx & 31;
            Ws[dd][e] = Wpw[(size_t)e * 128 + d0 + dd];
        }
        __syncthreads();
#pragma unroll
        for (int r = 0; r < 8; r++) {
            int idx = tid + r * 256;
            int dd = idx >> 6;
            int ll = idx & 63;
            int d = d0 + dd;
            float a = cws[d][7];
#pragma unroll
            for (int kk = 0; kk < 7; kk++) a += cws[d][kk] * Xl[dd][ll + kk];
            Xs[dd][ll] = a;
        }
        __syncthreads();
#pragma unroll
        for (int dd = 0; dd < 32; dd++) {
            float2 xv = *(const float2*)&Xs[dd][lq * 2];
            const float4* wp = (const float4*)&Ws[dd][eq * 16];
            float4 w0 = wp[0], w1 = wp[1], w2 = wp[2], w3 = wp[3];
            acc[0]  += w0.x * xv.x;  acc[1]  += w0.x * xv.y;
            acc[2]  += w0.y * xv.x;  acc[3]  += w0.y * xv.y;
            acc[4]  += w0.z * xv.x;  acc[5]  += w0.z * xv.y;
            acc[6]  += w0.w * xv.x;  acc[7]  += w0.w * xv.y;
            acc[8]  += w1.x * xv.x;  acc[9]  += w1.x * xv.y;
            acc[10] += w1.y * xv.x;  acc[11] += w1.y * xv.y;
            acc[12] += w1.z * xv.x;  acc[13] += w1.z * xv.y;
            acc[14] += w1.w * xv.x;  acc[15] += w1.w * xv.y;
            acc[16] += w2.x * xv.x;  acc[17] += w2.x * xv.y;
            acc[18] += w2.y * xv.x;  acc[19] += w2.y * xv.y;
            acc[20] += w2.z * xv.x;  acc[21] += w2.z * xv.y;
            acc[22] += w2.w * xv.x;  acc[23] += w2.w * xv.y;
            acc[24] += w3.x * xv.x;  acc[25] += w3.x * xv.y;
            acc[26] += w3.y * xv.x;  acc[27] += w3.y * xv.y;
            acc[28] += w3.z * xv.x;  acc[29] += w3.z * xv.y;
            acc[30] += w3.w * xv.x;  acc[31] += w3.w * xv.y;
        }
        __syncthreads();
    }

    float sum_l[2] = {0.f, 0.f};
    float sq_l[2] = {0.f, 0.f};
#pragma unroll
    for (int p = 0; p < 16; p++) {
        int e0 = eq * 16 + p;
        float bv = pwb[e0];
#pragma unroll
        for (int q = 0; q < 2; q++) {
            float v = fmaxf(acc[p * 2 + q] + bv, 0.f);
            int lg = l0 + lq * 2 + q;
            if (lg < L) {
                size_t oi = ((size_t)b * 128 + e0) * L + lg;
                v += X[oi];
                out[oi] = v;
            }
            sum_l[q] += v;
            sq_l[q] += v * v;
        }
    }
    float* red = &Ws[0][0];
    red[eq * 64 + lq * 2 + 0] = sum_l[0];
    red[eq * 64 + lq * 2 + 1] = sum_l[1];
    red[512 + eq * 64 + lq * 2 + 0] = sq_l[0];
    red[512 + eq * 64 + lq * 2 + 1] = sq_l[1];
    __syncthreads();
    if (tid < 64) {
        int lg = l0 + tid;
        if (lg < L) {
            float s = 0.f, ss = 0.f;
#pragma unroll
            for (int g = 0; g < 8; g++) {
                s += red[g * 64 + tid];
                ss += red[512 + g * 64 + tid];
            }
            float muv = s * (1.f / 128.f);
            float var = (ss - 128.f * muv * muv) * (1.f / 127.f);
            var = fmaxf(var, 0.f);
            muP[(size_t)b * L + lg] = muv;
            riP[(size_t)b * L + lg] = 1.f / (sqrtf(var) + 1e-6f);
        }
    }
}

// ------------------------------- GEMM (dual) --------------------------------
template <bool TR, bool RELU, bool RES, bool LNX, bool STATS>
__global__ void __launch_bounds__(256, 3) k_gemm(const float* __restrict__ Xc,
                                                 const float* __restrict__ Xq,
                                                 const float* __restrict__ W,
                                                 const float* __restrict__ bias,
                                                 const float* resc, const float* resq,
                                                 float* outc, float* outq,
                                                 int Etot,
                                                 float* __restrict__ muc,
                                                 float* __restrict__ ric,
                                                 float* __restrict__ muq,
                                                 float* __restrict__ riq,
                                                 const float* __restrict__ gamma,
                                                 const float* __restrict__ beta) {
    int id = blockIdx.x;
    bool isq = id < kB;
    int b, l0, L;
    if (isq) { b = id; l0 = 0; L = kM; }
    else { int cid = id - kB; b = cid / kLT; l0 = (cid % kLT) * 64; L = kN; }
    const float* X = isq ? Xq : Xc;
    const float* res = isq ? resq : resc;
    float* out = isq ? outq : outc;
    float* muP = isq ? muq : muc;
    float* riP = isq ? riq : ric;

    __shared__ __align__(16) float Xs[32][68];
    __shared__ __align__(16) float Ws[32][132];
    __shared__ float mus[64], ris[64];
    __shared__ float gs[128], bs2[128];

    int tid = threadIdx.x;
    int eq = tid >> 5;
    int lq = tid & 31;
    int et = blockIdx.y * 128;

    if (LNX) {
        if (tid < 64) {
            int p = l0 + tid;
            mus[tid] = (p < L) ? muP[(size_t)b * L + p] : 0.f;
            ris[tid] = (p < L) ? riP[(size_t)b * L + p] : 0.f;
        }
        if (tid < 128) {
            gs[tid] = gamma[tid];
            bs2[tid] = beta[tid];
        }
        __syncthreads();
    }

    float acc[32];
#pragma unroll
    for (int j = 0; j < 32; j++) acc[j] = 0.f;

    for (int k = 0; k < 4; k++) {
        int d0 = k * 32;
#pragma unroll
        for (int r = 0; r < 8; r++) {
            int idx = tid + r * 256;
            int dd = idx >> 6;
            int ll = idx & 63;
            int lg = l0 + ll;
            float v = 0.f;
            if (lg < L) {
                v = X[((size_t)b * 128 + d0 + dd) * L + lg];
                if (LNX) v = gs[d0 + dd] * (v - mus[ll]) * ris[ll] + bs2[d0 + dd];
            }
            Xs[dd][ll] = v;
        }
#pragma unroll
        for (int r = 0; r < 16; r++) {
            int idx = tid + r * 256;
            if (TR) {
                int dd = idx >> 7;
                int e = idx & 127;
                Ws[dd][e] = W[(size_t)(d0 + dd) * Etot + et + e];
            } else {
                int e = idx >> 5;
                int dd = idx & 31;
                Ws[dd][e] = W[(size_t)(et + e) * 128 + d0 + dd];
            }
        }
        __syncthreads();
#pragma unroll
        for (int dd = 0; dd < 32; dd++) {
            float2 xv = *(const float2*)&Xs[dd][lq * 2];
            const float4* wp = (const float4*)&Ws[dd][eq * 16];
            float4 w0 = wp[0], w1 = wp[1], w2 = wp[2], w3 = wp[3];
            acc[0]  += w0.x * xv.x;  acc[1]  += w0.x * xv.y;
            acc[2]  += w0.y * xv.x;  acc[3]  += w0.y * xv.y;
            acc[4]  += w0.z * xv.x;  acc[5]  += w0.z * xv.y;
            acc[6]  += w0.w * xv.x;  acc[7]  += w0.w * xv.y;
            acc[8]  += w1.x * xv.x;  acc[9]  += w1.x * xv.y;
            acc[10] += w1.y * xv.x;  acc[11] += w1.y * xv.y;
            acc[12] += w1.z * xv.x;  acc[13] += w1.z * xv.y;
            acc[14] += w1.w * xv.x;  acc[15] += w1.w * xv.y;
            acc[16] += w2.x * xv.x;  acc[17] += w2.x * xv.y;
            acc[18] += w2.y * xv.x;  acc[19] += w2.y * xv.y;
            acc[20] += w2.z * xv.x;  acc[21] += w2.z * xv.y;
            acc[22] += w2.w * xv.x;  acc[23] += w2.w * xv.y;
            acc[24] += w3.x * xv.x;  acc[25] += w3.x * xv.y;
            acc[26] += w3.y * xv.x;  acc[27] += w3.y * xv.y;
            acc[28] += w3.z * xv.x;  acc[29] += w3.z * xv.y;
            acc[30] += w3.w * xv.x;  acc[31] += w3.w * xv.y;
        }
        __syncthreads();
    }

    float sum_l[2] = {0.f, 0.f};
    float sq_l[2] = {0.f, 0.f};
#pragma unroll
    for (int p = 0; p < 16; p++) {
        int e0 = et + eq * 16 + p;
        float bv = bias[e0];
#pragma unroll
        for (int q = 0; q < 2; q++) {
            float v = acc[p * 2 + q] + bv;
            if (RELU) v = fmaxf(v, 0.f);
            int lg = l0 + lq * 2 + q;
            if (lg < L) {
                size_t oi = ((size_t)b * Etot + e0) * L + lg;
                if (RES) v += res[oi];
                out[oi] = v;
            }
            if (STATS) {
                sum_l[q] += v;
                sq_l[q] += v * v;
            }
        }
    }
    if (STATS) {
        float* red = &Ws[0][0];
        red[eq * 64 + lq * 2 + 0] = sum_l[0];
        red[eq * 64 + lq * 2 + 1] = sum_l[1];
        red[512 + eq * 64 + lq * 2 + 0] = sq_l[0];
        red[512 + eq * 64 + lq * 2 + 1] = sq_l[1];
        __syncthreads();
        if (tid < 64) {
            int lg = l0 + tid;
            if (lg < L) {
                float s = 0.f, ss = 0.f;
#pragma unroll
                for (int g = 0; g < 8; g++) {
                    s += red[g * 64 + tid];
                    ss += red[512 + g * 64 + tid];
                }
                float muv = s * (1.f / 128.f);
                float var = (ss - 128.f * muv * muv) * (1.f / 127.f);
                var = fmaxf(var, 0.f);
                muP[(size_t)b * L + lg] = muv;
                riP[(size_t)b * L + lg] = 1.f / (sqrtf(var) + 1e-6f);
            }
        }
    }
}

// --------------------- attention core (dual, 2 queries/thread) --------------
__global__ void __launch_bounds__(256) k_attn(const float* __restrict__ qkvc,
                                              const float* __restrict__ qkvq,
                                              const float* __restrict__ cmask,
                                              const float* __restrict__ qmask,
                                              float* __restrict__ oc,
                                              float* __restrict__ oq) {
    const int KT = 64;
    __shared__ u64 ks[KT][9], vs[KT][9];
    __shared__ float ms[KT];
    int tid = threadIdx.x;
    int bh = blockIdx.y;
    int z = bh >> 3;
    bool isq = z < kB;   // question first
    int b = isq ? z : z - kB;
    int h = bh & 7;
    int L = isq ? kM : kN;
    int i0 = blockIdx.x * 512 + tid;
    int i1 = i0 + 256;
    if (blockIdx.x * 512 >= L) return;
    const float* qkv = isq ? qkvq : qkvc;
    const float* mask = isq ? qmask : cmask;
    float* o = isq ? oq : oc;
    bool a0 = i0 < L, a1 = i1 < L;

    u64 qa[8], qb[8];
#pragma unroll
    for (int c = 0; c < 8; c++) { qa[c] = 0; qb[c] = 0; }
    if (a0) {
        const float* qp = qkv + ((size_t)b * 384 + h * 16) * L + i0;
#pragma unroll
        for (int c = 0; c < 8; c++)
            qa[c] = pk2(qp[(size_t)(2 * c) * L] * 0.25f, qp[(size_t)(2 * c + 1) * L] * 0.25f);
    }
    if (a1) {
        const float* qp = qkv + ((size_t)b * 384 + h * 16) * L + i1;
#pragma unroll
        for (int c = 0; c < 8; c++)
            qb[c] = pk2(qp[(size_t)(2 * c) * L] * 0.25f, qp[(size_t)(2 * c + 1) * L] * 0.25f);
    }
    float mA = -INFINITY, lA = 0.f;
    float mB = -INFINITY, lB = 0.f;
    u64 accA[8] = {0, 0, 0, 0, 0, 0, 0, 0};
    u64 accB[8] = {0, 0, 0, 0, 0, 0, 0, 0};

    for (int j0 = 0; j0 < L; j0 += KT) {
        int cnt = min(KT, L - j0);
        for (int idx = tid; idx < 8 * KT; idx += 256) {
            int c = idx >> 6;
            int t = idx & 63;
            if (t < cnt) {
                const float* kp = qkv + ((size_t)b * 384 + 128 + h * 16 + 2 * c) * L + j0 + t;
                ks[t][c] = pk2(kp[0], kp[(size_t)L]);
                const float* vp = kp + (size_t)128 * L;
                vs[t][c] = pk2(vp[0], vp[(size_t)L]);
            } else {
                ks[t][c] = 0;
                vs[t][c] = 0;
            }
        }
        if (tid < KT) ms[tid] = (tid < cnt) ? mask[(size_t)b * L + j0 + tid] : 0.f;
        __syncthreads();
        for (int g = 0; g < cnt; g += 8) {
            float sA[8], sB[8];
#pragma unroll
            for (int t2 = 0; t2 < 8; t2++) {
                int t = g + t2;
                u64 s2a = 0, s2b = 0;
#pragma unroll
                for (int c = 0; c < 8; c++) {
                    u64 kv = ks[t][c];
                    s2a = fma2(qa[c], kv, s2a);
                    s2b = fma2(qb[c], kv, s2b);
                }
                float lo, hi;
                float pen = 1e30f * (1.f - ms[t]);
                upk2(s2a, lo, hi);
                sA[t2] = lo + hi - pen;
                upk2(s2b, lo, hi);
                sB[t2] = lo + hi - pen;
            }
            float gA = sA[0], gB = sB[0];
#pragma unroll
            for (int t2 = 1; t2 < 8; t2++) {
                gA = fmaxf(gA, sA[t2]);
                gB = fmaxf(gB, sB[t2]);
            }
            float nA = fmaxf(mA, gA), nB = fmaxf(mB, gB);
            float scA = __expf(mA - nA), scB = __expf(mB - nB);
            lA *= scA;
            lB *= scB;
            u64 sa2 = pk2(scA, scA), sb2 = pk2(scB, scB);
#pragma unroll
            for (int c = 0; c < 8; c++) {
                accA[c] = mul2(sa2, accA[c]);
                accB[c] = mul2(sb2, accB[c]);
            }
#pragma unroll
            for (int t2 = 0; t2 < 8; t2++) {
                int t = g + t2;
                float pA = __expf(sA[t2] - nA);
                float pB = __expf(sB[t2] - nB);
                lA += pA;
                lB += pB;
                u64 pa2 = pk2(pA, pA), pb2 = pk2(pB, pB);
#pragma unroll
                for (int c = 0; c < 8; c++) {
                    u64 vv = vs[t][c];
                    accA[c] = fma2(pa2, vv, accA[c]);
                    accB[c] = fma2(pb2, vv, accB[c]);
                }
            }
            mA = nA;
            mB = nB;
        }
        __syncthreads();
    }
    if (a0) {
        float r = 1.f / lA;
        float* op = o + ((size_t)b * 128 + h * 16) * L + i0;
#pragma unroll
        for (int c = 0; c < 8; c++) {
            float lo, hi;
            upk2(accA[c], lo, hi);
            op[(size_t)(2 * c) * L] = lo * r;
            op[(size_t)(2 * c + 1) * L] = hi * r;
        }
    }
    if (a1) {
        float r = 1.f / lB;
        float* op = o + ((size_t)b * 128 + h * 16) * L + i1;
#pragma unroll
        for (int c = 0; c < 8; c++) {
            float lo, hi;
            upk2(accB[c], lo, hi);
            op[(size_t)(2 * c) * L] = lo * r;
            op[(size_t)(2 * c + 1) * L] = hi * r;
        }
    }
}

// ------------------- fused transposes (question tiles first) ----------------
// q tiles: 2*4*64 = 512 ids;  ctx tiles: 13*4*64 = 3328 ids.
__global__ void k_tr(const float* __restrict__ C, float* __restrict__ Ct,
                     const float* __restrict__ Q, float* __restrict__ Qt,
                     float* __restrict__ Qw, const float* __restrict__ wm) {
    __shared__ float t[32][33];
    int id = blockIdx.x;
    bool isq = id < 512;
    int b, d0, l0, L;
    const float* X;
    float* Y;
    if (isq) {
        int lx = id & 1;
        int dy = (id >> 1) & 3;
        b = id >> 3;
        d0 = dy * 32;
        l0 = lx * 32;
        L = kM;
        X = Q;
        Y = Qt;
    } else {
        int cid = id - 512;
        int lx = cid % 13;
        int dy = (cid / 13) & 3;
        b = cid / 52;
        d0 = dy * 32;
        l0 = lx * 32;
        L = kN;
        X = C;
        Y = Ct;
    }
    int tx = threadIdx.x, ty = threadIdx.y;
#pragma unroll
    for (int k = 0; k < 4; k++) {
        int l = l0 + tx;
        t[ty + 8 * k][tx] = (l < L) ? X[((size_t)b * 128 + d0 + ty + 8 * k) * L + l] : 0.f;
    }
    __syncthreads();
    float w = isq ? wm[d0 + tx] : 0.f;
#pragma unroll
    for (int k = 0; k < 4; k++) {
        int l = l0 + ty + 8 * k;
        if (l < L) {
            float v = t[tx][ty + 8 * k];
            size_t oi = ((size_t)b * L + l) * 128 + d0 + tx;
            Y[oi] = v;
            if (isq) Qw[oi] = v * w;
        }
    }
}

// ------------------------------ CQ attention -------------------------------
__global__ void k_dot(const float* __restrict__ X, const float* __restrict__ w,
                      float* __restrict__ out, int L) {
    int idx = blockIdx.x * blockDim.x + threadIdx.x;
    if (idx >= kB * L) return;
    int b = idx / L;
    int pos = idx % L;
    const float* xp = X + (size_t)b * kD * L + pos;
    float a = 0.f;
#pragma unroll 8
    for (int d = 0; d < kD; d++) a += w[d] * xp[(size_t)d * L];
    out[idx] = a;
}

// S GEMM with fused cc = C . wc (identical summation order to old k_dot)
__global__ void __launch_bounds__(256) k_sgemm(const float* __restrict__ X,
                                               const float* __restrict__ Qw,
                                               const float* __restrict__ wc,
                                               const float* __restrict__ qq,
                                               const float* __restrict__ b0,
                                               float* __restrict__ S) {
    __shared__ float Xs[32][33];
    __shared__ float Ws[32][68];
    __shared__ float wcs[128];
    int tid = threadIdx.x;
    int l = tid & 31;
    int eg = tid >> 5;
    int l0 = blockIdx.x * 32;
    int b = blockIdx.y;
    u64 acc[4] = {0, 0, 0, 0};
    float ccv = 0.f;
    if (tid < 128) wcs[tid] = wc[tid];

    for (int d0 = 0; d0 < 128; d0 += 32) {
#pragma unroll
        for (int r = 0; r < 4; r++) {
            int idx = tid + r * 256;
            int dd = idx >> 5, ll = idx & 31;
            int lg = l0 + ll;
            Xs[dd][ll] = (lg < kN) ? X[((size_t)b * 128 + d0 + dd) * kN + lg] : 0.f;
        }
#pragma unroll
        for (int r = 0; r < 8; r++) {
            int idx = tid + r * 256;
            int dd = idx >> 6;
            int e = idx & 63;
            Ws[dd][e] = (e < kM) ? Qw[((size_t)b * kM + e) * 128 + d0 + dd] : 0.f;
        }
        __syncthreads();
#pragma unroll
        for (int dd = 0; dd < 32; dd++) {
            float xv = Xs[dd][l];
            ccv += wcs[d0 + dd] * xv;
            u64 xx = pk2(xv, xv);
            const ulonglong2* wr = (const ulonglong2*)&Ws[dd][eg * 8];
            ulonglong2 w0 = wr[0], w1 = wr[1];
            acc[0] = fma2(xx, w0.x, acc[0]);
            acc[1] = fma2(xx, w0.y, acc[1]);
            acc[2] = fma2(xx, w1.x, acc[2]);
            acc[3] = fma2(xx, w1.y, acc[3]);
        }
        __syncthreads();
    }
    int lg = l0 + l;
    if (lg < kN) {
        float base = ccv + b0[0];
#pragma unroll
        for (int j = 0; j < 4; j++) {
            float v0, v1;
            upk2(acc[j], v0, v1);
            int e0 = eg * 8 + 2 * j;
            if (e0 < kM) S[((size_t)b * kM + e0) * kN + lg] = v0 + base + qq[b * kM + e0];
            if (e0 + 1 < kM) S[((size_t)b * kM + e0 + 1) * kN + lg] = v1 + base + qq[b * kM + e0 + 1];
        }
    }
}

// ----------------- fused softmaxes (row over m, col over n) -----------------
// blocks 0..99: smrow (256 threads each = (b,n) pairs); blocks 100..499: smcol.
__global__ void __launch_bounds__(256) k_sm(const float* __restrict__ qmask,
                                            const float* __restrict__ cmask) {
    int blk = blockIdx.x;
    if (blk < 100) {
        int idx = blk * 256 + threadIdx.x;
        if (idx >= kB * kN) return;
        int b = idx / kN;
        int n = idx % kN;
        float v[kM];
        float mx = -INFINITY;
#pragma unroll
        for (int m = 0; m < kM; m++) {
            v[m] = g_S[((size_t)b * kM + m) * kN + n] - 1e30f * (1.f - qmask[b * kM + m]);
            mx = fmaxf(mx, v[m]);
        }
        float s = 0.f;
#pragma unroll
        for (int m = 0; m < kM; m++) {
            v[m] = __expf(v[m] - mx);
            s += v[m];
        }
        float r = 1.f / s;
#pragma unroll
        for (int m = 0; m < kM; m++) g_Sr[((size_t)b * kM + m) * kN + n] = v[m] * r;
    } else {
        int w = (blk - 100) * 8 + (threadIdx.x >> 5);
        int lane = threadIdx.x & 31;
        if (w >= kB * kM) return;
        int b = w / kM;
        const float* row = g_S + (size_t)w * kN;
        const float* mrow = cmask + (size_t)b * kN;
        float v[13];
#pragma unroll
        for (int k = 0; k < 13; k++) {
            int n = lane + k * 32;
            v[k] = (n < kN) ? row[n] - 1e30f * (1.f - mrow[n]) : -INFINITY;
        }
        float mx = v[0];
#pragma unroll
        for (int k = 1; k < 13; k++) mx = fmaxf(mx, v[k]);
#pragma unroll
        for (int o = 16; o; o >>= 1) mx = fmaxf(mx, __shfl_xor_sync(0xffffffff, mx, o));
        float s = 0.f;
        float e[13];
#pragma unroll
        for (int k = 0; k < 13; k++) {
            int n = lane + k * 32;
            e[k] = (n < kN) ? __expf(v[k] - mx) : 0.f;
            s += e[k];
        }
#pragma unroll
        for (int o = 16; o; o >>= 1) s += __shfl_xor_sync(0xffffffff, s, o);
        float r = 1.f / s;
        float* orow = g_Sc + (size_t)w * kN;
#pragma unroll
        for (int k = 0; k < 13; k++) {
            int n = lane + k * 32;
            if (n < kN) orow[n] = e[k] * r;
        }
    }
}

// ------------- U partials: grid (kB, 4); chunk owns iter subrange -----------
__global__ void __launch_bounds__(512) k_U(const float* __restrict__ Ct) {
    const int starts[5] = {0, 7, 13, 19, 25};
    int b = blockIdx.x;
    int cnk = blockIdx.y;
    int tid = threadIdx.x;
    int d = tid & 127;
    int mq = tid >> 7;
    __shared__ float cts[16][128];
    __shared__ float scs[16][56];
    u64 acc[7] = {0, 0, 0, 0, 0, 0, 0};

    for (int it = starts[cnk]; it < starts[cnk + 1]; it++) {
        int n0 = it * 16;
#pragma unroll
        for (int r = 0; r < 4; r++) {
            int idx = tid + r * 512;
            int n = idx >> 7, dd = idx & 127;
            cts[n][dd] = Ct[((size_t)b * kN + n0 + n) * 128 + dd];
        }
        for (int idx = tid; idx < 16 * 56; idx += 512) {
            int n = idx & 15;
            int m = idx >> 4;
            scs[n][m] = (m < kM) ? g_Sc[((size_t)b * kM + m) * kN + n0 + n] : 0.f;
        }
        __syncthreads();
#pragma unroll
        for (int n = 0; n < 16; n++) {
            float ct = cts[n][d];
            u64 c2 = pk2(ct, ct);
            const u64* sp = (const u64*)&scs[n][mq * 14];
#pragma unroll
            for (int j = 0; j < 7; j++) acc[j] = fma2(c2, sp[j], acc[j]);
        }
        __syncthreads();
    }
#pragma unroll
    for (int j = 0; j < 7; j++) {
        float v0, v1;
        upk2(acc[j], v0, v1);
        int m = mq * 14 + 2 * j;
        size_t base = (((size_t)cnk * kB + b) * kM) * 128;
        if (m < kM) g_Upart[base + (size_t)m * 128 + d] = v0;
        if (m + 1 < kM) g_Upart[base + (size_t)(m + 1) * 128 + d] = v1;
    }
}

__global__ void __launch_bounds__(256) k_out(const float* __restrict__ Ct,
                                             float* __restrict__ out) {
    const size_t PS = (size_t)kB * kM * 128;
    int b = blockIdx.x / 25;
    int n0 = (blockIdx.x % 25) * 16;
    int tid = threadIdx.x;
    int d = tid & 127;
    int nq = tid >> 7;
    __shared__ float srs[kM][16];
    for (int idx = tid; idx < kM * 16; idx += 256) {
        int m = idx >> 4, nj = idx & 15;
        srs[m][nj] = g_Sr[((size_t)b * kM + m) * kN + n0 + nj];
    }
    __syncthreads();
    u64 a2[4] = {0, 0, 0, 0};
    u64 b2[4] = {0, 0, 0, 0};
    for (int m = 0; m < kM; m++) {
        size_t bi = ((size_t)b * kM + m) * 128 + d;
        float qv = g_Qt[bi];
        float uv = g_Upart[bi] + g_Upart[bi + PS] + g_Upart[bi + 2 * PS] + g_Upart[bi + 3 * PS];
        u64 q2 = pk2(qv, qv), u2 = pk2(uv, uv);
        const u64* sp = (const u64*)&srs[m][nq * 8];
#pragma unroll
        for (int j = 0; j < 4; j++) {
            a2[j] = fma2(sp[j], q2, a2[j]);
            b2[j] = fma2(sp[j], u2, b2[j]);
        }
    }
#pragma unroll
    for (int j = 0; j < 4; j++) {
        float a0, a1, bt0, bt1;
        upk2(a2[j], a0, a1);
        upk2(b2[j], bt0, bt1);
#pragma unroll
        for (int t = 0; t < 2; t++) {
            int n = n0 + nq * 8 + 2 * j + t;
            float a = (t == 0) ? a0 : a1;
            float bt = (t == 0) ? bt0 : bt1;
            float c = Ct[((size_t)b * kN + n) * 128 + d];
            size_t base = ((size_t)b * kN + n) * 512;
            out[base + d] = c;
            out[base + 128 + d] = a;
            out[base + 256 + d] = c * a;
            out[base + 384 + d] = c * bt;
        }
    }
}

// ------------------------------- host side ---------------------------------
static inline int ceil_div(int a, int b) { return (a + b - 1) / b; }

extern "C" void kernel_launch(void* const* d_in, const int* in_sizes, int n_in,
                              void* d_out, int out_size) {
    (void)in_sizes; (void)n_in; (void)out_size;
    const float* ctx   = (const float*)d_in[0];
    const float* qst   = (const float*)d_in[1];
    const float* cmask = (const float*)d_in[2];
    const float* qmask = (const float*)d_in[3];
    const float* ln_g  = (const float*)d_in[4];
    const float* ln_b  = (const float*)d_in[5];
    const float* dww   = (const float*)d_in[6];
    const float* dwb   = (const float*)d_in[7];
    const float* pww   = (const float*)d_in[8];
    const float* pwb   = (const float*)d_in[9];
    const float* Wq    = (const float*)d_in[10];
    const float* bq    = (const float*)d_in[11];
    const float* Wk    = (const float*)d_in[12];
    const float* bk    = (const float*)d_in[13];
    const float* Wv    = (const float*)d_in[14];
    const float* bv    = (const float*)d_in[15];
    const float* Wo    = (const float*)d_in[16];
    const float* bo    = (const float*)d_in[17];
    const float* Wfc   = (const float*)d_in[18];
    const float* bfc   = (const float*)d_in[19];
    const float* cq_wc = (const float*)d_in[20];
    const float* cq_wq = (const float*)d_in[21];
    const float* cq_wm = (const float*)d_in[22];
    const float* cq_b  = (const float*)d_in[23];

    float *pC, *pQ, *pdw, *pQ2, *pqkv, *pqkvq, *pao, *paoq, *pqq;
    float *pCt, *pQt, *pQw, *pmu, *pri, *pmu2, *pri2;
    cudaGetSymbolAddress((void**)&pC, g_C);
    cudaGetSymbolAddress((void**)&pQ, g_Q);
    cudaGetSymbolAddress((void**)&pdw, g_dw);
    cudaGetSymbolAddress((void**)&pQ2, g_Q2);
    cudaGetSymbolAddress((void**)&pqkv, g_qkv);
    cudaGetSymbolAddress((void**)&pqkvq, g_qkv_q);
    cudaGetSymbolAddress((void**)&pao, g_ao);
    cudaGetSymbolAddress((void**)&paoq, g_ao_q);
    cudaGetSymbolAddress((void**)&pqq, g_qq);
    cudaGetSymbolAddress((void**)&pCt, g_Ct);
    cudaGetSymbolAddress((void**)&pQt, g_Qt);
    cudaGetSymbolAddress((void**)&pQw, g_Qw);
    cudaGetSymbolAddress((void**)&pmu, g_mu);
    cudaGetSymbolAddress((void**)&pri, g_ri);
    cudaGetSymbolAddress((void**)&pmu2, g_mu2);
    cudaGetSymbolAddress((void**)&pri2, g_ri2);
    float* pWqkv; cudaGetSymbolAddress((void**)&pWqkv, g_Wqkv);
    float* pbqkv; cudaGetSymbolAddress((void**)&pbqkv, g_bqkv);
    float* pS;    cudaGetSymbolAddress((void**)&pS, g_S);

    // setup: pack (light) + PE table, one launch
    k_pe_pack<<<192 + ceil_div(kD * kN, 256), 256>>>(Wq, Wk, Wv, bq, bk, bv);

    // PE + LN stats, both sequences, one launch (question blocks first)
    k_pe_stats<<<ceil_div(kB * kM, 32) + (kB * kN) / 32, 128>>>(
        ctx, qst, pC, pQ, pmu, pri, pmu2, pri2);

    // Dual-sequence encoder: flattened grid, question first
    const int GX = kB + kB * kLT;   // 64 + 448 = 512
    float* cb_[2] = {pC, pdw};
    float* qb_[2] = {pQ, pQ2};
    for (int i = 0; i < kNC; i++) {
        float* srcC = cb_[i & 1];
        float* dstC = cb_[(i + 1) & 1];
        float* srcQ = qb_[i & 1];
        float* dstQ = qb_[(i + 1) & 1];
        k_cgemm<<<GX, 256>>>(srcC, srcQ, dstC, dstQ,
                             pww + (size_t)i * kD * kD, pwb + (size_t)i * kD,
                             dww + (size_t)i * kD * kKW, dwb + (size_t)i * kD,
                             ln_g, ln_b, pmu, pri, pmu2, pri2);
    }
    k_gemm<false, false, false, true, false><<<dim3(GX, 3), 256>>>(
        pC, pQ, pWqkv, pbqkv, nullptr, nullptr, pqkv, pqkvq, 384,
        pmu, pri, pmu2, pri2, ln_g, ln_b);
    k_attn<<<dim3(1, 2 * kB * kH), 256>>>(
        pqkv, pqkvq, cmask, qmask, pao, paoq);
    k_gemm<true, false, true, false, true><<<dim3(GX, 1), 256>>>(
        pao, paoq, Wo, bo, pC, pQ, pC, pQ, kD,
        pmu, pri, pmu2, pri2, nullptr, nullptr);
    k_gemm<false, false, true, true, false><<<dim3(GX, 1), 256>>>(
        pC, pQ, Wfc, bfc, pC, pQ, pC, pQ, kD,
        pmu, pri, pmu2, pri2, ln_g, ln_b);

    // --------- context-query attention ---------
    k_dot<<<ceil_div(kB * kM, 256), 256>>>(pQ, cq_wq, pqq, kM);
    k_tr<<<512 + 13 * 4 * kB, dim3(32, 8)>>>(pC, pCt, pQ, pQt, pQw, cq_wm);
    k_sgemm<<<dim3(13, kB), 256>>>(pC, pQw, cq_wc, pqq, cq_b, pS);
    k_sm<<<500, 256>>>(qmask, cmask);
    k_U<<<dim3(kB, 4), 512>>>(pCt);
    k_out<<<kB * 25, 256>>>(pCt, (float*)d_out);
}